// round 1
// baseline (speedup 1.0000x reference)
#include <cuda_runtime.h>
#include <cstdint>

// Problem constants (fixed by setup_inputs)
#define B_   16
#define N_   1024
#define C_   768
#define H_   12
#define D_   64
#define M_   (B_*N_)     // 16384 rows
#define QKV_ (3*C_)      // 2304

// ---------------- scratch (device globals: allocation-free) ----------------
__device__ float g_qkv[M_ * QKV_];            // 151 MB
__device__ float g_q[B_*H_*N_*D_];            // 48 MB
__device__ float g_k[B_*H_*N_*D_];
__device__ float g_v[B_*H_*N_*D_];
__device__ float g_att[M_ * C_];              // 48 MB

// ---------------- fast exp2 (FMA pipe only, no MUFU/CVT) ----------------
// valid for x <= 0; clamps at -120 (underflow -> ~0)
__device__ __forceinline__ float fexp2(float x) {
    x = fmaxf(x, -120.0f);
    float z  = x + 12582912.0f;          // 1.5*2^23: round-to-nearest-int magic
    float zi = z - 12582912.0f;          // rounded integer part
    float f  = x - zi;                   // f in [-0.5, 0.5]
    int   e  = __float_as_int(z);        // low mantissa bits hold the integer
    // 2^f, degree-5 Taylor around 0 (rel err < ~3e-6 on [-0.5,0.5])
    float p = 1.3333558e-3f;
    p = fmaf(p, f, 9.6181291e-3f);
    p = fmaf(p, f, 5.5504109e-2f);
    p = fmaf(p, f, 2.4022651e-1f);
    p = fmaf(p, f, 6.9314718e-1f);
    p = fmaf(p, f, 1.0f);
    float s = __int_as_float((e << 23) + 0x3f800000); // 2^round(x)
    return p * s;
}

// ---------------- 128x128x8 fp32 tiled GEMM: C = A@B (+bias) ----------------
// A[M,K] row-major, B[K,N] row-major. M%128==0, N%128==0, K%8==0.
__global__ __launch_bounds__(256)
void sgemm128(const float* __restrict__ A, const float* __restrict__ Bm,
              float* __restrict__ Cm, int M, int N, int K,
              const float* __restrict__ bias)
{
    __shared__ float As[8][128];
    __shared__ float Bs[8][128];
    const int tid = threadIdx.x;
    const int bm = blockIdx.y, bn = blockIdx.x;
    const int tx = tid & 15, ty = tid >> 4;

    const int arow = tid >> 1;           // 0..127
    const int acol = (tid & 1) * 4;      // 0 or 4
    const int brow = tid >> 5;           // 0..7
    const int bcol = (tid & 31) * 4;     // 0..124

    const float* Aptr = A + (size_t)(bm*128 + arow)*K + acol;
    const float* Bptr = Bm + (size_t)brow*N + bn*128 + bcol;

    float acc[8][8];
    #pragma unroll
    for (int i = 0; i < 8; i++)
        #pragma unroll
        for (int j = 0; j < 8; j++) acc[i][j] = 0.f;

    for (int k0 = 0; k0 < K; k0 += 8) {
        float4 av = *(const float4*)(Aptr + k0);
        float4 bv = *(const float4*)(Bptr + (size_t)k0*N);
        As[acol+0][arow] = av.x; As[acol+1][arow] = av.y;
        As[acol+2][arow] = av.z; As[acol+3][arow] = av.w;
        *(float4*)&Bs[brow][bcol] = bv;
        __syncthreads();
        #pragma unroll
        for (int k = 0; k < 8; k++) {
            float a[8], b[8];
            float4 a0 = *(const float4*)&As[k][ty*8];
            float4 a1 = *(const float4*)&As[k][ty*8+4];
            float4 b0 = *(const float4*)&Bs[k][tx*8];
            float4 b1 = *(const float4*)&Bs[k][tx*8+4];
            a[0]=a0.x;a[1]=a0.y;a[2]=a0.z;a[3]=a0.w;a[4]=a1.x;a[5]=a1.y;a[6]=a1.z;a[7]=a1.w;
            b[0]=b0.x;b[1]=b0.y;b[2]=b0.z;b[3]=b0.w;b[4]=b1.x;b[5]=b1.y;b[6]=b1.z;b[7]=b1.w;
            #pragma unroll
            for (int i = 0; i < 8; i++)
                #pragma unroll
                for (int j = 0; j < 8; j++)
                    acc[i][j] = fmaf(a[i], b[j], acc[i][j]);
        }
        __syncthreads();
    }

    float badd[8];
    #pragma unroll
    for (int j = 0; j < 8; j++)
        badd[j] = bias ? bias[bn*128 + tx*8 + j] : 0.f;

    #pragma unroll
    for (int i = 0; i < 8; i++) {
        const int row = bm*128 + ty*8 + i;
        float* Crow = Cm + (size_t)row*N + bn*128 + tx*8;
        float4 r0, r1;
        r0.x = acc[i][0]+badd[0]; r0.y = acc[i][1]+badd[1];
        r0.z = acc[i][2]+badd[2]; r0.w = acc[i][3]+badd[3];
        r1.x = acc[i][4]+badd[4]; r1.y = acc[i][5]+badd[5];
        r1.z = acc[i][6]+badd[6]; r1.w = acc[i][7]+badd[7];
        *(float4*)(Crow)     = r0;
        *(float4*)(Crow + 4) = r1;
    }
}

// ---------------- per-head LayerNorm + RoPE + layout split ----------------
// one block per (b,n), one warp per head. Q gets scale*log2e folded in.
__global__ __launch_bounds__(384)
void ln_rope_kernel(const float* __restrict__ qkv,
                    const float* __restrict__ cosr, const float* __restrict__ sinr,
                    const float* __restrict__ qw, const float* __restrict__ qb,
                    const float* __restrict__ kw, const float* __restrict__ kb,
                    const int* __restrict__ pP, const int* __restrict__ pL,
                    float* __restrict__ Q, float* __restrict__ K, float* __restrict__ V)
{
    const int blk  = blockIdx.x;
    const int b    = blk >> 10;
    const int n    = blk & (N_-1);
    const int h    = threadIdx.x >> 5;
    const int lane = threadIdx.x & 31;
    const int P = __ldg(pP), L = __ldg(pL);
    const bool rope = (n >= P) && (n < N_ - L);
    float rc = 1.f, rs = 0.f;
    if (rope) {
        int pos = n - P;
        rc = cosr[pos*32 + lane];
        rs = sinr[pos*32 + lane];
    }
    const float* row = qkv + (size_t)blk * QKV_;
    const size_t obase = (((size_t)(b*H_ + h))*N_ + n) * D_ + 2*lane;

    // Q
    {
        float2 v = *(const float2*)(row + h*D_ + 2*lane);
        float sum = v.x + v.y;
        #pragma unroll
        for (int o = 16; o; o >>= 1) sum += __shfl_xor_sync(~0u, sum, o);
        float mu = sum * (1.0f/64.0f);
        float dx = v.x - mu, dy = v.y - mu;
        float vv = dx*dx + dy*dy;
        #pragma unroll
        for (int o = 16; o; o >>= 1) vv += __shfl_xor_sync(~0u, vv, o);
        float inv = rsqrtf(vv*(1.0f/64.0f) + 1e-5f);
        float2 w2 = *(const float2*)(qw + 2*lane);
        float2 b2 = *(const float2*)(qb + 2*lane);
        float ox = fmaf(dx*inv, w2.x, b2.x);
        float oy = fmaf(dy*inv, w2.y, b2.y);
        if (rope) { float tx = ox*rc - oy*rs, ty = ox*rs + oy*rc; ox = tx; oy = ty; }
        const float QSC = 0.18033688011112042f; // (1/8)*log2(e)
        *(float2*)(Q + obase) = make_float2(ox*QSC, oy*QSC);
    }
    // K
    {
        float2 v = *(const float2*)(row + C_ + h*D_ + 2*lane);
        float sum = v.x + v.y;
        #pragma unroll
        for (int o = 16; o; o >>= 1) sum += __shfl_xor_sync(~0u, sum, o);
        float mu = sum * (1.0f/64.0f);
        float dx = v.x - mu, dy = v.y - mu;
        float vv = dx*dx + dy*dy;
        #pragma unroll
        for (int o = 16; o; o >>= 1) vv += __shfl_xor_sync(~0u, vv, o);
        float inv = rsqrtf(vv*(1.0f/64.0f) + 1e-5f);
        float2 w2 = *(const float2*)(kw + 2*lane);
        float2 b2 = *(const float2*)(kb + 2*lane);
        float ox = fmaf(dx*inv, w2.x, b2.x);
        float oy = fmaf(dy*inv, w2.y, b2.y);
        if (rope) { float tx = ox*rc - oy*rs, ty = ox*rs + oy*rc; ox = tx; oy = ty; }
        *(float2*)(K + obase) = make_float2(ox, oy);
    }
    // V (copy)
    {
        float2 v = *(const float2*)(row + 2*C_ + h*D_ + 2*lane);
        *(float2*)(V + obase) = v;
    }
}

// ---------------- flash attention, 64-row q tiles, fp32 ----------------
// Q pre-scaled by scale*log2e -> softmax uses exp2. Output layout [B,N,H*D].
#define KSTRIDE 68   // 64 + 4 : keeps float4 alignment, conflict-friendly
#define ATT_SMEM ((64*64 + 64*KSTRIDE + 64*64) * 4)   // 50176 bytes

__global__ __launch_bounds__(256)
void attn_kernel(const float* __restrict__ Q, const float* __restrict__ K,
                 const float* __restrict__ V, float* __restrict__ O)
{
    extern __shared__ float sm[];
    float* Qs = sm;                          // [64][64]
    float* KP = sm + 64*64;                  // [64][KSTRIDE] : K tile then P tile
    float* Vs = sm + 64*64 + 64*KSTRIDE;     // [64][64]

    const int tid = threadIdx.x;
    const int rg = tid >> 4, cg = tid & 15;
    const int b = blockIdx.z, h = blockIdx.y;
    const int q0 = blockIdx.x << 6;
    const size_t base = ((size_t)(b*H_ + h)) * N_ * D_;

    const float* Qt = Q + base + (size_t)q0 * D_;
    for (int i = tid; i < 64*16; i += 256) {
        int r = i >> 4, c4 = (i & 15) << 2;
        *(float4*)(Qs + r*64 + c4) = *(const float4*)(Qt + r*64 + c4);
    }

    float o[4][4];
    #pragma unroll
    for (int i = 0; i < 4; i++)
        #pragma unroll
        for (int j = 0; j < 4; j++) o[i][j] = 0.f;
    float mi[4] = {-3.0e38f, -3.0e38f, -3.0e38f, -3.0e38f};
    float li[4] = {0.f, 0.f, 0.f, 0.f};

    for (int kt = 0; kt < N_/64; kt++) {
        __syncthreads();   // previous PV reads done
        const float* Kt = K + base + (size_t)kt*64*D_;
        const float* Vt = V + base + (size_t)kt*64*D_;
        for (int i = tid; i < 64*16; i += 256) {
            int r = i >> 4, c4 = (i & 15) << 2;
            *(float4*)(KP + r*KSTRIDE + c4) = *(const float4*)(Kt + r*64 + c4);
            *(float4*)(Vs + r*64      + c4) = *(const float4*)(Vt + r*64 + c4);
        }
        __syncthreads();

        // S = Q K^T  — thread covers rows rg*4+i, key cols 16*j + cg
        float s[4][4];
        #pragma unroll
        for (int i = 0; i < 4; i++)
            #pragma unroll
            for (int j = 0; j < 4; j++) s[i][j] = 0.f;
        #pragma unroll
        for (int d = 0; d < 64; d += 4) {
            float a[4][4], kk[4][4];
            #pragma unroll
            for (int i = 0; i < 4; i++) {
                float4 t = *(const float4*)(Qs + (rg*4+i)*64 + d);
                a[i][0]=t.x; a[i][1]=t.y; a[i][2]=t.z; a[i][3]=t.w;
            }
            #pragma unroll
            for (int j = 0; j < 4; j++) {
                float4 t = *(const float4*)(KP + (16*j+cg)*KSTRIDE + d);
                kk[j][0]=t.x; kk[j][1]=t.y; kk[j][2]=t.z; kk[j][3]=t.w;
            }
            #pragma unroll
            for (int i = 0; i < 4; i++)
                #pragma unroll
                for (int j = 0; j < 4; j++) {
                    s[i][j] = fmaf(a[i][0], kk[j][0], s[i][j]);
                    s[i][j] = fmaf(a[i][1], kk[j][1], s[i][j]);
                    s[i][j] = fmaf(a[i][2], kk[j][2], s[i][j]);
                    s[i][j] = fmaf(a[i][3], kk[j][3], s[i][j]);
                }
        }

        // online softmax (values already in log2 domain)
        #pragma unroll
        for (int i = 0; i < 4; i++) {
            float mx = fmaxf(fmaxf(s[i][0], s[i][1]), fmaxf(s[i][2], s[i][3]));
            #pragma unroll
            for (int off = 8; off; off >>= 1)
                mx = fmaxf(mx, __shfl_xor_sync(~0u, mx, off));
            float mnew = fmaxf(mi[i], mx);
            float corr = fexp2(mi[i] - mnew);
            mi[i] = mnew;
            float rsum = 0.f;
            #pragma unroll
            for (int j = 0; j < 4; j++) {
                s[i][j] = fexp2(s[i][j] - mnew);
                rsum += s[i][j];
            }
            #pragma unroll
            for (int off = 8; off; off >>= 1)
                rsum += __shfl_xor_sync(~0u, rsum, off);
            li[i] = li[i]*corr + rsum;
            #pragma unroll
            for (int j = 0; j < 4; j++) o[i][j] *= corr;
        }

        __syncthreads();   // all K reads finished; reuse KP as P
        #pragma unroll
        for (int i = 0; i < 4; i++)
            #pragma unroll
            for (int j = 0; j < 4; j++)
                KP[(rg*4+i)*KSTRIDE + 16*j + cg] = s[i][j];
        __syncthreads();

        // O += P V  — thread output cols = cg*4 + j (contiguous)
        #pragma unroll
        for (int c4 = 0; c4 < 16; c4++) {
            float pr[4][4];
            #pragma unroll
            for (int i = 0; i < 4; i++) {
                float4 t = *(const float4*)(KP + (rg*4+i)*KSTRIDE + c4*4);
                pr[i][0]=t.x; pr[i][1]=t.y; pr[i][2]=t.z; pr[i][3]=t.w;
            }
            #pragma unroll
            for (int cc = 0; cc < 4; cc++) {
                float4 v4 = *(const float4*)(Vs + (c4*4+cc)*64 + cg*4);
                #pragma unroll
                for (int i = 0; i < 4; i++) {
                    o[i][0] = fmaf(pr[i][cc], v4.x, o[i][0]);
                    o[i][1] = fmaf(pr[i][cc], v4.y, o[i][1]);
                    o[i][2] = fmaf(pr[i][cc], v4.z, o[i][2]);
                    o[i][3] = fmaf(pr[i][cc], v4.w, o[i][3]);
                }
            }
        }
    }

    #pragma unroll
    for (int i = 0; i < 4; i++) {
        float inv = 1.0f / li[i];
        float4 r;
        r.x = o[i][0]*inv; r.y = o[i][1]*inv; r.z = o[i][2]*inv; r.w = o[i][3]*inv;
        size_t off = ((size_t)(b*N_ + q0 + rg*4 + i))*C_ + h*D_ + cg*4;
        *(float4*)(O + off) = r;
    }
}

// ---------------- launch ----------------
extern "C" void kernel_launch(void* const* d_in, const int* in_sizes, int n_in,
                              void* d_out, int out_size)
{
    const float* x      = (const float*)d_in[0];
    const float* cosr   = (const float*)d_in[1];
    const float* sinr   = (const float*)d_in[2];
    const float* w_qkv  = (const float*)d_in[3];
    const float* q_ln_w = (const float*)d_in[4];
    const float* q_ln_b = (const float*)d_in[5];
    const float* k_ln_w = (const float*)d_in[6];
    const float* k_ln_b = (const float*)d_in[7];
    const float* w_proj = (const float*)d_in[8];
    const float* b_proj = (const float*)d_in[9];
    const int*   pP     = (const int*)d_in[10];
    const int*   pL     = (const int*)d_in[11];
    float* out = (float*)d_out;

    float *qkv, *Q, *K, *V, *att;
    cudaGetSymbolAddress((void**)&qkv, g_qkv);
    cudaGetSymbolAddress((void**)&Q,   g_q);
    cudaGetSymbolAddress((void**)&K,   g_k);
    cudaGetSymbolAddress((void**)&V,   g_v);
    cudaGetSymbolAddress((void**)&att, g_att);

    // 1) QKV projection: [16384,768] @ [768,2304]
    sgemm128<<<dim3(QKV_/128, M_/128), 256>>>(x, w_qkv, qkv, M_, QKV_, C_, nullptr);

    // 2) per-head LN + RoPE + split into [B,H,N,D]
    ln_rope_kernel<<<M_, 384>>>(qkv, cosr, sinr, q_ln_w, q_ln_b, k_ln_w, k_ln_b,
                                pP, pL, Q, K, V);

    // 3) attention
    cudaFuncSetAttribute(attn_kernel, cudaFuncAttributeMaxDynamicSharedMemorySize,
                         ATT_SMEM);
    attn_kernel<<<dim3(N_/64, H_, B_), 256, ATT_SMEM>>>(Q, K, V, att);

    // 4) output projection + bias: [16384,768] @ [768,768]
    sgemm128<<<dim3(C_/128, M_/128), 256>>>(att, w_proj, out, M_, C_, C_, b_proj);
}

// round 3
// speedup vs baseline: 2.6434x; 2.6434x over previous
#include <cuda_runtime.h>
#include <cuda_bf16.h>
#include <cstdint>

// Problem constants (fixed by setup_inputs)
#define B_   16
#define N_   1024
#define C_   768
#define H_   12
#define D_   64
#define M_   (B_*N_)     // 16384
#define QKV_ (3*C_)      // 2304

// ---------------- scratch (device globals: allocation-free) ----------------
__device__ __align__(16) float g_qkv[M_ * QKV_];
__device__ __align__(16) __nv_bfloat16 g_xh[M_*C_],  g_xl[M_*C_];
__device__ __align__(16) __nv_bfloat16 g_wqh[QKV_*C_], g_wql[QKV_*C_];  // [N,K]
__device__ __align__(16) __nv_bfloat16 g_wph[C_*C_],   g_wpl[C_*C_];    // [N,K]
__device__ __align__(16) __nv_bfloat16 g_qh[B_*H_*N_*D_], g_ql[B_*H_*N_*D_];
__device__ __align__(16) __nv_bfloat16 g_kh[B_*H_*N_*D_], g_kl[B_*H_*N_*D_];
__device__ __align__(16) __nv_bfloat16 g_vh[B_*H_*N_*D_], g_vl[B_*H_*N_*D_];
__device__ __align__(16) __nv_bfloat16 g_oh[M_*C_], g_ol[M_*C_];

// ================= low-level helpers =================
__device__ __forceinline__ uint32_t smem_u32(const void* p) {
    uint32_t a;
    asm("{ .reg .u64 t; cvta.to.shared.u64 t, %1; cvt.u32.u64 %0, t; }"
        : "=r"(a) : "l"(p));
    return a;
}
__device__ __forceinline__ uint32_t sw128(uint32_t off) {
    return off ^ ((off >> 3) & 0x70);
}
#define CP_A16(s, g) \
    asm volatile("cp.async.cg.shared.global [%0], [%1], 16;" :: "r"(s), "l"(g) : "memory")
#define CP_COMMIT() asm volatile("cp.async.commit_group;" ::: "memory")
#define CP_WAIT1()  asm volatile("cp.async.wait_group 1;" ::: "memory")
#define CP_WAIT0()  asm volatile("cp.async.wait_group 0;" ::: "memory")

#define LDSM4(r, addr) \
    asm volatile("ldmatrix.sync.aligned.m8n8.x4.shared.b16 {%0,%1,%2,%3}, [%4];" \
        : "=r"((r)[0]), "=r"((r)[1]), "=r"((r)[2]), "=r"((r)[3]) : "r"(addr))
#define LDSM4T(r, addr) \
    asm volatile("ldmatrix.sync.aligned.m8n8.x4.trans.shared.b16 {%0,%1,%2,%3}, [%4];" \
        : "=r"((r)[0]), "=r"((r)[1]), "=r"((r)[2]), "=r"((r)[3]) : "r"(addr))

__device__ __forceinline__ void mma16816(float* c, const uint32_t* a,
                                         uint32_t b0, uint32_t b1) {
    asm volatile(
        "mma.sync.aligned.m16n8k16.row.col.f32.bf16.bf16.f32 "
        "{%0,%1,%2,%3}, {%4,%5,%6,%7}, {%8,%9}, {%0,%1,%2,%3};"
        : "+f"(c[0]), "+f"(c[1]), "+f"(c[2]), "+f"(c[3])
        : "r"(a[0]), "r"(a[1]), "r"(a[2]), "r"(a[3]), "r"(b0), "r"(b1));
}
// pack (lo,hi) floats -> bf16x2 (lo in low 16 bits)
__device__ __forceinline__ uint32_t packbf(float lo, float hi) {
    uint32_t r;
    asm("cvt.rn.bf16x2.f32 %0, %1, %2;" : "=r"(r) : "f"(hi), "f"(lo));
    return r;
}
__device__ __forceinline__ float bflo(uint32_t p) { return __uint_as_float(p << 16); }
__device__ __forceinline__ float bfhi(uint32_t p) { return __uint_as_float(p & 0xFFFF0000u); }

// fast exp2 (FMA pipe only), valid x <= ~0
__device__ __forceinline__ float fexp2(float x) {
    x = fmaxf(x, -120.0f);
    float z  = x + 12582912.0f;
    float zi = z - 12582912.0f;
    float f  = x - zi;
    int   e  = __float_as_int(z);
    float p = 1.3333558e-3f;
    p = fmaf(p, f, 9.6181291e-3f);
    p = fmaf(p, f, 5.5504109e-2f);
    p = fmaf(p, f, 2.4022651e-1f);
    p = fmaf(p, f, 6.9314718e-1f);
    p = fmaf(p, f, 1.0f);
    float s = __int_as_float((e << 23) + 0x3f800000);
    return p * s;
}

// ================= split / transpose prep kernels =================
__global__ __launch_bounds__(256)
void asplit(const float4* __restrict__ in, __nv_bfloat16* __restrict__ h,
            __nv_bfloat16* __restrict__ l)
{
    const uint32_t i = blockIdx.x * 256 + threadIdx.x;
    float4 v = in[i];
    __nv_bfloat16 h0 = __float2bfloat16(v.x), h1 = __float2bfloat16(v.y);
    __nv_bfloat16 h2 = __float2bfloat16(v.z), h3 = __float2bfloat16(v.w);
    __nv_bfloat16 l0 = __float2bfloat16(v.x - __bfloat162float(h0));
    __nv_bfloat16 l1 = __float2bfloat16(v.y - __bfloat162float(h1));
    __nv_bfloat16 l2 = __float2bfloat16(v.z - __bfloat162float(h2));
    __nv_bfloat16 l3 = __float2bfloat16(v.w - __bfloat162float(h3));
    *(__nv_bfloat162*)(h + 4*(size_t)i)     = __nv_bfloat162(h0, h1);
    *(__nv_bfloat162*)(h + 4*(size_t)i + 2) = __nv_bfloat162(h2, h3);
    *(__nv_bfloat162*)(l + 4*(size_t)i)     = __nv_bfloat162(l0, l1);
    *(__nv_bfloat162*)(l + 4*(size_t)i + 2) = __nv_bfloat162(l2, l3);
}

// W[K,N] fp32 -> Wt hi/lo [N,K] bf16 (transpose + split)
__global__ __launch_bounds__(256)
void wsplit_t(const float* __restrict__ W, __nv_bfloat16* __restrict__ Th,
              __nv_bfloat16* __restrict__ Tl, int K, int N)
{
    __shared__ float t[32][33];
    const int kk = blockIdx.x * 32, nn = blockIdx.y * 32;
    const int tx = threadIdx.x & 31, ty = threadIdx.x >> 5;
    #pragma unroll
    for (int i = ty; i < 32; i += 8)
        t[i][tx] = W[(size_t)(kk + i) * N + nn + tx];
    __syncthreads();
    #pragma unroll
    for (int i = ty; i < 32; i += 8) {
        float v = t[tx][i];
        __nv_bfloat16 h = __float2bfloat16(v);
        __nv_bfloat16 l = __float2bfloat16(v - __bfloat162float(h));
        size_t o = (size_t)(nn + i) * K + kk + tx;
        Th[o] = h; Tl[o] = l;
    }
}

// ================= HMMA bf16x3 GEMM =================
// C[M,N] = A[M,K] * B[N,K]^T (+bias), fp32 out. 128x128 tiles, KC=64,
// cp.async double-buffered. A,B pre-split bf16 hi/lo.
#define TILEB 16384                 // 128 rows x 128 bytes
#define GSTAGE (4*TILEB)            // Ah,Al,Bh,Bl
#define GEMM_SMEM (2*GSTAGE)        // 131072

__global__ __launch_bounds__(256)
void sgemm_mma(const __nv_bfloat16* __restrict__ Ah, const __nv_bfloat16* __restrict__ Al,
               const __nv_bfloat16* __restrict__ Bh, const __nv_bfloat16* __restrict__ Bl,
               float* __restrict__ Cm, int Mdim, int Ndim, int Kdim,
               const float* __restrict__ bias)
{
    extern __shared__ char smem[];
    const uint32_t sb = smem_u32(smem);
    const int tid = threadIdx.x;
    const int wid = tid >> 5, lane = tid & 31;
    const int m0 = blockIdx.y * 128, n0 = blockIdx.x * 128;
    const int wm = (wid & 3) * 32, wn = (wid >> 2) * 64;
    const int nchunks = Kdim / 64;

    const __nv_bfloat16* tp[4] = {Ah, Al, Bh, Bl};

    float acc[2][8][4];
    #pragma unroll
    for (int i = 0; i < 2; i++)
        #pragma unroll
        for (int j = 0; j < 8; j++)
            #pragma unroll
            for (int q = 0; q < 4; q++) acc[i][j][q] = 0.f;

    // -------- async stage loader --------
    auto issue = [&](int c) {
        const uint32_t stg = sb + (uint32_t)(c & 1) * GSTAGE;
        const int k0 = c * 64;
        #pragma unroll
        for (int t = 0; t < 16; t++) {
            int e = tid + t * 256;
            int tile = e >> 10;
            int i = e & 1023;
            int row = i >> 3, u = i & 7;
            int grow = (tile < 2 ? m0 : n0) + row;
            const __nv_bfloat16* src = tp[tile] + (size_t)grow * Kdim + k0 + u * 8;
            uint32_t dst = stg + tile * TILEB + sw128((uint32_t)(row * 128 + u * 16));
            unsigned long long ga = (unsigned long long)__cvta_generic_to_global(src);
            CP_A16(dst, ga);
        }
    };

    issue(0); CP_COMMIT();
    issue(1); CP_COMMIT();

    for (int c = 0; c < nchunks; c++) {
        if (c + 1 < nchunks) { CP_WAIT1(); } else { CP_WAIT0(); }
        __syncthreads();

        const uint32_t stg = sb + (uint32_t)(c & 1) * GSTAGE;
        const uint32_t sAh = stg, sAl = stg + TILEB, sBh = stg + 2*TILEB, sBl = stg + 3*TILEB;

        #pragma unroll
        for (int ks = 0; ks < 4; ks++) {
            uint32_t ah[2][4], al[2][4];
            #pragma unroll
            for (int mt = 0; mt < 2; mt++) {
                uint32_t off = sw128((uint32_t)((wm + mt*16 + (lane & 15)) * 128
                                                + ks*32 + (lane & 16)));
                LDSM4(ah[mt], sAh + off);
                LDSM4(al[mt], sAl + off);
            }
            uint32_t bh[4][4], bl[4][4];
            #pragma unroll
            for (int p = 0; p < 4; p++) {
                uint32_t off = sw128((uint32_t)((wn + p*16 + (lane & 7) + ((lane & 16) >> 1)) * 128
                                                + ks*32 + ((lane & 8) << 1)));
                LDSM4(bh[p], sBh + off);
                LDSM4(bl[p], sBl + off);
            }
            #pragma unroll
            for (int mt = 0; mt < 2; mt++)
                #pragma unroll
                for (int p = 0; p < 4; p++)
                    #pragma unroll
                    for (int h2 = 0; h2 < 2; h2++) {
                        int nt = 2*p + h2;
                        mma16816(acc[mt][nt], ah[mt], bh[p][2*h2], bh[p][2*h2+1]);
                        mma16816(acc[mt][nt], ah[mt], bl[p][2*h2], bl[p][2*h2+1]);
                        mma16816(acc[mt][nt], al[mt], bh[p][2*h2], bh[p][2*h2+1]);
                    }
        }
        __syncthreads();
        if (c + 2 < nchunks) { issue(c + 2); CP_COMMIT(); }
    }

    // -------- epilogue --------
    #pragma unroll
    for (int mt = 0; mt < 2; mt++)
        #pragma unroll
        for (int nt = 0; nt < 8; nt++) {
            int row = m0 + wm + mt*16 + (lane >> 2);
            int col = n0 + wn + nt*8 + 2*(lane & 3);
            float b0 = 0.f, b1 = 0.f;
            if (bias) { b0 = bias[col]; b1 = bias[col + 1]; }
            float2 v0 = make_float2(acc[mt][nt][0] + b0, acc[mt][nt][1] + b1);
            float2 v1 = make_float2(acc[mt][nt][2] + b0, acc[mt][nt][3] + b1);
            *(float2*)(Cm + (size_t)row * Ndim + col)       = v0;
            *(float2*)(Cm + (size_t)(row + 8) * Ndim + col) = v1;
        }
}

// ================= per-head LayerNorm + RoPE -> bf16 hi/lo =================
__global__ __launch_bounds__(384)
void ln_rope_kernel(const float* __restrict__ qkv,
                    const float* __restrict__ cosr, const float* __restrict__ sinr,
                    const float* __restrict__ qw, const float* __restrict__ qb,
                    const float* __restrict__ kw, const float* __restrict__ kb,
                    const int* __restrict__ pP, const int* __restrict__ pL,
                    __nv_bfloat16* __restrict__ Qh, __nv_bfloat16* __restrict__ Ql,
                    __nv_bfloat16* __restrict__ Kh, __nv_bfloat16* __restrict__ Kl,
                    __nv_bfloat16* __restrict__ Vh, __nv_bfloat16* __restrict__ Vl)
{
    const int blk  = blockIdx.x;
    const int b    = blk >> 10;
    const int n    = blk & (N_-1);
    const int h    = threadIdx.x >> 5;
    const int lane = threadIdx.x & 31;
    const int P = __ldg(pP), L = __ldg(pL);
    const bool rope = (n >= P) && (n < N_ - L);
    float rc = 1.f, rs = 0.f;
    if (rope) {
        int pos = n - P;
        rc = cosr[pos*32 + lane];
        rs = sinr[pos*32 + lane];
    }
    const float* row = qkv + (size_t)blk * QKV_;
    const size_t obase = (((size_t)(b*H_ + h))*N_ + n) * D_ + 2*lane;

    // Q (scaled by (1/8)*log2(e))
    {
        float2 v = *(const float2*)(row + h*D_ + 2*lane);
        float sum = v.x + v.y;
        #pragma unroll
        for (int o = 16; o; o >>= 1) sum += __shfl_xor_sync(~0u, sum, o);
        float mu = sum * (1.0f/64.0f);
        float dx = v.x - mu, dy = v.y - mu;
        float vv = dx*dx + dy*dy;
        #pragma unroll
        for (int o = 16; o; o >>= 1) vv += __shfl_xor_sync(~0u, vv, o);
        float inv = rsqrtf(vv*(1.0f/64.0f) + 1e-5f);
        float2 w2 = *(const float2*)(qw + 2*lane);
        float2 b2 = *(const float2*)(qb + 2*lane);
        float ox = fmaf(dx*inv, w2.x, b2.x);
        float oy = fmaf(dy*inv, w2.y, b2.y);
        if (rope) { float tx = ox*rc - oy*rs, ty = ox*rs + oy*rc; ox = tx; oy = ty; }
        const float QSC = 0.18033688011112042f;
        ox *= QSC; oy *= QSC;
        __nv_bfloat16 hx = __float2bfloat16(ox), hy = __float2bfloat16(oy);
        __nv_bfloat16 lx = __float2bfloat16(ox - __bfloat162float(hx));
        __nv_bfloat16 ly = __float2bfloat16(oy - __bfloat162float(hy));
        *(__nv_bfloat162*)(Qh + obase) = __nv_bfloat162(hx, hy);
        *(__nv_bfloat162*)(Ql + obase) = __nv_bfloat162(lx, ly);
    }
    // K
    {
        float2 v = *(const float2*)(row + C_ + h*D_ + 2*lane);
        float sum = v.x + v.y;
        #pragma unroll
        for (int o = 16; o; o >>= 1) sum += __shfl_xor_sync(~0u, sum, o);
        float mu = sum * (1.0f/64.0f);
        float dx = v.x - mu, dy = v.y - mu;
        float vv = dx*dx + dy*dy;
        #pragma unroll
        for (int o = 16; o; o >>= 1) vv += __shfl_xor_sync(~0u, vv, o);
        float inv = rsqrtf(vv*(1.0f/64.0f) + 1e-5f);
        float2 w2 = *(const float2*)(kw + 2*lane);
        float2 b2 = *(const float2*)(kb + 2*lane);
        float ox = fmaf(dx*inv, w2.x, b2.x);
        float oy = fmaf(dy*inv, w2.y, b2.y);
        if (rope) { float tx = ox*rc - oy*rs, ty = ox*rs + oy*rc; ox = tx; oy = ty; }
        __nv_bfloat16 hx = __float2bfloat16(ox), hy = __float2bfloat16(oy);
        __nv_bfloat16 lx = __float2bfloat16(ox - __bfloat162float(hx));
        __nv_bfloat16 ly = __float2bfloat16(oy - __bfloat162float(hy));
        *(__nv_bfloat162*)(Kh + obase) = __nv_bfloat162(hx, hy);
        *(__nv_bfloat162*)(Kl + obase) = __nv_bfloat162(lx, ly);
    }
    // V
    {
        float2 v = *(const float2*)(row + 2*C_ + h*D_ + 2*lane);
        __nv_bfloat16 hx = __float2bfloat16(v.x), hy = __float2bfloat16(v.y);
        __nv_bfloat16 lx = __float2bfloat16(v.x - __bfloat162float(hx));
        __nv_bfloat16 ly = __float2bfloat16(v.y - __bfloat162float(hy));
        *(__nv_bfloat162*)(Vh + obase) = __nv_bfloat162(hx, hy);
        *(__nv_bfloat162*)(Vl + obase) = __nv_bfloat162(lx, ly);
    }
}

// ================= HMMA flash attention =================
// 128 q-rows per CTA, 8 warps (16 rows each, full 64-key width).
// Q pre-scaled by scale*log2e; softmax in exp2 domain.
// Output written as bf16 hi/lo in [B,N,C] layout.
#define KTILE 8192                    // 64 rows x 128 bytes
#define ASTAGE (4*KTILE)              // Kh,Kl,Vh,Vl
#define ATT_SMEM (2*TILEB + 2*ASTAGE) // Qh,Ql (32KB) + 2 KV stages (64KB) = 98304

__global__ __launch_bounds__(256)
void attn_mma(const __nv_bfloat16* __restrict__ Qh, const __nv_bfloat16* __restrict__ Ql,
              const __nv_bfloat16* __restrict__ Kh, const __nv_bfloat16* __restrict__ Kl,
              const __nv_bfloat16* __restrict__ Vh, const __nv_bfloat16* __restrict__ Vl,
              __nv_bfloat16* __restrict__ Oh, __nv_bfloat16* __restrict__ Ol)
{
    extern __shared__ char smem[];
    const uint32_t sb = smem_u32(smem);
    const int tid = threadIdx.x;
    const int wid = tid >> 5, lane = tid & 31;
    const int b = blockIdx.z, h = blockIdx.y;
    const int q0 = blockIdx.x * 128;
    const size_t base = ((size_t)(b*H_ + h)) * N_;

    const uint32_t sQh = sb, sQl = sb + TILEB;
    const uint32_t sKV = sb + 2*TILEB;

    // ---- load Q tile (plain loads) ----
    {
        const __nv_bfloat16* srcs[2] = {Qh, Ql};
        #pragma unroll
        for (int t = 0; t < 8; t++) {
            int e = tid + t * 256;
            int tile = e >> 10;
            int i = e & 1023;
            int row = i >> 3, u = i & 7;
            const __nv_bfloat16* src = srcs[tile] + (base + q0 + row) * D_ + u * 8;
            uint4 v = *(const uint4*)src;
            *(uint4*)(smem + (tile ? TILEB : 0) + sw128((uint32_t)(row*128 + u*16))) = v;
        }
    }
    __syncthreads();

    // Q fragments, resident in registers
    uint32_t qh[4][4], ql[4][4];
    #pragma unroll
    for (int ks = 0; ks < 4; ks++) {
        uint32_t off = sw128((uint32_t)((wid*16 + (lane & 15)) * 128 + ks*32 + (lane & 16)));
        LDSM4(qh[ks], sQh + off);
        LDSM4(ql[ks], sQl + off);
    }

    const __nv_bfloat16* tp[4] = {Kh, Kl, Vh, Vl};
    auto issue = [&](int kt) {
        const uint32_t stg = sKV + (uint32_t)(kt & 1) * ASTAGE;
        #pragma unroll
        for (int t = 0; t < 8; t++) {
            int e = tid + t * 256;
            int tile = e >> 9;
            int i = e & 511;
            int row = i >> 3, u = i & 7;
            const __nv_bfloat16* src = tp[tile] + (base + kt*64 + row) * D_ + u * 8;
            uint32_t dst = stg + tile * KTILE + sw128((uint32_t)(row*128 + u*16));
            unsigned long long ga = (unsigned long long)__cvta_generic_to_global(src);
            CP_A16(dst, ga);
        }
    };

    float o[8][4];
    #pragma unroll
    for (int j = 0; j < 8; j++)
        #pragma unroll
        for (int q = 0; q < 4; q++) o[j][q] = 0.f;
    float mi[2] = {-3.0e38f, -3.0e38f};
    float li[2] = {0.f, 0.f};

    issue(0); CP_COMMIT();
    issue(1); CP_COMMIT();

    for (int kt = 0; kt < 16; kt++) {
        if (kt + 1 < 16) { CP_WAIT1(); } else { CP_WAIT0(); }
        __syncthreads();
        const uint32_t stg = sKV + (uint32_t)(kt & 1) * ASTAGE;
        const uint32_t sKh = stg, sKl = stg + KTILE, sVh = stg + 2*KTILE, sVl = stg + 3*KTILE;

        // ---- S = Q K^T (bf16x3) ----
        float s[8][4];
        #pragma unroll
        for (int j = 0; j < 8; j++)
            #pragma unroll
            for (int q = 0; q < 4; q++) s[j][q] = 0.f;

        #pragma unroll
        for (int ks = 0; ks < 4; ks++) {
            uint32_t kh[4][4], kl[4][4];
            #pragma unroll
            for (int p = 0; p < 4; p++) {
                uint32_t off = sw128((uint32_t)((p*16 + (lane & 7) + ((lane & 16) >> 1)) * 128
                                                + ks*32 + ((lane & 8) << 1)));
                LDSM4(kh[p], sKh + off);
                LDSM4(kl[p], sKl + off);
            }
            #pragma unroll
            for (int p = 0; p < 4; p++)
                #pragma unroll
                for (int h2 = 0; h2 < 2; h2++) {
                    int nt = 2*p + h2;
                    mma16816(s[nt], qh[ks], kh[p][2*h2], kh[p][2*h2+1]);
                    mma16816(s[nt], qh[ks], kl[p][2*h2], kl[p][2*h2+1]);
                    mma16816(s[nt], ql[ks], kh[p][2*h2], kh[p][2*h2+1]);
                }
        }

        // ---- online softmax (exp2 domain); rows r1=lane/4, r2=r1+8 ----
        #pragma unroll
        for (int r = 0; r < 2; r++) {
            int i0 = 2*r;                     // acc idx 0,1 (row1) / 2,3 (row2)
            float mx = -3.0e38f;
            #pragma unroll
            for (int nt = 0; nt < 8; nt++)
                mx = fmaxf(mx, fmaxf(s[nt][i0], s[nt][i0+1]));
            mx = fmaxf(mx, __shfl_xor_sync(~0u, mx, 1));
            mx = fmaxf(mx, __shfl_xor_sync(~0u, mx, 2));
            float mnew = fmaxf(mi[r], mx);
            float corr = fexp2(mi[r] - mnew);
            mi[r] = mnew;
            float rsum = 0.f;
            #pragma unroll
            for (int nt = 0; nt < 8; nt++) {
                s[nt][i0]   = fexp2(s[nt][i0]   - mnew);
                s[nt][i0+1] = fexp2(s[nt][i0+1] - mnew);
                rsum += s[nt][i0] + s[nt][i0+1];
            }
            rsum += __shfl_xor_sync(~0u, rsum, 1);
            rsum += __shfl_xor_sync(~0u, rsum, 2);
            li[r] = li[r]*corr + rsum;
            #pragma unroll
            for (int dt = 0; dt < 8; dt++) {
                o[dt][i0]   *= corr;
                o[dt][i0+1] *= corr;
            }
        }

        // ---- O += P V (bf16x3), P frags built in registers ----
        #pragma unroll
        for (int ds = 0; ds < 4; ds++) {
            uint32_t ph[4], pl[4];
            #pragma unroll
            for (int half = 0; half < 2; half++) {      // n-tile 2ds / 2ds+1
                int nt = 2*ds + half;
                uint32_t p0 = packbf(s[nt][0], s[nt][1]);   // row1
                uint32_t p1 = packbf(s[nt][2], s[nt][3]);   // row2
                ph[2*half]   = p0;
                ph[2*half+1] = p1;
                float r00 = s[nt][0] - bflo(p0), r01 = s[nt][1] - bfhi(p0);
                float r10 = s[nt][2] - bflo(p1), r11 = s[nt][3] - bfhi(p1);
                pl[2*half]   = packbf(r00, r01);
                pl[2*half+1] = packbf(r10, r11);
            }
            uint32_t vh[4][4], vl[4][4];
            #pragma unroll
            for (int dj = 0; dj < 4; dj++) {
                uint32_t off = sw128((uint32_t)((ds*16 + (lane & 15)) * 128
                                                + dj*32 + (lane & 16)));
                LDSM4T(vh[dj], sVh + off);
                LDSM4T(vl[dj], sVl + off);
            }
            #pragma unroll
            for (int dj = 0; dj < 4; dj++)
                #pragma unroll
                for (int h2 = 0; h2 < 2; h2++) {
                    int dt = 2*dj + h2;
                    mma16816(o[dt], ph, vh[dj][2*h2], vh[dj][2*h2+1]);
                    mma16816(o[dt], pl, vh[dj][2*h2], vh[dj][2*h2+1]);
                    mma16816(o[dt], ph, vl[dj][2*h2], vl[dj][2*h2+1]);
                }
        }

        __syncthreads();
        if (kt + 2 < 16) { issue(kt + 2); CP_COMMIT(); }
    }

    // ---- epilogue: normalize, split hi/lo, store [B,N,C] ----
    const float inv1 = 1.0f / li[0];
    const float inv2 = 1.0f / li[1];
    const int row1 = q0 + wid*16 + (lane >> 2);
    #pragma unroll
    for (int dt = 0; dt < 8; dt++) {
        int col = h*D_ + dt*8 + 2*(lane & 3);
        float a0 = o[dt][0]*inv1, a1 = o[dt][1]*inv1;
        float b0 = o[dt][2]*inv2, b1 = o[dt][3]*inv2;
        uint32_t h0 = packbf(a0, a1);
        uint32_t l0 = packbf(a0 - bflo(h0), a1 - bfhi(h0));
        uint32_t h1 = packbf(b0, b1);
        uint32_t l1 = packbf(b0 - bflo(h1), b1 - bfhi(h1));
        size_t i1 = (size_t)(b*N_ + row1) * C_ + col;
        size_t i2 = (size_t)(b*N_ + row1 + 8) * C_ + col;
        *(uint32_t*)(Oh + i1) = h0;
        *(uint32_t*)(Ol + i1) = l0;
        *(uint32_t*)(Oh + i2) = h1;
        *(uint32_t*)(Ol + i2) = l1;
    }
}

// ================= launch =================
extern "C" void kernel_launch(void* const* d_in, const int* in_sizes, int n_in,
                              void* d_out, int out_size)
{
    const float* x      = (const float*)d_in[0];
    const float* cosr   = (const float*)d_in[1];
    const float* sinr   = (const float*)d_in[2];
    const float* w_qkv  = (const float*)d_in[3];
    const float* q_ln_w = (const float*)d_in[4];
    const float* q_ln_b = (const float*)d_in[5];
    const float* k_ln_w = (const float*)d_in[6];
    const float* k_ln_b = (const float*)d_in[7];
    const float* w_proj = (const float*)d_in[8];
    const float* b_proj = (const float*)d_in[9];
    const int*   pP     = (const int*)d_in[10];
    const int*   pL     = (const int*)d_in[11];
    float* out = (float*)d_out;

    float* qkv;
    __nv_bfloat16 *xh, *xl, *wqh, *wql, *wph, *wpl;
    __nv_bfloat16 *qh, *ql, *kh, *kl, *vh, *vl, *oh, *ol;
    cudaGetSymbolAddress((void**)&qkv, g_qkv);
    cudaGetSymbolAddress((void**)&xh,  g_xh);
    cudaGetSymbolAddress((void**)&xl,  g_xl);
    cudaGetSymbolAddress((void**)&wqh, g_wqh);
    cudaGetSymbolAddress((void**)&wql, g_wql);
    cudaGetSymbolAddress((void**)&wph, g_wph);
    cudaGetSymbolAddress((void**)&wpl, g_wpl);
    cudaGetSymbolAddress((void**)&qh,  g_qh);
    cudaGetSymbolAddress((void**)&ql,  g_ql);
    cudaGetSymbolAddress((void**)&kh,  g_kh);
    cudaGetSymbolAddress((void**)&kl,  g_kl);
    cudaGetSymbolAddress((void**)&vh,  g_vh);
    cudaGetSymbolAddress((void**)&vl,  g_vl);
    cudaGetSymbolAddress((void**)&oh,  g_oh);
    cudaGetSymbolAddress((void**)&ol,  g_ol);

    cudaFuncSetAttribute(sgemm_mma, cudaFuncAttributeMaxDynamicSharedMemorySize, GEMM_SMEM);
    cudaFuncSetAttribute(attn_mma,  cudaFuncAttributeMaxDynamicSharedMemorySize, ATT_SMEM);

    // 0) weight transpose+split, input split
    wsplit_t<<<dim3(C_/32, QKV_/32), 256>>>(w_qkv, wqh, wql, C_, QKV_);
    wsplit_t<<<dim3(C_/32, C_/32),   256>>>(w_proj, wph, wpl, C_, C_);
    asplit<<<(M_*C_/4)/256, 256>>>((const float4*)x, xh, xl);

    // 1) QKV projection
    sgemm_mma<<<dim3(QKV_/128, M_/128), 256, GEMM_SMEM>>>(
        xh, xl, wqh, wql, qkv, M_, QKV_, C_, nullptr);

    // 2) LN + RoPE -> bf16 hi/lo [B,H,N,D]
    ln_rope_kernel<<<M_, 384>>>(qkv, cosr, sinr, q_ln_w, q_ln_b, k_ln_w, k_ln_b,
                                pP, pL, qh, ql, kh, kl, vh, vl);

    // 3) attention -> bf16 hi/lo [B,N,C]
    attn_mma<<<dim3(N_/128, H_, B_), 256, ATT_SMEM>>>(qh, ql, kh, kl, vh, vl, oh, ol);

    // 4) output projection + bias
    sgemm_mma<<<dim3(C_/128, M_/128), 256, GEMM_SMEM>>>(
        oh, ol, wph, wpl, out, M_, C_, C_, b_proj);
}

// round 4
// speedup vs baseline: 2.8695x; 1.0856x over previous
#include <cuda_runtime.h>
#include <cuda_bf16.h>
#include <cstdint>

// Problem constants (fixed by setup_inputs)
#define B_   16
#define N_   1024
#define C_   768
#define H_   12
#define D_   64
#define M_   (B_*N_)     // 16384
#define QKV_ (3*C_)      // 2304

// ---------------- scratch (device globals: allocation-free) ----------------
__device__ __align__(16) float g_qkv[M_ * QKV_];
__device__ __align__(16) __nv_bfloat16 g_xh[M_*C_],  g_xl[M_*C_];
__device__ __align__(16) __nv_bfloat16 g_wqh[QKV_*C_], g_wql[QKV_*C_];  // [N,K]
__device__ __align__(16) __nv_bfloat16 g_wph[C_*C_],   g_wpl[C_*C_];    // [N,K]
__device__ __align__(16) __nv_bfloat16 g_qh[B_*H_*N_*D_], g_ql[B_*H_*N_*D_];
__device__ __align__(16) __nv_bfloat16 g_kh[B_*H_*N_*D_], g_kl[B_*H_*N_*D_];
__device__ __align__(16) __nv_bfloat16 g_vh[B_*H_*N_*D_], g_vl[B_*H_*N_*D_];
__device__ __align__(16) __nv_bfloat16 g_oh[M_*C_], g_ol[M_*C_];

// ================= low-level helpers =================
__device__ __forceinline__ uint32_t smem_u32(const void* p) {
    uint32_t a;
    asm("{ .reg .u64 t; cvta.to.shared.u64 t, %1; cvt.u32.u64 %0, t; }"
        : "=r"(a) : "l"(p));
    return a;
}
__device__ __forceinline__ uint32_t sw128(uint32_t off) {
    return off ^ ((off >> 3) & 0x70);
}
__device__ __forceinline__ uint32_t sw64(uint32_t off) {
    return off ^ ((off >> 3) & 0x30);
}
#define CP_A16(s, g) \
    asm volatile("cp.async.cg.shared.global [%0], [%1], 16;" :: "r"(s), "l"(g) : "memory")
#define CP_COMMIT() asm volatile("cp.async.commit_group;" ::: "memory")
#define CP_WAIT1()  asm volatile("cp.async.wait_group 1;" ::: "memory")
#define CP_WAIT0()  asm volatile("cp.async.wait_group 0;" ::: "memory")

#define LDSM4(r, addr) \
    asm volatile("ldmatrix.sync.aligned.m8n8.x4.shared.b16 {%0,%1,%2,%3}, [%4];" \
        : "=r"((r)[0]), "=r"((r)[1]), "=r"((r)[2]), "=r"((r)[3]) : "r"(addr))
#define LDSM4T(r, addr) \
    asm volatile("ldmatrix.sync.aligned.m8n8.x4.trans.shared.b16 {%0,%1,%2,%3}, [%4];" \
        : "=r"((r)[0]), "=r"((r)[1]), "=r"((r)[2]), "=r"((r)[3]) : "r"(addr))

__device__ __forceinline__ void mma16816(float* c, const uint32_t* a,
                                         uint32_t b0, uint32_t b1) {
    asm volatile(
        "mma.sync.aligned.m16n8k16.row.col.f32.bf16.bf16.f32 "
        "{%0,%1,%2,%3}, {%4,%5,%6,%7}, {%8,%9}, {%0,%1,%2,%3};"
        : "+f"(c[0]), "+f"(c[1]), "+f"(c[2]), "+f"(c[3])
        : "r"(a[0]), "r"(a[1]), "r"(a[2]), "r"(a[3]), "r"(b0), "r"(b1));
}
// pack (lo,hi) floats -> bf16x2 (lo in low 16 bits)
__device__ __forceinline__ uint32_t packbf(float lo, float hi) {
    uint32_t r;
    asm("cvt.rn.bf16x2.f32 %0, %1, %2;" : "=r"(r) : "f"(hi), "f"(lo));
    return r;
}
__device__ __forceinline__ float bflo(uint32_t p) { return __uint_as_float(p << 16); }
__device__ __forceinline__ float bfhi(uint32_t p) { return __uint_as_float(p & 0xFFFF0000u); }

// fast exp2 (FMA pipe only), valid x <= ~0
__device__ __forceinline__ float fexp2(float x) {
    x = fmaxf(x, -120.0f);
    float z  = x + 12582912.0f;
    float zi = z - 12582912.0f;
    float f  = x - zi;
    int   e  = __float_as_int(z);
    float p = 1.3333558e-3f;
    p = fmaf(p, f, 9.6181291e-3f);
    p = fmaf(p, f, 5.5504109e-2f);
    p = fmaf(p, f, 2.4022651e-1f);
    p = fmaf(p, f, 6.9314718e-1f);
    p = fmaf(p, f, 1.0f);
    float s = __int_as_float((e << 23) + 0x3f800000);
    return p * s;
}

// ================= split / transpose prep kernels =================
__global__ __launch_bounds__(256)
void asplit(const float4* __restrict__ in, __nv_bfloat16* __restrict__ h,
            __nv_bfloat16* __restrict__ l)
{
    const uint32_t i = blockIdx.x * 256 + threadIdx.x;
    float4 v = in[i];
    __nv_bfloat16 h0 = __float2bfloat16(v.x), h1 = __float2bfloat16(v.y);
    __nv_bfloat16 h2 = __float2bfloat16(v.z), h3 = __float2bfloat16(v.w);
    __nv_bfloat16 l0 = __float2bfloat16(v.x - __bfloat162float(h0));
    __nv_bfloat16 l1 = __float2bfloat16(v.y - __bfloat162float(h1));
    __nv_bfloat16 l2 = __float2bfloat16(v.z - __bfloat162float(h2));
    __nv_bfloat16 l3 = __float2bfloat16(v.w - __bfloat162float(h3));
    *(__nv_bfloat162*)(h + 4*(size_t)i)     = __nv_bfloat162(h0, h1);
    *(__nv_bfloat162*)(h + 4*(size_t)i + 2) = __nv_bfloat162(h2, h3);
    *(__nv_bfloat162*)(l + 4*(size_t)i)     = __nv_bfloat162(l0, l1);
    *(__nv_bfloat162*)(l + 4*(size_t)i + 2) = __nv_bfloat162(l2, l3);
}

// W[K,N] fp32 -> Wt hi/lo [N,K] bf16 (transpose + split)
__global__ __launch_bounds__(256)
void wsplit_t(const float* __restrict__ W, __nv_bfloat16* __restrict__ Th,
              __nv_bfloat16* __restrict__ Tl, int K, int N)
{
    __shared__ float t[32][33];
    const int kk = blockIdx.x * 32, nn = blockIdx.y * 32;
    const int tx = threadIdx.x & 31, ty = threadIdx.x >> 5;
    #pragma unroll
    for (int i = ty; i < 32; i += 8)
        t[i][tx] = W[(size_t)(kk + i) * N + nn + tx];
    __syncthreads();
    #pragma unroll
    for (int i = ty; i < 32; i += 8) {
        float v = t[tx][i];
        __nv_bfloat16 h = __float2bfloat16(v);
        __nv_bfloat16 l = __float2bfloat16(v - __bfloat162float(h));
        size_t o = (size_t)(nn + i) * K + kk + tx;
        Th[o] = h; Tl[o] = l;
    }
}

// ================= HMMA bf16x3 GEMM =================
// C[M,N] = A[M,K] * B[N,K]^T (+bias), fp32 out. 128x128 tiles, KC=32,
// 2-stage cp.async, 64KB smem -> 2 CTAs/SM. A,B pre-split bf16 hi/lo.
#define GTILE 8192                  // 128 rows x 64 bytes
#define GSTAGE (4*GTILE)            // Ah,Al,Bh,Bl = 32 KB
#define GEMM_SMEM (2*GSTAGE)        // 65536

__global__ __launch_bounds__(256, 2)
void sgemm_mma(const __nv_bfloat16* __restrict__ Ah, const __nv_bfloat16* __restrict__ Al,
               const __nv_bfloat16* __restrict__ Bh, const __nv_bfloat16* __restrict__ Bl,
               float* __restrict__ Cm, int Mdim, int Ndim, int Kdim,
               const float* __restrict__ bias)
{
    extern __shared__ char smem[];
    const uint32_t sb = smem_u32(smem);
    const int tid = threadIdx.x;
    const int wid = tid >> 5, lane = tid & 31;
    const int m0 = blockIdx.y * 128, n0 = blockIdx.x * 128;
    const int wm = (wid & 3) * 32, wn = (wid >> 2) * 64;
    const int nchunks = Kdim / 32;

    const __nv_bfloat16* tp[4] = {Ah, Al, Bh, Bl};

    float acc[2][8][4];
    #pragma unroll
    for (int i = 0; i < 2; i++)
        #pragma unroll
        for (int j = 0; j < 8; j++)
            #pragma unroll
            for (int q = 0; q < 4; q++) acc[i][j][q] = 0.f;

    // -------- async stage loader: 32 KB per chunk --------
    auto issue = [&](int c) {
        const uint32_t stg = sb + (uint32_t)(c & 1) * GSTAGE;
        const int k0 = c * 32;
        #pragma unroll
        for (int t = 0; t < 8; t++) {
            int e = tid + t * 256;
            int tile = e >> 9;
            int i = e & 511;
            int row = i >> 2, u = i & 3;
            int grow = (tile < 2 ? m0 : n0) + row;
            const __nv_bfloat16* src = tp[tile] + (size_t)grow * Kdim + k0 + u * 8;
            uint32_t dst = stg + tile * GTILE + sw64((uint32_t)(row * 64 + u * 16));
            unsigned long long ga = (unsigned long long)__cvta_generic_to_global(src);
            CP_A16(dst, ga);
        }
    };

    issue(0); CP_COMMIT();
    issue(1); CP_COMMIT();

    for (int c = 0; c < nchunks; c++) {
        if (c + 1 < nchunks) { CP_WAIT1(); } else { CP_WAIT0(); }
        __syncthreads();

        const uint32_t stg = sb + (uint32_t)(c & 1) * GSTAGE;
        const uint32_t sAh = stg, sAl = stg + GTILE, sBh = stg + 2*GTILE, sBl = stg + 3*GTILE;

        #pragma unroll
        for (int ks = 0; ks < 2; ks++) {
            uint32_t ah[2][4], al[2][4];
            #pragma unroll
            for (int mt = 0; mt < 2; mt++) {
                uint32_t off = sw64((uint32_t)((wm + mt*16 + (lane & 15)) * 64
                                               + ks*32 + (lane & 16)));
                LDSM4(ah[mt], sAh + off);
                LDSM4(al[mt], sAl + off);
            }
            uint32_t bh[4][4], bl[4][4];
            #pragma unroll
            for (int p = 0; p < 4; p++) {
                uint32_t off = sw64((uint32_t)((wn + p*16 + (lane & 7) + ((lane & 16) >> 1)) * 64
                                               + ks*32 + ((lane & 8) << 1)));
                LDSM4(bh[p], sBh + off);
                LDSM4(bl[p], sBl + off);
            }
            #pragma unroll
            for (int mt = 0; mt < 2; mt++)
                #pragma unroll
                for (int p = 0; p < 4; p++)
                    #pragma unroll
                    for (int h2 = 0; h2 < 2; h2++) {
                        int nt = 2*p + h2;
                        mma16816(acc[mt][nt], ah[mt], bh[p][2*h2], bh[p][2*h2+1]);
                        mma16816(acc[mt][nt], ah[mt], bl[p][2*h2], bl[p][2*h2+1]);
                        mma16816(acc[mt][nt], al[mt], bh[p][2*h2], bh[p][2*h2+1]);
                    }
        }
        __syncthreads();
        if (c + 2 < nchunks) { issue(c + 2); CP_COMMIT(); }
    }

    // -------- epilogue --------
    #pragma unroll
    for (int mt = 0; mt < 2; mt++)
        #pragma unroll
        for (int nt = 0; nt < 8; nt++) {
            int row = m0 + wm + mt*16 + (lane >> 2);
            int col = n0 + wn + nt*8 + 2*(lane & 3);
            float b0 = 0.f, b1 = 0.f;
            if (bias) { b0 = bias[col]; b1 = bias[col + 1]; }
            float2 v0 = make_float2(acc[mt][nt][0] + b0, acc[mt][nt][1] + b1);
            float2 v1 = make_float2(acc[mt][nt][2] + b0, acc[mt][nt][3] + b1);
            *(float2*)(Cm + (size_t)row * Ndim + col)       = v0;
            *(float2*)(Cm + (size_t)(row + 8) * Ndim + col) = v1;
        }
}

// ================= per-head LayerNorm + RoPE -> bf16 hi/lo =================
__global__ __launch_bounds__(384)
void ln_rope_kernel(const float* __restrict__ qkv,
                    const float* __restrict__ cosr, const float* __restrict__ sinr,
                    const float* __restrict__ qw, const float* __restrict__ qb,
                    const float* __restrict__ kw, const float* __restrict__ kb,
                    const int* __restrict__ pP, const int* __restrict__ pL,
                    __nv_bfloat16* __restrict__ Qh, __nv_bfloat16* __restrict__ Ql,
                    __nv_bfloat16* __restrict__ Kh, __nv_bfloat16* __restrict__ Kl,
                    __nv_bfloat16* __restrict__ Vh, __nv_bfloat16* __restrict__ Vl)
{
    const int blk  = blockIdx.x;
    const int b    = blk >> 10;
    const int n    = blk & (N_-1);
    const int h    = threadIdx.x >> 5;
    const int lane = threadIdx.x & 31;
    const int P = __ldg(pP), L = __ldg(pL);
    const bool rope = (n >= P) && (n < N_ - L);
    float rc = 1.f, rs = 0.f;
    if (rope) {
        int pos = n - P;
        rc = cosr[pos*32 + lane];
        rs = sinr[pos*32 + lane];
    }
    const float* row = qkv + (size_t)blk * QKV_;
    const size_t obase = (((size_t)(b*H_ + h))*N_ + n) * D_ + 2*lane;

    // Q (scaled by (1/8)*log2(e))
    {
        float2 v = *(const float2*)(row + h*D_ + 2*lane);
        float sum = v.x + v.y;
        #pragma unroll
        for (int o = 16; o; o >>= 1) sum += __shfl_xor_sync(~0u, sum, o);
        float mu = sum * (1.0f/64.0f);
        float dx = v.x - mu, dy = v.y - mu;
        float vv = dx*dx + dy*dy;
        #pragma unroll
        for (int o = 16; o; o >>= 1) vv += __shfl_xor_sync(~0u, vv, o);
        float inv = rsqrtf(vv*(1.0f/64.0f) + 1e-5f);
        float2 w2 = *(const float2*)(qw + 2*lane);
        float2 b2 = *(const float2*)(qb + 2*lane);
        float ox = fmaf(dx*inv, w2.x, b2.x);
        float oy = fmaf(dy*inv, w2.y, b2.y);
        if (rope) { float tx = ox*rc - oy*rs, ty = ox*rs + oy*rc; ox = tx; oy = ty; }
        const float QSC = 0.18033688011112042f;
        ox *= QSC; oy *= QSC;
        __nv_bfloat16 hx = __float2bfloat16(ox), hy = __float2bfloat16(oy);
        __nv_bfloat16 lx = __float2bfloat16(ox - __bfloat162float(hx));
        __nv_bfloat16 ly = __float2bfloat16(oy - __bfloat162float(hy));
        *(__nv_bfloat162*)(Qh + obase) = __nv_bfloat162(hx, hy);
        *(__nv_bfloat162*)(Ql + obase) = __nv_bfloat162(lx, ly);
    }
    // K
    {
        float2 v = *(const float2*)(row + C_ + h*D_ + 2*lane);
        float sum = v.x + v.y;
        #pragma unroll
        for (int o = 16; o; o >>= 1) sum += __shfl_xor_sync(~0u, sum, o);
        float mu = sum * (1.0f/64.0f);
        float dx = v.x - mu, dy = v.y - mu;
        float vv = dx*dx + dy*dy;
        #pragma unroll
        for (int o = 16; o; o >>= 1) vv += __shfl_xor_sync(~0u, vv, o);
        float inv = rsqrtf(vv*(1.0f/64.0f) + 1e-5f);
        float2 w2 = *(const float2*)(kw + 2*lane);
        float2 b2 = *(const float2*)(kb + 2*lane);
        float ox = fmaf(dx*inv, w2.x, b2.x);
        float oy = fmaf(dy*inv, w2.y, b2.y);
        if (rope) { float tx = ox*rc - oy*rs, ty = ox*rs + oy*rc; ox = tx; oy = ty; }
        __nv_bfloat16 hx = __float2bfloat16(ox), hy = __float2bfloat16(oy);
        __nv_bfloat16 lx = __float2bfloat16(ox - __bfloat162float(hx));
        __nv_bfloat16 ly = __float2bfloat16(oy - __bfloat162float(hy));
        *(__nv_bfloat162*)(Kh + obase) = __nv_bfloat162(hx, hy);
        *(__nv_bfloat162*)(Kl + obase) = __nv_bfloat162(lx, ly);
    }
    // V
    {
        float2 v = *(const float2*)(row + 2*C_ + h*D_ + 2*lane);
        __nv_bfloat16 hx = __float2bfloat16(v.x), hy = __float2bfloat16(v.y);
        __nv_bfloat16 lx = __float2bfloat16(v.x - __bfloat162float(hx));
        __nv_bfloat16 ly = __float2bfloat16(v.y - __bfloat162float(hy));
        *(__nv_bfloat162*)(Vh + obase) = __nv_bfloat162(hx, hy);
        *(__nv_bfloat162*)(Vl + obase) = __nv_bfloat162(lx, ly);
    }
}

// ================= HMMA flash attention =================
// 128 q-rows per CTA, 8 warps (16 rows each, full 64-key width).
// Q staged through KV smem then register-resident; 64KB smem -> 2 CTAs/SM.
#define KTILE 8192                    // 64 rows x 128 bytes
#define ASTAGE (4*KTILE)              // Kh,Kl,Vh,Vl = 32 KB
#define ATT_SMEM (2*ASTAGE)           // 65536

__global__ __launch_bounds__(256, 2)
void attn_mma(const __nv_bfloat16* __restrict__ Qh, const __nv_bfloat16* __restrict__ Ql,
              const __nv_bfloat16* __restrict__ Kh, const __nv_bfloat16* __restrict__ Kl,
              const __nv_bfloat16* __restrict__ Vh, const __nv_bfloat16* __restrict__ Vl,
              __nv_bfloat16* __restrict__ Oh, __nv_bfloat16* __restrict__ Ol)
{
    extern __shared__ char smem[];
    const uint32_t sb = smem_u32(smem);
    const int tid = threadIdx.x;
    const int wid = tid >> 5, lane = tid & 31;
    const int b = blockIdx.z, h = blockIdx.y;
    const int q0 = blockIdx.x * 128;
    const size_t base = ((size_t)(b*H_ + h)) * N_;

    // ---- stage Q tile (hi at sb, lo at sb+16KB) in stage-0 area ----
    {
        const __nv_bfloat16* srcs[2] = {Qh, Ql};
        #pragma unroll
        for (int t = 0; t < 8; t++) {
            int e = tid + t * 256;
            int tile = e >> 10;
            int i = e & 1023;
            int row = i >> 3, u = i & 7;
            const __nv_bfloat16* src = srcs[tile] + (base + q0 + row) * D_ + u * 8;
            uint4 v = *(const uint4*)src;
            *(uint4*)(smem + tile*16384 + sw128((uint32_t)(row*128 + u*16))) = v;
        }
    }
    __syncthreads();

    // Q fragments, register-resident
    uint32_t qh[4][4], ql[4][4];
    #pragma unroll
    for (int ks = 0; ks < 4; ks++) {
        uint32_t off = sw128((uint32_t)((wid*16 + (lane & 15)) * 128 + ks*32 + (lane & 16)));
        LDSM4(qh[ks], sb + off);
        LDSM4(ql[ks], sb + 16384 + off);
    }
    __syncthreads();   // Q reads done; stage-0 area reusable for KV

    const __nv_bfloat16* tp[4] = {Kh, Kl, Vh, Vl};
    auto issue = [&](int kt) {
        const uint32_t stg = sb + (uint32_t)(kt & 1) * ASTAGE;
        #pragma unroll
        for (int t = 0; t < 8; t++) {
            int e = tid + t * 256;
            int tile = e >> 9;
            int i = e & 511;
            int row = i >> 3, u = i & 7;
            const __nv_bfloat16* src = tp[tile] + (base + kt*64 + row) * D_ + u * 8;
            uint32_t dst = stg + tile * KTILE + sw128((uint32_t)(row*128 + u*16));
            unsigned long long ga = (unsigned long long)__cvta_generic_to_global(src);
            CP_A16(dst, ga);
        }
    };

    float o[8][4];
    #pragma unroll
    for (int j = 0; j < 8; j++)
        #pragma unroll
        for (int q = 0; q < 4; q++) o[j][q] = 0.f;
    float mi[2] = {-3.0e38f, -3.0e38f};
    float li[2] = {0.f, 0.f};

    issue(0); CP_COMMIT();
    issue(1); CP_COMMIT();

    for (int kt = 0; kt < 16; kt++) {
        if (kt + 1 < 16) { CP_WAIT1(); } else { CP_WAIT0(); }
        __syncthreads();
        const uint32_t stg = sb + (uint32_t)(kt & 1) * ASTAGE;
        const uint32_t sKh = stg, sKl = stg + KTILE, sVh = stg + 2*KTILE, sVl = stg + 3*KTILE;

        // ---- S = Q K^T (bf16x3) ----
        float s[8][4];
        #pragma unroll
        for (int j = 0; j < 8; j++)
            #pragma unroll
            for (int q = 0; q < 4; q++) s[j][q] = 0.f;

        #pragma unroll
        for (int ks = 0; ks < 4; ks++) {
            uint32_t kh[4][4], kl[4][4];
            #pragma unroll
            for (int p = 0; p < 4; p++) {
                uint32_t off = sw128((uint32_t)((p*16 + (lane & 7) + ((lane & 16) >> 1)) * 128
                                                + ks*32 + ((lane & 8) << 1)));
                LDSM4(kh[p], sKh + off);
                LDSM4(kl[p], sKl + off);
            }
            #pragma unroll
            for (int p = 0; p < 4; p++)
                #pragma unroll
                for (int h2 = 0; h2 < 2; h2++) {
                    int nt = 2*p + h2;
                    mma16816(s[nt], qh[ks], kh[p][2*h2], kh[p][2*h2+1]);
                    mma16816(s[nt], qh[ks], kl[p][2*h2], kl[p][2*h2+1]);
                    mma16816(s[nt], ql[ks], kh[p][2*h2], kh[p][2*h2+1]);
                }
        }

        // ---- online softmax (exp2 domain); rows r1=lane/4, r2=r1+8 ----
        #pragma unroll
        for (int r = 0; r < 2; r++) {
            int i0 = 2*r;
            float mx = -3.0e38f;
            #pragma unroll
            for (int nt = 0; nt < 8; nt++)
                mx = fmaxf(mx, fmaxf(s[nt][i0], s[nt][i0+1]));
            mx = fmaxf(mx, __shfl_xor_sync(~0u, mx, 1));
            mx = fmaxf(mx, __shfl_xor_sync(~0u, mx, 2));
            float mnew = fmaxf(mi[r], mx);
            float corr = fexp2(mi[r] - mnew);
            mi[r] = mnew;
            float rsum = 0.f;
            #pragma unroll
            for (int nt = 0; nt < 8; nt++) {
                s[nt][i0]   = fexp2(s[nt][i0]   - mnew);
                s[nt][i0+1] = fexp2(s[nt][i0+1] - mnew);
                rsum += s[nt][i0] + s[nt][i0+1];
            }
            rsum += __shfl_xor_sync(~0u, rsum, 1);
            rsum += __shfl_xor_sync(~0u, rsum, 2);
            li[r] = li[r]*corr + rsum;
            #pragma unroll
            for (int dt = 0; dt < 8; dt++) {
                o[dt][i0]   *= corr;
                o[dt][i0+1] *= corr;
            }
        }

        // ---- O += P V (bf16x3), P frags built in registers ----
        #pragma unroll
        for (int ds = 0; ds < 4; ds++) {
            uint32_t ph[4], pl[4];
            #pragma unroll
            for (int half = 0; half < 2; half++) {
                int nt = 2*ds + half;
                uint32_t p0 = packbf(s[nt][0], s[nt][1]);
                uint32_t p1 = packbf(s[nt][2], s[nt][3]);
                ph[2*half]   = p0;
                ph[2*half+1] = p1;
                float r00 = s[nt][0] - bflo(p0), r01 = s[nt][1] - bfhi(p0);
                float r10 = s[nt][2] - bflo(p1), r11 = s[nt][3] - bfhi(p1);
                pl[2*half]   = packbf(r00, r01);
                pl[2*half+1] = packbf(r10, r11);
            }
            uint32_t vh[4][4], vl[4][4];
            #pragma unroll
            for (int dj = 0; dj < 4; dj++) {
                uint32_t off = sw128((uint32_t)((ds*16 + (lane & 15)) * 128
                                                + dj*32 + (lane & 16)));
                LDSM4T(vh[dj], sVh + off);
                LDSM4T(vl[dj], sVl + off);
            }
            #pragma unroll
            for (int dj = 0; dj < 4; dj++)
                #pragma unroll
                for (int h2 = 0; h2 < 2; h2++) {
                    int dt = 2*dj + h2;
                    mma16816(o[dt], ph, vh[dj][2*h2], vh[dj][2*h2+1]);
                    mma16816(o[dt], pl, vh[dj][2*h2], vh[dj][2*h2+1]);
                    mma16816(o[dt], ph, vl[dj][2*h2], vl[dj][2*h2+1]);
                }
        }

        __syncthreads();
        if (kt + 2 < 16) { issue(kt + 2); CP_COMMIT(); }
    }

    // ---- epilogue: normalize, split hi/lo, store [B,N,C] ----
    const float inv1 = 1.0f / li[0];
    const float inv2 = 1.0f / li[1];
    const int row1 = q0 + wid*16 + (lane >> 2);
    #pragma unroll
    for (int dt = 0; dt < 8; dt++) {
        int col = h*D_ + dt*8 + 2*(lane & 3);
        float a0 = o[dt][0]*inv1, a1 = o[dt][1]*inv1;
        float b0 = o[dt][2]*inv2, b1 = o[dt][3]*inv2;
        uint32_t h0 = packbf(a0, a1);
        uint32_t l0 = packbf(a0 - bflo(h0), a1 - bfhi(h0));
        uint32_t h1 = packbf(b0, b1);
        uint32_t l1 = packbf(b0 - bflo(h1), b1 - bfhi(h1));
        size_t i1 = (size_t)(b*N_ + row1) * C_ + col;
        size_t i2 = (size_t)(b*N_ + row1 + 8) * C_ + col;
        *(uint32_t*)(Oh + i1) = h0;
        *(uint32_t*)(Ol + i1) = l0;
        *(uint32_t*)(Oh + i2) = h1;
        *(uint32_t*)(Ol + i2) = l1;
    }
}

// ================= launch =================
extern "C" void kernel_launch(void* const* d_in, const int* in_sizes, int n_in,
                              void* d_out, int out_size)
{
    const float* x      = (const float*)d_in[0];
    const float* cosr   = (const float*)d_in[1];
    const float* sinr   = (const float*)d_in[2];
    const float* w_qkv  = (const float*)d_in[3];
    const float* q_ln_w = (const float*)d_in[4];
    const float* q_ln_b = (const float*)d_in[5];
    const float* k_ln_w = (const float*)d_in[6];
    const float* k_ln_b = (const float*)d_in[7];
    const float* w_proj = (const float*)d_in[8];
    const float* b_proj = (const float*)d_in[9];
    const int*   pP     = (const int*)d_in[10];
    const int*   pL     = (const int*)d_in[11];
    float* out = (float*)d_out;

    float* qkv;
    __nv_bfloat16 *xh, *xl, *wqh, *wql, *wph, *wpl;
    __nv_bfloat16 *qh, *ql, *kh, *kl, *vh, *vl, *oh, *ol;
    cudaGetSymbolAddress((void**)&qkv, g_qkv);
    cudaGetSymbolAddress((void**)&xh,  g_xh);
    cudaGetSymbolAddress((void**)&xl,  g_xl);
    cudaGetSymbolAddress((void**)&wqh, g_wqh);
    cudaGetSymbolAddress((void**)&wql, g_wql);
    cudaGetSymbolAddress((void**)&wph, g_wph);
    cudaGetSymbolAddress((void**)&wpl, g_wpl);
    cudaGetSymbolAddress((void**)&qh,  g_qh);
    cudaGetSymbolAddress((void**)&ql,  g_ql);
    cudaGetSymbolAddress((void**)&kh,  g_kh);
    cudaGetSymbolAddress((void**)&kl,  g_kl);
    cudaGetSymbolAddress((void**)&vh,  g_vh);
    cudaGetSymbolAddress((void**)&vl,  g_vl);
    cudaGetSymbolAddress((void**)&oh,  g_oh);
    cudaGetSymbolAddress((void**)&ol,  g_ol);

    cudaFuncSetAttribute(sgemm_mma, cudaFuncAttributeMaxDynamicSharedMemorySize, GEMM_SMEM);
    cudaFuncSetAttribute(attn_mma,  cudaFuncAttributeMaxDynamicSharedMemorySize, ATT_SMEM);

    // 0) weight transpose+split, input split
    wsplit_t<<<dim3(C_/32, QKV_/32), 256>>>(w_qkv, wqh, wql, C_, QKV_);
    wsplit_t<<<dim3(C_/32, C_/32),   256>>>(w_proj, wph, wpl, C_, C_);
    asplit<<<(M_*C_/4)/256, 256>>>((const float4*)x, xh, xl);

    // 1) QKV projection
    sgemm_mma<<<dim3(QKV_/128, M_/128), 256, GEMM_SMEM>>>(
        xh, xl, wqh, wql, qkv, M_, QKV_, C_, nullptr);

    // 2) LN + RoPE -> bf16 hi/lo [B,H,N,D]
    ln_rope_kernel<<<M_, 384>>>(qkv, cosr, sinr, q_ln_w, q_ln_b, k_ln_w, k_ln_b,
                                pP, pL, qh, ql, kh, kl, vh, vl);

    // 3) attention -> bf16 hi/lo [B,N,C]
    attn_mma<<<dim3(N_/128, H_, B_), 256, ATT_SMEM>>>(qh, ql, kh, kl, vh, vl, oh, ol);

    // 4) output projection + bias
    sgemm_mma<<<dim3(C_/128, M_/128), 256, GEMM_SMEM>>>(
        oh, ol, wph, wpl, out, M_, C_, C_, b_proj);
}

// round 5
// speedup vs baseline: 3.8220x; 1.3319x over previous
#include <cuda_runtime.h>
#include <cuda_fp16.h>
#include <cstdint>

// Problem constants (fixed by setup_inputs)
#define B_   16
#define N_   1024
#define C_   768
#define H_   12
#define D_   64
#define M_   (B_*N_)     // 16384
#define QKV_ (3*C_)      // 2304

// ---------------- scratch (device globals: allocation-free) ----------------
__device__ __align__(16) float g_qkv[M_ * QKV_];
__device__ __align__(16) __half g_xh[M_*C_],  g_xl[M_*C_];
__device__ __align__(16) __half g_wqh[QKV_*C_];        // [N,K] rounded
__device__ __align__(16) __half g_wph[C_*C_];          // [N,K] rounded
__device__ __align__(16) __half g_qh[B_*H_*N_*D_], g_ql[B_*H_*N_*D_];
__device__ __align__(16) __half g_kh[B_*H_*N_*D_];
__device__ __align__(16) __half g_vh[B_*H_*N_*D_];
__device__ __align__(16) __half g_oh[M_*C_], g_ol[M_*C_];

// ================= low-level helpers =================
__device__ __forceinline__ uint32_t smem_u32(const void* p) {
    uint32_t a;
    asm("{ .reg .u64 t; cvta.to.shared.u64 t, %1; cvt.u32.u64 %0, t; }"
        : "=r"(a) : "l"(p));
    return a;
}
__device__ __forceinline__ uint32_t sw128(uint32_t off) {
    return off ^ ((off >> 3) & 0x70);
}
__device__ __forceinline__ uint32_t sw64(uint32_t off) {
    return off ^ ((off >> 3) & 0x30);
}
#define CP_A16(s, g) \
    asm volatile("cp.async.cg.shared.global [%0], [%1], 16;" :: "r"(s), "l"(g) : "memory")
#define CP_COMMIT() asm volatile("cp.async.commit_group;" ::: "memory")
#define CP_WAIT2()  asm volatile("cp.async.wait_group 2;" ::: "memory")
#define CP_WAIT1()  asm volatile("cp.async.wait_group 1;" ::: "memory")
#define CP_WAIT0()  asm volatile("cp.async.wait_group 0;" ::: "memory")

#define LDSM4(r, addr) \
    asm volatile("ldmatrix.sync.aligned.m8n8.x4.shared.b16 {%0,%1,%2,%3}, [%4];" \
        : "=r"((r)[0]), "=r"((r)[1]), "=r"((r)[2]), "=r"((r)[3]) : "r"(addr))
#define LDSM4T(r, addr) \
    asm volatile("ldmatrix.sync.aligned.m8n8.x4.trans.shared.b16 {%0,%1,%2,%3}, [%4];" \
        : "=r"((r)[0]), "=r"((r)[1]), "=r"((r)[2]), "=r"((r)[3]) : "r"(addr))

__device__ __forceinline__ void mma16816(float* c, const uint32_t* a,
                                         uint32_t b0, uint32_t b1) {
    asm volatile(
        "mma.sync.aligned.m16n8k16.row.col.f32.f16.f16.f32 "
        "{%0,%1,%2,%3}, {%4,%5,%6,%7}, {%8,%9}, {%0,%1,%2,%3};"
        : "+f"(c[0]), "+f"(c[1]), "+f"(c[2]), "+f"(c[3])
        : "r"(a[0]), "r"(a[1]), "r"(a[2]), "r"(a[3]), "r"(b0), "r"(b1));
}
// pack two floats -> f16x2 (first arg in low half)
__device__ __forceinline__ uint32_t packhf(float a, float b) {
    __half2 h = __floats2half2_rn(a, b);
    return *reinterpret_cast<uint32_t*>(&h);
}
__device__ __forceinline__ float hflo(uint32_t p) {
    __half2 h = *reinterpret_cast<__half2*>(&p);
    return __low2float(h);
}
__device__ __forceinline__ float hfhi(uint32_t p) {
    __half2 h = *reinterpret_cast<__half2*>(&p);
    return __high2float(h);
}

// fast exp2 (FMA pipe only), valid x <= ~0
__device__ __forceinline__ float fexp2(float x) {
    x = fmaxf(x, -120.0f);
    float z  = x + 12582912.0f;
    float zi = z - 12582912.0f;
    float f  = x - zi;
    int   e  = __float_as_int(z);
    float p = 1.3333558e-3f;
    p = fmaf(p, f, 9.6181291e-3f);
    p = fmaf(p, f, 5.5504109e-2f);
    p = fmaf(p, f, 2.4022651e-1f);
    p = fmaf(p, f, 6.9314718e-1f);
    p = fmaf(p, f, 1.0f);
    float s = __int_as_float((e << 23) + 0x3f800000);
    return p * s;
}

// ================= split / transpose prep kernels =================
// fp32 -> fp16 hi + fp16 residual
__global__ __launch_bounds__(256)
void asplit(const float4* __restrict__ in, __half* __restrict__ h,
            __half* __restrict__ l)
{
    const uint32_t i = blockIdx.x * 256 + threadIdx.x;
    float4 v = in[i];
    __half h0 = __float2half_rn(v.x), h1 = __float2half_rn(v.y);
    __half h2 = __float2half_rn(v.z), h3 = __float2half_rn(v.w);
    __half l0 = __float2half_rn(v.x - __half2float(h0));
    __half l1 = __float2half_rn(v.y - __half2float(h1));
    __half l2 = __float2half_rn(v.z - __half2float(h2));
    __half l3 = __float2half_rn(v.w - __half2float(h3));
    *(__half2*)(h + 4*(size_t)i)     = __half2(h0, h1);
    *(__half2*)(h + 4*(size_t)i + 2) = __half2(h2, h3);
    *(__half2*)(l + 4*(size_t)i)     = __half2(l0, l1);
    *(__half2*)(l + 4*(size_t)i + 2) = __half2(l2, l3);
}

// W[K,N] fp32 -> Wt[N,K] fp16 (transpose + round, single term)
__global__ __launch_bounds__(256)
void wround_t(const float* __restrict__ W, __half* __restrict__ Th, int K, int N)
{
    __shared__ float t[32][33];
    const int kk = blockIdx.x * 32, nn = blockIdx.y * 32;
    const int tx = threadIdx.x & 31, ty = threadIdx.x >> 5;
    #pragma unroll
    for (int i = ty; i < 32; i += 8)
        t[i][tx] = W[(size_t)(kk + i) * N + nn + tx];
    __syncthreads();
    #pragma unroll
    for (int i = ty; i < 32; i += 8)
        Th[(size_t)(nn + i) * K + kk + tx] = __float2half_rn(t[tx][i]);
}

// ================= HMMA fp16x2 GEMM =================
// C[M,N] = (Ah+Al)[M,K] * Bh[N,K]^T (+bias), fp32 out.
// 128x128 tiles, KC=32, 3-stage cp.async (24KB/stage), 2 CTAs/SM.
#define GTILE 8192                  // 128 rows x 64 bytes
#define GSTAGE (3*GTILE)            // Ah,Al,Bh = 24 KB
#define GEMM_SMEM (3*GSTAGE)        // 73728

__global__ __launch_bounds__(256, 2)
void sgemm_mma(const __half* __restrict__ Ah, const __half* __restrict__ Al,
               const __half* __restrict__ Bh,
               float* __restrict__ Cm, int Mdim, int Ndim, int Kdim,
               const float* __restrict__ bias)
{
    extern __shared__ char smem[];
    const uint32_t sb = smem_u32(smem);
    const int tid = threadIdx.x;
    const int wid = tid >> 5, lane = tid & 31;
    const int m0 = blockIdx.y * 128, n0 = blockIdx.x * 128;
    const int wm = (wid & 3) * 32, wn = (wid >> 2) * 64;
    const int nchunks = Kdim / 32;

    const __half* tp[3] = {Ah, Al, Bh};

    float acc[2][8][4];
    #pragma unroll
    for (int i = 0; i < 2; i++)
        #pragma unroll
        for (int j = 0; j < 8; j++)
            #pragma unroll
            for (int q = 0; q < 4; q++) acc[i][j][q] = 0.f;

    // -------- async stage loader: 24 KB per chunk (1536 x 16B) --------
    auto issue = [&](int c) {
        const uint32_t stg = sb + (uint32_t)(c % 3) * GSTAGE;
        const int k0 = c * 32;
        #pragma unroll
        for (int t = 0; t < 6; t++) {
            int e = tid + t * 256;
            int tile = e >> 9;
            int i = e & 511;
            int row = i >> 2, u = i & 3;
            int grow = (tile < 2 ? m0 : n0) + row;
            const __half* src = tp[tile] + (size_t)grow * Kdim + k0 + u * 8;
            uint32_t dst = stg + tile * GTILE + sw64((uint32_t)(row * 64 + u * 16));
            unsigned long long ga = (unsigned long long)__cvta_generic_to_global(src);
            CP_A16(dst, ga);
        }
    };

    issue(0); CP_COMMIT();
    issue(1); CP_COMMIT();
    issue(2); CP_COMMIT();

    for (int c = 0; c < nchunks; c++) {
        if (c + 3 <= nchunks)      { CP_WAIT2(); }
        else if (c + 2 == nchunks) { CP_WAIT1(); }
        else                       { CP_WAIT0(); }
        __syncthreads();

        const uint32_t stg = sb + (uint32_t)(c % 3) * GSTAGE;
        const uint32_t sAh = stg, sAl = stg + GTILE, sBh = stg + 2*GTILE;

        #pragma unroll
        for (int ks = 0; ks < 2; ks++) {
            uint32_t ah[2][4], al[2][4];
            #pragma unroll
            for (int mt = 0; mt < 2; mt++) {
                uint32_t off = sw64((uint32_t)((wm + mt*16 + (lane & 15)) * 64
                                               + ks*32 + (lane & 16)));
                LDSM4(ah[mt], sAh + off);
                LDSM4(al[mt], sAl + off);
            }
            uint32_t bh[4][4];
            #pragma unroll
            for (int p = 0; p < 4; p++) {
                uint32_t off = sw64((uint32_t)((wn + p*16 + (lane & 7) + ((lane & 16) >> 1)) * 64
                                               + ks*32 + ((lane & 8) << 1)));
                LDSM4(bh[p], sBh + off);
            }
            #pragma unroll
            for (int mt = 0; mt < 2; mt++)
                #pragma unroll
                for (int p = 0; p < 4; p++)
                    #pragma unroll
                    for (int h2 = 0; h2 < 2; h2++) {
                        int nt = 2*p + h2;
                        mma16816(acc[mt][nt], ah[mt], bh[p][2*h2], bh[p][2*h2+1]);
                        mma16816(acc[mt][nt], al[mt], bh[p][2*h2], bh[p][2*h2+1]);
                    }
        }
        __syncthreads();
        if (c + 3 < nchunks) { issue(c + 3); CP_COMMIT(); }
    }

    // -------- epilogue --------
    #pragma unroll
    for (int mt = 0; mt < 2; mt++)
        #pragma unroll
        for (int nt = 0; nt < 8; nt++) {
            int row = m0 + wm + mt*16 + (lane >> 2);
            int col = n0 + wn + nt*8 + 2*(lane & 3);
            float b0 = 0.f, b1 = 0.f;
            if (bias) { b0 = bias[col]; b1 = bias[col + 1]; }
            float2 v0 = make_float2(acc[mt][nt][0] + b0, acc[mt][nt][1] + b1);
            float2 v1 = make_float2(acc[mt][nt][2] + b0, acc[mt][nt][3] + b1);
            *(float2*)(Cm + (size_t)row * Ndim + col)       = v0;
            *(float2*)(Cm + (size_t)(row + 8) * Ndim + col) = v1;
        }
}

// ================= per-head LayerNorm + RoPE -> fp16 =================
// Q split hi/lo (pre-scaled by scale*log2e); K,V rounded single.
__global__ __launch_bounds__(384)
void ln_rope_kernel(const float* __restrict__ qkv,
                    const float* __restrict__ cosr, const float* __restrict__ sinr,
                    const float* __restrict__ qw, const float* __restrict__ qb,
                    const float* __restrict__ kw, const float* __restrict__ kb,
                    const int* __restrict__ pP, const int* __restrict__ pL,
                    __half* __restrict__ Qh, __half* __restrict__ Ql,
                    __half* __restrict__ Kh, __half* __restrict__ Vh)
{
    const int blk  = blockIdx.x;
    const int b    = blk >> 10;
    const int n    = blk & (N_-1);
    const int h    = threadIdx.x >> 5;
    const int lane = threadIdx.x & 31;
    const int P = __ldg(pP), L = __ldg(pL);
    const bool rope = (n >= P) && (n < N_ - L);
    float rc = 1.f, rs = 0.f;
    if (rope) {
        int pos = n - P;
        rc = cosr[pos*32 + lane];
        rs = sinr[pos*32 + lane];
    }
    const float* row = qkv + (size_t)blk * QKV_;
    const size_t obase = (((size_t)(b*H_ + h))*N_ + n) * D_ + 2*lane;

    // Q
    {
        float2 v = *(const float2*)(row + h*D_ + 2*lane);
        float sum = v.x + v.y;
        #pragma unroll
        for (int o = 16; o; o >>= 1) sum += __shfl_xor_sync(~0u, sum, o);
        float mu = sum * (1.0f/64.0f);
        float dx = v.x - mu, dy = v.y - mu;
        float vv = dx*dx + dy*dy;
        #pragma unroll
        for (int o = 16; o; o >>= 1) vv += __shfl_xor_sync(~0u, vv, o);
        float inv = rsqrtf(vv*(1.0f/64.0f) + 1e-5f);
        float2 w2 = *(const float2*)(qw + 2*lane);
        float2 b2 = *(const float2*)(qb + 2*lane);
        float ox = fmaf(dx*inv, w2.x, b2.x);
        float oy = fmaf(dy*inv, w2.y, b2.y);
        if (rope) { float tx = ox*rc - oy*rs, ty = ox*rs + oy*rc; ox = tx; oy = ty; }
        const float QSC = 0.18033688011112042f; // (1/8)*log2(e)
        ox *= QSC; oy *= QSC;
        __half hx = __float2half_rn(ox), hy = __float2half_rn(oy);
        __half lx = __float2half_rn(ox - __half2float(hx));
        __half ly = __float2half_rn(oy - __half2float(hy));
        *(__half2*)(Qh + obase) = __half2(hx, hy);
        *(__half2*)(Ql + obase) = __half2(lx, ly);
    }
    // K (rounded)
    {
        float2 v = *(const float2*)(row + C_ + h*D_ + 2*lane);
        float sum = v.x + v.y;
        #pragma unroll
        for (int o = 16; o; o >>= 1) sum += __shfl_xor_sync(~0u, sum, o);
        float mu = sum * (1.0f/64.0f);
        float dx = v.x - mu, dy = v.y - mu;
        float vv = dx*dx + dy*dy;
        #pragma unroll
        for (int o = 16; o; o >>= 1) vv += __shfl_xor_sync(~0u, vv, o);
        float inv = rsqrtf(vv*(1.0f/64.0f) + 1e-5f);
        float2 w2 = *(const float2*)(kw + 2*lane);
        float2 b2 = *(const float2*)(kb + 2*lane);
        float ox = fmaf(dx*inv, w2.x, b2.x);
        float oy = fmaf(dy*inv, w2.y, b2.y);
        if (rope) { float tx = ox*rc - oy*rs, ty = ox*rs + oy*rc; ox = tx; oy = ty; }
        *(__half2*)(Kh + obase) = __floats2half2_rn(ox, oy);
    }
    // V (rounded)
    {
        float2 v = *(const float2*)(row + 2*C_ + h*D_ + 2*lane);
        *(__half2*)(Vh + obase) = __floats2half2_rn(v.x, v.y);
    }
}

// ================= HMMA flash attention (fp16x2) =================
// 128 q-rows per CTA, 8 warps. Q split (regs), K/V rounded, P split (regs).
#define KTILE 8192                    // 64 rows x 128 bytes
#define ASTAGE (2*KTILE)              // Kh,Vh = 16 KB
#define ATT_SMEM (3*ASTAGE)           // 49152 (Q staging uses first 32KB)

__global__ __launch_bounds__(256, 2)
void attn_mma(const __half* __restrict__ Qh, const __half* __restrict__ Ql,
              const __half* __restrict__ Kh, const __half* __restrict__ Vh,
              __half* __restrict__ Oh, __half* __restrict__ Ol)
{
    extern __shared__ char smem[];
    const uint32_t sb = smem_u32(smem);
    const int tid = threadIdx.x;
    const int wid = tid >> 5, lane = tid & 31;
    const int b = blockIdx.z, h = blockIdx.y;
    const int q0 = blockIdx.x * 128;
    const size_t base = ((size_t)(b*H_ + h)) * N_;

    // ---- stage Q tile (hi at sb, lo at sb+16KB) ----
    {
        const __half* srcs[2] = {Qh, Ql};
        #pragma unroll
        for (int t = 0; t < 8; t++) {
            int e = tid + t * 256;
            int tile = e >> 10;
            int i = e & 1023;
            int row = i >> 3, u = i & 7;
            const __half* src = srcs[tile] + (base + q0 + row) * D_ + u * 8;
            uint4 v = *(const uint4*)src;
            *(uint4*)(smem + tile*16384 + sw128((uint32_t)(row*128 + u*16))) = v;
        }
    }
    __syncthreads();

    // Q fragments, register-resident
    uint32_t qh[4][4], ql[4][4];
    #pragma unroll
    for (int ks = 0; ks < 4; ks++) {
        uint32_t off = sw128((uint32_t)((wid*16 + (lane & 15)) * 128 + ks*32 + (lane & 16)));
        LDSM4(qh[ks], sb + off);
        LDSM4(ql[ks], sb + 16384 + off);
    }
    __syncthreads();   // Q reads done; smem reusable for KV stages

    const __half* tp[2] = {Kh, Vh};
    auto issue = [&](int kt) {
        const uint32_t stg = sb + (uint32_t)(kt % 3) * ASTAGE;
        #pragma unroll
        for (int t = 0; t < 4; t++) {
            int e = tid + t * 256;
            int tile = e >> 9;
            int i = e & 511;
            int row = i >> 3, u = i & 7;
            const __half* src = tp[tile] + (base + kt*64 + row) * D_ + u * 8;
            uint32_t dst = stg + tile * KTILE + sw128((uint32_t)(row*128 + u*16));
            unsigned long long ga = (unsigned long long)__cvta_generic_to_global(src);
            CP_A16(dst, ga);
        }
    };

    float o[8][4];
    #pragma unroll
    for (int j = 0; j < 8; j++)
        #pragma unroll
        for (int q = 0; q < 4; q++) o[j][q] = 0.f;
    float mi[2] = {-3.0e38f, -3.0e38f};
    float li[2] = {0.f, 0.f};

    issue(0); CP_COMMIT();
    issue(1); CP_COMMIT();
    issue(2); CP_COMMIT();

    for (int kt = 0; kt < 16; kt++) {
        if (kt + 3 <= 16)      { CP_WAIT2(); }
        else if (kt + 2 == 16) { CP_WAIT1(); }
        else                   { CP_WAIT0(); }
        __syncthreads();
        const uint32_t stg = sb + (uint32_t)(kt % 3) * ASTAGE;
        const uint32_t sKh = stg, sVh = stg + KTILE;

        // ---- S = Q K^T (fp16x2) ----
        float s[8][4];
        #pragma unroll
        for (int j = 0; j < 8; j++)
            #pragma unroll
            for (int q = 0; q < 4; q++) s[j][q] = 0.f;

        #pragma unroll
        for (int ks = 0; ks < 4; ks++) {
            uint32_t kh[4][4];
            #pragma unroll
            for (int p = 0; p < 4; p++) {
                uint32_t off = sw128((uint32_t)((p*16 + (lane & 7) + ((lane & 16) >> 1)) * 128
                                                + ks*32 + ((lane & 8) << 1)));
                LDSM4(kh[p], sKh + off);
            }
            #pragma unroll
            for (int p = 0; p < 4; p++)
                #pragma unroll
                for (int h2 = 0; h2 < 2; h2++) {
                    int nt = 2*p + h2;
                    mma16816(s[nt], qh[ks], kh[p][2*h2], kh[p][2*h2+1]);
                    mma16816(s[nt], ql[ks], kh[p][2*h2], kh[p][2*h2+1]);
                }
        }

        // ---- online softmax (exp2 domain); rows r1=lane/4, r2=r1+8 ----
        #pragma unroll
        for (int r = 0; r < 2; r++) {
            int i0 = 2*r;
            float mx = -3.0e38f;
            #pragma unroll
            for (int nt = 0; nt < 8; nt++)
                mx = fmaxf(mx, fmaxf(s[nt][i0], s[nt][i0+1]));
            mx = fmaxf(mx, __shfl_xor_sync(~0u, mx, 1));
            mx = fmaxf(mx, __shfl_xor_sync(~0u, mx, 2));
            float mnew = fmaxf(mi[r], mx);
            float corr = fexp2(mi[r] - mnew);
            mi[r] = mnew;
            float rsum = 0.f;
            #pragma unroll
            for (int nt = 0; nt < 8; nt++) {
                s[nt][i0]   = fexp2(s[nt][i0]   - mnew);
                s[nt][i0+1] = fexp2(s[nt][i0+1] - mnew);
                rsum += s[nt][i0] + s[nt][i0+1];
            }
            rsum += __shfl_xor_sync(~0u, rsum, 1);
            rsum += __shfl_xor_sync(~0u, rsum, 2);
            li[r] = li[r]*corr + rsum;
            #pragma unroll
            for (int dt = 0; dt < 8; dt++) {
                o[dt][i0]   *= corr;
                o[dt][i0+1] *= corr;
            }
        }

        // ---- O += P V (fp16x2), P frags built in registers ----
        #pragma unroll
        for (int ds = 0; ds < 4; ds++) {
            uint32_t ph[4], pl[4];
            #pragma unroll
            for (int half = 0; half < 2; half++) {
                int nt = 2*ds + half;
                uint32_t p0 = packhf(s[nt][0], s[nt][1]);
                uint32_t p1 = packhf(s[nt][2], s[nt][3]);
                ph[2*half]   = p0;
                ph[2*half+1] = p1;
                float r00 = s[nt][0] - hflo(p0), r01 = s[nt][1] - hfhi(p0);
                float r10 = s[nt][2] - hflo(p1), r11 = s[nt][3] - hfhi(p1);
                pl[2*half]   = packhf(r00, r01);
                pl[2*half+1] = packhf(r10, r11);
            }
            uint32_t vh[4][4];
            #pragma unroll
            for (int dj = 0; dj < 4; dj++) {
                uint32_t off = sw128((uint32_t)((ds*16 + (lane & 15)) * 128
                                                + dj*32 + (lane & 16)));
                LDSM4T(vh[dj], sVh + off);
            }
            #pragma unroll
            for (int dj = 0; dj < 4; dj++)
                #pragma unroll
                for (int h2 = 0; h2 < 2; h2++) {
                    int dt = 2*dj + h2;
                    mma16816(o[dt], ph, vh[dj][2*h2], vh[dj][2*h2+1]);
                    mma16816(o[dt], pl, vh[dj][2*h2], vh[dj][2*h2+1]);
                }
        }

        __syncthreads();
        if (kt + 3 < 16) { issue(kt + 3); CP_COMMIT(); }
    }

    // ---- epilogue: normalize, split hi/lo, store [B,N,C] ----
    const float inv1 = 1.0f / li[0];
    const float inv2 = 1.0f / li[1];
    const int row1 = q0 + wid*16 + (lane >> 2);
    #pragma unroll
    for (int dt = 0; dt < 8; dt++) {
        int col = h*D_ + dt*8 + 2*(lane & 3);
        float a0 = o[dt][0]*inv1, a1 = o[dt][1]*inv1;
        float b0 = o[dt][2]*inv2, b1 = o[dt][3]*inv2;
        uint32_t h0 = packhf(a0, a1);
        uint32_t l0 = packhf(a0 - hflo(h0), a1 - hfhi(h0));
        uint32_t h1 = packhf(b0, b1);
        uint32_t l1 = packhf(b0 - hflo(h1), b1 - hfhi(h1));
        size_t i1 = (size_t)(b*N_ + row1) * C_ + col;
        size_t i2 = (size_t)(b*N_ + row1 + 8) * C_ + col;
        *(uint32_t*)(Oh + i1) = h0;
        *(uint32_t*)(Ol + i1) = l0;
        *(uint32_t*)(Oh + i2) = h1;
        *(uint32_t*)(Ol + i2) = l1;
    }
}

// ================= launch =================
extern "C" void kernel_launch(void* const* d_in, const int* in_sizes, int n_in,
                              void* d_out, int out_size)
{
    const float* x      = (const float*)d_in[0];
    const float* cosr   = (const float*)d_in[1];
    const float* sinr   = (const float*)d_in[2];
    const float* w_qkv  = (const float*)d_in[3];
    const float* q_ln_w = (const float*)d_in[4];
    const float* q_ln_b = (const float*)d_in[5];
    const float* k_ln_w = (const float*)d_in[6];
    const float* k_ln_b = (const float*)d_in[7];
    const float* w_proj = (const float*)d_in[8];
    const float* b_proj = (const float*)d_in[9];
    const int*   pP     = (const int*)d_in[10];
    const int*   pL     = (const int*)d_in[11];
    float* out = (float*)d_out;

    float* qkv;
    __half *xh, *xl, *wqh, *wph, *qh, *ql, *kh, *vh, *oh, *ol;
    cudaGetSymbolAddress((void**)&qkv, g_qkv);
    cudaGetSymbolAddress((void**)&xh,  g_xh);
    cudaGetSymbolAddress((void**)&xl,  g_xl);
    cudaGetSymbolAddress((void**)&wqh, g_wqh);
    cudaGetSymbolAddress((void**)&wph, g_wph);
    cudaGetSymbolAddress((void**)&qh,  g_qh);
    cudaGetSymbolAddress((void**)&ql,  g_ql);
    cudaGetSymbolAddress((void**)&kh,  g_kh);
    cudaGetSymbolAddress((void**)&vh,  g_vh);
    cudaGetSymbolAddress((void**)&oh,  g_oh);
    cudaGetSymbolAddress((void**)&ol,  g_ol);

    cudaFuncSetAttribute(sgemm_mma, cudaFuncAttributeMaxDynamicSharedMemorySize, GEMM_SMEM);
    cudaFuncSetAttribute(attn_mma,  cudaFuncAttributeMaxDynamicSharedMemorySize, ATT_SMEM);

    // 0) weight transpose+round, input split
    wround_t<<<dim3(C_/32, QKV_/32), 256>>>(w_qkv, wqh, C_, QKV_);
    wround_t<<<dim3(C_/32, C_/32),   256>>>(w_proj, wph, C_, C_);
    asplit<<<(M_*C_/4)/256, 256>>>((const float4*)x, xh, xl);

    // 1) QKV projection
    sgemm_mma<<<dim3(QKV_/128, M_/128), 256, GEMM_SMEM>>>(
        xh, xl, wqh, qkv, M_, QKV_, C_, nullptr);

    // 2) LN + RoPE -> fp16 [B,H,N,D]
    ln_rope_kernel<<<M_, 384>>>(qkv, cosr, sinr, q_ln_w, q_ln_b, k_ln_w, k_ln_b,
                                pP, pL, qh, ql, kh, vh);

    // 3) attention -> fp16 hi/lo [B,N,C]
    attn_mma<<<dim3(N_/128, H_, B_), 256, ATT_SMEM>>>(qh, ql, kh, vh, oh, ol);

    // 4) output projection + bias
    sgemm_mma<<<dim3(C_/128, M_/128), 256, GEMM_SMEM>>>(
        oh, ol, wph, out, M_, C_, C_, b_proj);
}

// round 6
// speedup vs baseline: 4.0393x; 1.0569x over previous
#include <cuda_runtime.h>
#include <cuda_fp16.h>
#include <cstdint>

// Problem constants (fixed by setup_inputs)
#define B_   16
#define N_   1024
#define C_   768
#define H_   12
#define D_   64
#define M_   (B_*N_)     // 16384
#define QKV_ (3*C_)      // 2304

// ---------------- scratch (device globals: allocation-free) ----------------
__device__ __align__(16) __half g_xh[M_*C_],  g_xl[M_*C_];
__device__ __align__(16) __half g_wqh[QKV_*C_];        // [N,K] rounded
__device__ __align__(16) __half g_wph[C_*C_];          // [N,K] rounded
__device__ __align__(16) __half g_qh[B_*H_*N_*D_], g_ql[B_*H_*N_*D_];
__device__ __align__(16) __half g_kh[B_*H_*N_*D_];
__device__ __align__(16) __half g_vh[B_*H_*N_*D_];
__device__ __align__(16) __half g_oh[M_*C_], g_ol[M_*C_];

// ================= low-level helpers =================
__device__ __forceinline__ uint32_t smem_u32(const void* p) {
    uint32_t a;
    asm("{ .reg .u64 t; cvta.to.shared.u64 t, %1; cvt.u32.u64 %0, t; }"
        : "=r"(a) : "l"(p));
    return a;
}
__device__ __forceinline__ uint32_t sw128(uint32_t off) {
    return off ^ ((off >> 3) & 0x70);
}
__device__ __forceinline__ uint32_t sw64(uint32_t off) {
    return off ^ ((off >> 3) & 0x30);
}
#define CP_A16(s, g) \
    asm volatile("cp.async.cg.shared.global [%0], [%1], 16;" :: "r"(s), "l"(g) : "memory")
#define CP_COMMIT() asm volatile("cp.async.commit_group;" ::: "memory")
#define CP_WAIT1()  asm volatile("cp.async.wait_group 1;" ::: "memory")
#define CP_WAIT0()  asm volatile("cp.async.wait_group 0;" ::: "memory")

#define LDSM4(r, addr) \
    asm volatile("ldmatrix.sync.aligned.m8n8.x4.shared.b16 {%0,%1,%2,%3}, [%4];" \
        : "=r"((r)[0]), "=r"((r)[1]), "=r"((r)[2]), "=r"((r)[3]) : "r"(addr))
#define LDSM4T(r, addr) \
    asm volatile("ldmatrix.sync.aligned.m8n8.x4.trans.shared.b16 {%0,%1,%2,%3}, [%4];" \
        : "=r"((r)[0]), "=r"((r)[1]), "=r"((r)[2]), "=r"((r)[3]) : "r"(addr))

__device__ __forceinline__ void mma16816(float* c, const uint32_t* a,
                                         uint32_t b0, uint32_t b1) {
    asm volatile(
        "mma.sync.aligned.m16n8k16.row.col.f32.f16.f16.f32 "
        "{%0,%1,%2,%3}, {%4,%5,%6,%7}, {%8,%9}, {%0,%1,%2,%3};"
        : "+f"(c[0]), "+f"(c[1]), "+f"(c[2]), "+f"(c[3])
        : "r"(a[0]), "r"(a[1]), "r"(a[2]), "r"(a[3]), "r"(b0), "r"(b1));
}
__device__ __forceinline__ uint32_t packhf(float a, float b) {
    __half2 h = __floats2half2_rn(a, b);
    return *reinterpret_cast<uint32_t*>(&h);
}
__device__ __forceinline__ float hflo(uint32_t p) {
    __half2 h = *reinterpret_cast<__half2*>(&p);
    return __low2float(h);
}
__device__ __forceinline__ float hfhi(uint32_t p) {
    __half2 h = *reinterpret_cast<__half2*>(&p);
    return __high2float(h);
}

// fast exp2 (FMA pipe only), valid x <= ~0
__device__ __forceinline__ float fexp2(float x) {
    x = fmaxf(x, -120.0f);
    float z  = x + 12582912.0f;
    float zi = z - 12582912.0f;
    float f  = x - zi;
    int   e  = __float_as_int(z);
    float p = 1.3333558e-3f;
    p = fmaf(p, f, 9.6181291e-3f);
    p = fmaf(p, f, 5.5504109e-2f);
    p = fmaf(p, f, 2.4022651e-1f);
    p = fmaf(p, f, 6.9314718e-1f);
    p = fmaf(p, f, 1.0f);
    float s = __int_as_float((e << 23) + 0x3f800000);
    return p * s;
}

// ================= split / transpose prep kernels =================
__global__ __launch_bounds__(256)
void asplit(const float4* __restrict__ in, __half* __restrict__ h,
            __half* __restrict__ l)
{
    const uint32_t i = blockIdx.x * 256 + threadIdx.x;
    float4 v = in[i];
    __half h0 = __float2half_rn(v.x), h1 = __float2half_rn(v.y);
    __half h2 = __float2half_rn(v.z), h3 = __float2half_rn(v.w);
    __half l0 = __float2half_rn(v.x - __half2float(h0));
    __half l1 = __float2half_rn(v.y - __half2float(h1));
    __half l2 = __float2half_rn(v.z - __half2float(h2));
    __half l3 = __float2half_rn(v.w - __half2float(h3));
    *(__half2*)(h + 4*(size_t)i)     = __half2(h0, h1);
    *(__half2*)(h + 4*(size_t)i + 2) = __half2(h2, h3);
    *(__half2*)(l + 4*(size_t)i)     = __half2(l0, l1);
    *(__half2*)(l + 4*(size_t)i + 2) = __half2(l2, l3);
}

__global__ __launch_bounds__(256)
void wround_t(const float* __restrict__ W, __half* __restrict__ Th, int K, int N)
{
    __shared__ float t[32][33];
    const int kk = blockIdx.x * 32, nn = blockIdx.y * 32;
    const int tx = threadIdx.x & 31, ty = threadIdx.x >> 5;
    #pragma unroll
    for (int i = ty; i < 32; i += 8)
        t[i][tx] = W[(size_t)(kk + i) * N + nn + tx];
    __syncthreads();
    #pragma unroll
    for (int i = ty; i < 32; i += 8)
        Th[(size_t)(nn + i) * K + kk + tx] = __float2half_rn(t[tx][i]);
}

// ================= HMMA fp16x2 GEMM, optional fused LN/RoPE epilogue =======
// C = (Ah+Al)[M,K] * Bh[N,K]^T. 128x128 tiles, KC=32, 3-stage single-sync
// pipeline, 2 CTAs/SM.
// FUSED=0: fp32 out + bias.  FUSED=1: per-head LN + RoPE -> Qh/Ql/Kh/Vh fp16.
#define GTILE 8192                  // 128 rows x 64 bytes
#define GSTAGE (3*GTILE)            // Ah,Al,Bh = 24 KB
#define GEMM_SMEM (3*GSTAGE)        // 73728

template<bool FUSED>
__global__ __launch_bounds__(256, 2)
void gemm_mma(const __half* __restrict__ Ah, const __half* __restrict__ Al,
              const __half* __restrict__ Bh,
              float* __restrict__ Cm, int Mdim, int Ndim, int Kdim,
              const float* __restrict__ bias,
              const float* __restrict__ cosr, const float* __restrict__ sinr,
              const float* __restrict__ qw, const float* __restrict__ qb,
              const float* __restrict__ kw, const float* __restrict__ kb,
              const int* __restrict__ pP, const int* __restrict__ pL,
              __half* __restrict__ Qh, __half* __restrict__ Ql,
              __half* __restrict__ Kh, __half* __restrict__ Vh)
{
    extern __shared__ char smem[];
    const uint32_t sb = smem_u32(smem);
    const int tid = threadIdx.x;
    const int wid = tid >> 5, lane = tid & 31;
    const int m0 = blockIdx.y * 128, n0 = blockIdx.x * 128;
    const int wm = (wid & 3) * 32, wn = (wid >> 2) * 64;
    const int nchunks = Kdim / 32;

    const __half* tp[3] = {Ah, Al, Bh};

    float acc[2][8][4];
    #pragma unroll
    for (int i = 0; i < 2; i++)
        #pragma unroll
        for (int j = 0; j < 8; j++)
            #pragma unroll
            for (int q = 0; q < 4; q++) acc[i][j][q] = 0.f;

    auto issue = [&](int c) {
        const uint32_t stg = sb + (uint32_t)(c % 3) * GSTAGE;
        const int k0 = c * 32;
        #pragma unroll
        for (int t = 0; t < 6; t++) {
            int e = tid + t * 256;
            int tile = e >> 9;
            int i = e & 511;
            int row = i >> 2, u = i & 3;
            int grow = (tile < 2 ? m0 : n0) + row;
            const __half* src = tp[tile] + (size_t)grow * Kdim + k0 + u * 8;
            uint32_t dst = stg + tile * GTILE + sw64((uint32_t)(row * 64 + u * 16));
            unsigned long long ga = (unsigned long long)__cvta_generic_to_global(src);
            CP_A16(dst, ga);
        }
    };

    issue(0); CP_COMMIT();
    issue(1); CP_COMMIT();

    for (int c = 0; c < nchunks; c++) {
        if (c == nchunks - 1) { CP_WAIT0(); } else { CP_WAIT1(); }
        __syncthreads();
        // stage (c+2)%3 == (c-1)%3 was consumed at iter c-1; safe to refill now
        if (c + 2 < nchunks) { issue(c + 2); CP_COMMIT(); }

        const uint32_t stg = sb + (uint32_t)(c % 3) * GSTAGE;
        const uint32_t sAh = stg, sAl = stg + GTILE, sBh = stg + 2*GTILE;

        #pragma unroll
        for (int ks = 0; ks < 2; ks++) {
            uint32_t ah[2][4], al[2][4];
            #pragma unroll
            for (int mt = 0; mt < 2; mt++) {
                uint32_t off = sw64((uint32_t)((wm + mt*16 + (lane & 15)) * 64
                                               + ks*32 + (lane & 16)));
                LDSM4(ah[mt], sAh + off);
                LDSM4(al[mt], sAl + off);
            }
            uint32_t bh[4][4];
            #pragma unroll
            for (int p = 0; p < 4; p++) {
                uint32_t off = sw64((uint32_t)((wn + p*16 + (lane & 7) + ((lane & 16) >> 1)) * 64
                                               + ks*32 + ((lane & 8) << 1)));
                LDSM4(bh[p], sBh + off);
            }
            #pragma unroll
            for (int mt = 0; mt < 2; mt++)
                #pragma unroll
                for (int p = 0; p < 4; p++)
                    #pragma unroll
                    for (int h2 = 0; h2 < 2; h2++) {
                        int nt = 2*p + h2;
                        mma16816(acc[mt][nt], ah[mt], bh[p][2*h2], bh[p][2*h2+1]);
                        mma16816(acc[mt][nt], al[mt], bh[p][2*h2], bh[p][2*h2+1]);
                    }
        }
    }

    if (!FUSED) {
        // -------- plain epilogue: fp32 + bias --------
        #pragma unroll
        for (int mt = 0; mt < 2; mt++)
            #pragma unroll
            for (int nt = 0; nt < 8; nt++) {
                int row = m0 + wm + mt*16 + (lane >> 2);
                int col = n0 + wn + nt*8 + 2*(lane & 3);
                float b0 = 0.f, b1 = 0.f;
                if (bias) { b0 = bias[col]; b1 = bias[col + 1]; }
                float2 v0 = make_float2(acc[mt][nt][0] + b0, acc[mt][nt][1] + b1);
                float2 v1 = make_float2(acc[mt][nt][2] + b0, acc[mt][nt][3] + b1);
                *(float2*)(Cm + (size_t)row * Ndim + col)       = v0;
                *(float2*)(Cm + (size_t)(row + 8) * Ndim + col) = v1;
            }
    } else {
        // -------- fused epilogue: per-head LN + RoPE -> fp16 Q/K/V --------
        // warp's 64-col slice = one head of one of {Q,K,V}
        const int gcol = n0 + wn;
        const int kind = gcol / C_;             // 0=q, 1=k, 2=v
        const int head = (gcol % C_) / D_;
        const int Pp = __ldg(pP), Ll = __ldg(pL);
        const float* lw = (kind == 0) ? qw : kw;
        const float* lb = (kind == 0) ? qb : kb;
        const float QSC = 0.18033688011112042f; // (1/8)*log2(e)

        #pragma unroll
        for (int mt = 0; mt < 2; mt++) {
            const int m1 = m0 + wm + mt*16 + (lane >> 2);
            const int m2 = m1 + 8;
            const int b1i = m1 >> 10, n1 = m1 & (N_-1);
            const int b2i = m2 >> 10, n2 = m2 & (N_-1);
            const size_t o1 = (((size_t)(b1i*H_ + head))*N_ + n1) * D_;
            const size_t o2 = (((size_t)(b2i*H_ + head))*N_ + n2) * D_;

            if (kind == 2) {
                // V: plain fp16 round
                #pragma unroll
                for (int nt = 0; nt < 8; nt++) {
                    int col = nt*8 + 2*(lane & 3);
                    *(uint32_t*)(Vh + o1 + col) = packhf(acc[mt][nt][0], acc[mt][nt][1]);
                    *(uint32_t*)(Vh + o2 + col) = packhf(acc[mt][nt][2], acc[mt][nt][3]);
                }
            } else {
                // LN over the 64 head cols: in-thread over nt, then 4-lane group
                float s1 = 0.f, s2 = 0.f;
                #pragma unroll
                for (int nt = 0; nt < 8; nt++) {
                    s1 += acc[mt][nt][0] + acc[mt][nt][1];
                    s2 += acc[mt][nt][2] + acc[mt][nt][3];
                }
                s1 += __shfl_xor_sync(~0u, s1, 1); s1 += __shfl_xor_sync(~0u, s1, 2);
                s2 += __shfl_xor_sync(~0u, s2, 1); s2 += __shfl_xor_sync(~0u, s2, 2);
                const float mu1 = s1 * (1.0f/64.0f), mu2 = s2 * (1.0f/64.0f);
                float v1 = 0.f, v2 = 0.f;
                #pragma unroll
                for (int nt = 0; nt < 8; nt++) {
                    float d0 = acc[mt][nt][0] - mu1, d1 = acc[mt][nt][1] - mu1;
                    float d2 = acc[mt][nt][2] - mu2, d3 = acc[mt][nt][3] - mu2;
                    v1 += d0*d0 + d1*d1;
                    v2 += d2*d2 + d3*d3;
                }
                v1 += __shfl_xor_sync(~0u, v1, 1); v1 += __shfl_xor_sync(~0u, v1, 2);
                v2 += __shfl_xor_sync(~0u, v2, 1); v2 += __shfl_xor_sync(~0u, v2, 2);
                const float iv1 = rsqrtf(v1*(1.0f/64.0f) + 1e-5f);
                const float iv2 = rsqrtf(v2*(1.0f/64.0f) + 1e-5f);
                const bool r1 = (n1 >= Pp) && (n1 < N_ - Ll);
                const bool r2 = (n2 >= Pp) && (n2 < N_ - Ll);

                #pragma unroll
                for (int nt = 0; nt < 8; nt++) {
                    const int col  = nt*8 + 2*(lane & 3);
                    const int colp = nt*4 + (lane & 3);
                    float2 w2 = *(const float2*)(lw + col);
                    float2 bb = *(const float2*)(lb + col);
                    float y0 = fmaf((acc[mt][nt][0]-mu1)*iv1, w2.x, bb.x);
                    float y1 = fmaf((acc[mt][nt][1]-mu1)*iv1, w2.y, bb.y);
                    float y2 = fmaf((acc[mt][nt][2]-mu2)*iv2, w2.x, bb.x);
                    float y3 = fmaf((acc[mt][nt][3]-mu2)*iv2, w2.y, bb.y);
                    if (r1) {
                        float rc = cosr[(n1-Pp)*32 + colp], rs = sinr[(n1-Pp)*32 + colp];
                        float t0 = y0*rc - y1*rs, t1 = y0*rs + y1*rc;
                        y0 = t0; y1 = t1;
                    }
                    if (r2) {
                        float rc = cosr[(n2-Pp)*32 + colp], rs = sinr[(n2-Pp)*32 + colp];
                        float t2 = y2*rc - y3*rs, t3 = y2*rs + y3*rc;
                        y2 = t2; y3 = t3;
                    }
                    if (kind == 0) {
                        y0 *= QSC; y1 *= QSC; y2 *= QSC; y3 *= QSC;
                        uint32_t h0 = packhf(y0, y1);
                        uint32_t l0 = packhf(y0 - hflo(h0), y1 - hfhi(h0));
                        uint32_t h1 = packhf(y2, y3);
                        uint32_t l1 = packhf(y2 - hflo(h1), y3 - hfhi(h1));
                        *(uint32_t*)(Qh + o1 + col) = h0;
                        *(uint32_t*)(Ql + o1 + col) = l0;
                        *(uint32_t*)(Qh + o2 + col) = h1;
                        *(uint32_t*)(Ql + o2 + col) = l1;
                    } else {
                        *(uint32_t*)(Kh + o1 + col) = packhf(y0, y1);
                        *(uint32_t*)(Kh + o2 + col) = packhf(y2, y3);
                    }
                }
            }
        }
    }
}

// ================= HMMA flash attention (fp16x2) =================
// 128 q-rows per CTA, 8 warps. Q split (regs), K/V rounded, P split (regs).
// 3-stage single-sync pipeline.
#define KTILE 8192                    // 64 rows x 128 bytes
#define ASTAGE (2*KTILE)              // Kh,Vh = 16 KB
#define ATT_SMEM (3*ASTAGE)           // 49152

__global__ __launch_bounds__(256, 2)
void attn_mma(const __half* __restrict__ Qh, const __half* __restrict__ Ql,
              const __half* __restrict__ Kh, const __half* __restrict__ Vh,
              __half* __restrict__ Oh, __half* __restrict__ Ol)
{
    extern __shared__ char smem[];
    const uint32_t sb = smem_u32(smem);
    const int tid = threadIdx.x;
    const int wid = tid >> 5, lane = tid & 31;
    const int b = blockIdx.z, h = blockIdx.y;
    const int q0 = blockIdx.x * 128;
    const size_t base = ((size_t)(b*H_ + h)) * N_;

    // ---- stage Q tile (hi at sb, lo at sb+16KB) ----
    {
        const __half* srcs[2] = {Qh, Ql};
        #pragma unroll
        for (int t = 0; t < 8; t++) {
            int e = tid + t * 256;
            int tile = e >> 10;
            int i = e & 1023;
            int row = i >> 3, u = i & 7;
            const __half* src = srcs[tile] + (base + q0 + row) * D_ + u * 8;
            uint4 v = *(const uint4*)src;
            *(uint4*)(smem + tile*16384 + sw128((uint32_t)(row*128 + u*16))) = v;
        }
    }
    __syncthreads();

    uint32_t qh[4][4], ql[4][4];
    #pragma unroll
    for (int ks = 0; ks < 4; ks++) {
        uint32_t off = sw128((uint32_t)((wid*16 + (lane & 15)) * 128 + ks*32 + (lane & 16)));
        LDSM4(qh[ks], sb + off);
        LDSM4(ql[ks], sb + 16384 + off);
    }
    __syncthreads();   // Q reads done; smem reusable for KV stages

    const __half* tp[2] = {Kh, Vh};
    auto issue = [&](int kt) {
        const uint32_t stg = sb + (uint32_t)(kt % 3) * ASTAGE;
        #pragma unroll
        for (int t = 0; t < 4; t++) {
            int e = tid + t * 256;
            int tile = e >> 9;
            int i = e & 511;
            int row = i >> 3, u = i & 7;
            const __half* src = tp[tile] + (base + kt*64 + row) * D_ + u * 8;
            uint32_t dst = stg + tile * KTILE + sw128((uint32_t)(row*128 + u*16));
            unsigned long long ga = (unsigned long long)__cvta_generic_to_global(src);
            CP_A16(dst, ga);
        }
    };

    float o[8][4];
    #pragma unroll
    for (int j = 0; j < 8; j++)
        #pragma unroll
        for (int q = 0; q < 4; q++) o[j][q] = 0.f;
    float mi[2] = {-3.0e38f, -3.0e38f};
    float li[2] = {0.f, 0.f};

    issue(0); CP_COMMIT();
    issue(1); CP_COMMIT();

    for (int kt = 0; kt < 16; kt++) {
        if (kt == 15) { CP_WAIT0(); } else { CP_WAIT1(); }
        __syncthreads();
        if (kt + 2 < 16) { issue(kt + 2); CP_COMMIT(); }

        const uint32_t stg = sb + (uint32_t)(kt % 3) * ASTAGE;
        const uint32_t sKh = stg, sVh = stg + KTILE;

        // ---- S = Q K^T (fp16x2) ----
        float s[8][4];
        #pragma unroll
        for (int j = 0; j < 8; j++)
            #pragma unroll
            for (int q = 0; q < 4; q++) s[j][q] = 0.f;

        #pragma unroll
        for (int ks = 0; ks < 4; ks++) {
            uint32_t kh[4][4];
            #pragma unroll
            for (int p = 0; p < 4; p++) {
                uint32_t off = sw128((uint32_t)((p*16 + (lane & 7) + ((lane & 16) >> 1)) * 128
                                                + ks*32 + ((lane & 8) << 1)));
                LDSM4(kh[p], sKh + off);
            }
            #pragma unroll
            for (int p = 0; p < 4; p++)
                #pragma unroll
                for (int h2 = 0; h2 < 2; h2++) {
                    int nt = 2*p + h2;
                    mma16816(s[nt], qh[ks], kh[p][2*h2], kh[p][2*h2+1]);
                    mma16816(s[nt], ql[ks], kh[p][2*h2], kh[p][2*h2+1]);
                }
        }

        // ---- online softmax (exp2 domain) ----
        #pragma unroll
        for (int r = 0; r < 2; r++) {
            int i0 = 2*r;
            float mx = -3.0e38f;
            #pragma unroll
            for (int nt = 0; nt < 8; nt++)
                mx = fmaxf(mx, fmaxf(s[nt][i0], s[nt][i0+1]));
            mx = fmaxf(mx, __shfl_xor_sync(~0u, mx, 1));
            mx = fmaxf(mx, __shfl_xor_sync(~0u, mx, 2));
            float mnew = fmaxf(mi[r], mx);
            float corr = fexp2(mi[r] - mnew);
            mi[r] = mnew;
            float rsum = 0.f;
            #pragma unroll
            for (int nt = 0; nt < 8; nt++) {
                s[nt][i0]   = fexp2(s[nt][i0]   - mnew);
                s[nt][i0+1] = fexp2(s[nt][i0+1] - mnew);
                rsum += s[nt][i0] + s[nt][i0+1];
            }
            rsum += __shfl_xor_sync(~0u, rsum, 1);
            rsum += __shfl_xor_sync(~0u, rsum, 2);
            li[r] = li[r]*corr + rsum;
            #pragma unroll
            for (int dt = 0; dt < 8; dt++) {
                o[dt][i0]   *= corr;
                o[dt][i0+1] *= corr;
            }
        }

        // ---- O += P V (fp16x2), P frags built in registers ----
        #pragma unroll
        for (int ds = 0; ds < 4; ds++) {
            uint32_t ph[4], pl[4];
            #pragma unroll
            for (int half = 0; half < 2; half++) {
                int nt = 2*ds + half;
                uint32_t p0 = packhf(s[nt][0], s[nt][1]);
                uint32_t p1 = packhf(s[nt][2], s[nt][3]);
                ph[2*half]   = p0;
                ph[2*half+1] = p1;
                float r00 = s[nt][0] - hflo(p0), r01 = s[nt][1] - hfhi(p0);
                float r10 = s[nt][2] - hflo(p1), r11 = s[nt][3] - hfhi(p1);
                pl[2*half]   = packhf(r00, r01);
                pl[2*half+1] = packhf(r10, r11);
            }
            uint32_t vh[4][4];
            #pragma unroll
            for (int dj = 0; dj < 4; dj++) {
                uint32_t off = sw128((uint32_t)((ds*16 + (lane & 15)) * 128
                                                + dj*32 + (lane & 16)));
                LDSM4T(vh[dj], sVh + off);
            }
            #pragma unroll
            for (int dj = 0; dj < 4; dj++)
                #pragma unroll
                for (int h2 = 0; h2 < 2; h2++) {
                    int dt = 2*dj + h2;
                    mma16816(o[dt], ph, vh[dj][2*h2], vh[dj][2*h2+1]);
                    mma16816(o[dt], pl, vh[dj][2*h2], vh[dj][2*h2+1]);
                }
        }
    }

    // ---- epilogue: normalize, split hi/lo, store [B,N,C] ----
    const float inv1 = 1.0f / li[0];
    const float inv2 = 1.0f / li[1];
    const int row1 = q0 + wid*16 + (lane >> 2);
    #pragma unroll
    for (int dt = 0; dt < 8; dt++) {
        int col = h*D_ + dt*8 + 2*(lane & 3);
        float a0 = o[dt][0]*inv1, a1 = o[dt][1]*inv1;
        float b0 = o[dt][2]*inv2, b1 = o[dt][3]*inv2;
        uint32_t h0 = packhf(a0, a1);
        uint32_t l0 = packhf(a0 - hflo(h0), a1 - hfhi(h0));
        uint32_t h1 = packhf(b0, b1);
        uint32_t l1 = packhf(b0 - hflo(h1), b1 - hfhi(h1));
        size_t i1 = (size_t)(b*N_ + row1) * C_ + col;
        size_t i2 = (size_t)(b*N_ + row1 + 8) * C_ + col;
        *(uint32_t*)(Oh + i1) = h0;
        *(uint32_t*)(Ol + i1) = l0;
        *(uint32_t*)(Oh + i2) = h1;
        *(uint32_t*)(Ol + i2) = l1;
    }
}

// ================= launch =================
extern "C" void kernel_launch(void* const* d_in, const int* in_sizes, int n_in,
                              void* d_out, int out_size)
{
    const float* x      = (const float*)d_in[0];
    const float* cosr   = (const float*)d_in[1];
    const float* sinr   = (const float*)d_in[2];
    const float* w_qkv  = (const float*)d_in[3];
    const float* q_ln_w = (const float*)d_in[4];
    const float* q_ln_b = (const float*)d_in[5];
    const float* k_ln_w = (const float*)d_in[6];
    const float* k_ln_b = (const float*)d_in[7];
    const float* w_proj = (const float*)d_in[8];
    const float* b_proj = (const float*)d_in[9];
    const int*   pP     = (const int*)d_in[10];
    const int*   pL     = (const int*)d_in[11];
    float* out = (float*)d_out;

    __half *xh, *xl, *wqh, *wph, *qh, *ql, *kh, *vh, *oh, *ol;
    cudaGetSymbolAddress((void**)&xh,  g_xh);
    cudaGetSymbolAddress((void**)&xl,  g_xl);
    cudaGetSymbolAddress((void**)&wqh, g_wqh);
    cudaGetSymbolAddress((void**)&wph, g_wph);
    cudaGetSymbolAddress((void**)&qh,  g_qh);
    cudaGetSymbolAddress((void**)&ql,  g_ql);
    cudaGetSymbolAddress((void**)&kh,  g_kh);
    cudaGetSymbolAddress((void**)&vh,  g_vh);
    cudaGetSymbolAddress((void**)&oh,  g_oh);
    cudaGetSymbolAddress((void**)&ol,  g_ol);

    cudaFuncSetAttribute(gemm_mma<false>, cudaFuncAttributeMaxDynamicSharedMemorySize, GEMM_SMEM);
    cudaFuncSetAttribute(gemm_mma<true>,  cudaFuncAttributeMaxDynamicSharedMemorySize, GEMM_SMEM);
    cudaFuncSetAttribute(attn_mma, cudaFuncAttributeMaxDynamicSharedMemorySize, ATT_SMEM);

    // 0) weight transpose+round, input split
    wround_t<<<dim3(C_/32, QKV_/32), 256>>>(w_qkv, wqh, C_, QKV_);
    wround_t<<<dim3(C_/32, C_/32),   256>>>(w_proj, wph, C_, C_);
    asplit<<<(M_*C_/4)/256, 256>>>((const float4*)x, xh, xl);

    // 1) QKV projection with fused LN+RoPE epilogue -> fp16 Q(hi/lo)/K/V
    gemm_mma<true><<<dim3(QKV_/128, M_/128), 256, GEMM_SMEM>>>(
        xh, xl, wqh, nullptr, M_, QKV_, C_, nullptr,
        cosr, sinr, q_ln_w, q_ln_b, k_ln_w, k_ln_b, pP, pL,
        qh, ql, kh, vh);

    // 2) attention -> fp16 hi/lo [B,N,C]
    attn_mma<<<dim3(N_/128, H_, B_), 256, ATT_SMEM>>>(qh, ql, kh, vh, oh, ol);

    // 3) output projection + bias
    gemm_mma<false><<<dim3(C_/128, M_/128), 256, GEMM_SMEM>>>(
        oh, ol, wph, out, M_, C_, C_, b_proj,
        nullptr, nullptr, nullptr, nullptr, nullptr, nullptr, nullptr, nullptr,
        nullptr, nullptr, nullptr, nullptr);
}

// round 7
// speedup vs baseline: 4.1566x; 1.0290x over previous
#include <cuda_runtime.h>
#include <cuda_fp16.h>
#include <cstdint>

// Problem constants (fixed by setup_inputs)
#define B_   16
#define N_   1024
#define C_   768
#define H_   12
#define D_   64
#define M_   (B_*N_)     // 16384
#define QKV_ (3*C_)      // 2304

// ---------------- scratch (device globals: allocation-free) ----------------
__device__ __align__(16) __half g_xh[M_*C_],  g_xl[M_*C_];
__device__ __align__(16) __half g_wqh[QKV_*C_];        // [N,K] rounded
__device__ __align__(16) __half g_wph[C_*C_];          // [N,K] rounded
__device__ __align__(16) __half g_qh[B_*H_*N_*D_], g_ql[B_*H_*N_*D_];
__device__ __align__(16) __half g_kh[B_*H_*N_*D_];
__device__ __align__(16) __half g_vh[B_*H_*N_*D_];
__device__ __align__(16) __half g_oh[M_*C_], g_ol[M_*C_];

// ================= low-level helpers =================
__device__ __forceinline__ uint32_t smem_u32(const void* p) {
    uint32_t a;
    asm("{ .reg .u64 t; cvta.to.shared.u64 t, %1; cvt.u32.u64 %0, t; }"
        : "=r"(a) : "l"(p));
    return a;
}
__device__ __forceinline__ uint32_t sw128(uint32_t off) {
    return off ^ ((off >> 3) & 0x70);
}
__device__ __forceinline__ uint32_t sw64(uint32_t off) {
    return off ^ ((off >> 3) & 0x30);
}
#define CP_A16(s, g) \
    asm volatile("cp.async.cg.shared.global [%0], [%1], 16;" :: "r"(s), "l"(g) : "memory")
#define CP_COMMIT() asm volatile("cp.async.commit_group;" ::: "memory")
#define CP_WAIT1()  asm volatile("cp.async.wait_group 1;" ::: "memory")
#define CP_WAIT0()  asm volatile("cp.async.wait_group 0;" ::: "memory")

#define LDSM4(r, addr) \
    asm volatile("ldmatrix.sync.aligned.m8n8.x4.shared.b16 {%0,%1,%2,%3}, [%4];" \
        : "=r"((r)[0]), "=r"((r)[1]), "=r"((r)[2]), "=r"((r)[3]) : "r"(addr))
#define LDSM4T(r, addr) \
    asm volatile("ldmatrix.sync.aligned.m8n8.x4.trans.shared.b16 {%0,%1,%2,%3}, [%4];" \
        : "=r"((r)[0]), "=r"((r)[1]), "=r"((r)[2]), "=r"((r)[3]) : "r"(addr))

__device__ __forceinline__ void mma16816(float* c, const uint32_t* a,
                                         uint32_t b0, uint32_t b1) {
    asm volatile(
        "mma.sync.aligned.m16n8k16.row.col.f32.f16.f16.f32 "
        "{%0,%1,%2,%3}, {%4,%5,%6,%7}, {%8,%9}, {%0,%1,%2,%3};"
        : "+f"(c[0]), "+f"(c[1]), "+f"(c[2]), "+f"(c[3])
        : "r"(a[0]), "r"(a[1]), "r"(a[2]), "r"(a[3]), "r"(b0), "r"(b1));
}
__device__ __forceinline__ uint32_t packhf(float a, float b) {
    __half2 h = __floats2half2_rn(a, b);
    return *reinterpret_cast<uint32_t*>(&h);
}
__device__ __forceinline__ float hflo(uint32_t p) {
    __half2 h = *reinterpret_cast<__half2*>(&p);
    return __low2float(h);
}
__device__ __forceinline__ float hfhi(uint32_t p) {
    __half2 h = *reinterpret_cast<__half2*>(&p);
    return __high2float(h);
}

// ---------- packed f32x2 helpers (sm_100+ base ISA) ----------
typedef unsigned long long u64;
__device__ __forceinline__ u64 pk2(float a, float b) {
    u64 r;
    asm("mov.b64 %0, {%1,%2};" : "=l"(r) : "f"(a), "f"(b));
    return r;
}
__device__ __forceinline__ void upk2(u64 p, float& a, float& b) {
    asm("mov.b64 {%0,%1}, %2;" : "=f"(a), "=f"(b) : "l"(p));
}
#define ADD2(d, a, b) asm("add.rn.f32x2 %0, %1, %2;" : "=l"(d) : "l"(a), "l"(b))
#define MUL2(d, a, b) asm("mul.rn.f32x2 %0, %1, %2;" : "=l"(d) : "l"(a), "l"(b))
#define FMA2(d, a, b, c) \
    asm("fma.rn.f32x2 %0, %1, %2, %3;" : "=l"(d) : "l"(a), "l"(b), "l"(c))

// packed exp2 of two lanes; inputs must be <= 0 and >= ~-126 (clamp upstream
// where needed). Degree-4 poly on [-0.5,0.5], rel err ~4e-5.
struct ExpC {
    u64 M, NM, C4, C3, C2, C1, C0;
    __device__ __forceinline__ void init() {
        M  = pk2(12582912.0f, 12582912.0f);
        NM = pk2(-12582912.0f, -12582912.0f);
        C4 = pk2(9.6181291e-3f, 9.6181291e-3f);
        C3 = pk2(5.5504109e-2f, 5.5504109e-2f);
        C2 = pk2(2.4022651e-1f, 2.4022651e-1f);
        C1 = pk2(6.9314718e-1f, 6.9314718e-1f);
        C0 = pk2(1.0f, 1.0f);
    }
};
__device__ __forceinline__ u64 exp2x2(u64 x, const ExpC& C) {
    u64 z, t, f, p, sc;
    ADD2(z, x, C.M);                        // z = x + magic
    ADD2(t, z, C.NM);                       // t = round(x)
    t ^= 0x8000000080000000ull;             // -t (ALU pipe)
    ADD2(f, x, t);                          // f = x - round(x)
    p = C.C4;
    FMA2(p, p, f, C.C3);
    FMA2(p, p, f, C.C2);
    FMA2(p, p, f, C.C1);
    FMA2(p, p, f, C.C0);
    uint32_t elo = (uint32_t)z, ehi = (uint32_t)(z >> 32);
    uint32_t slo = (elo << 23) + 0x3f800000u;   // 2^round(x) per half (ALU)
    uint32_t shi = (ehi << 23) + 0x3f800000u;
    asm("mov.b64 %0, {%1,%2};" : "=l"(sc) : "r"(slo), "r"(shi));
    MUL2(p, p, sc);
    return p;
}

// ================= split / transpose prep kernels =================
__global__ __launch_bounds__(256)
void asplit(const float4* __restrict__ in, __half* __restrict__ h,
            __half* __restrict__ l)
{
    const uint32_t i = blockIdx.x * 256 + threadIdx.x;
    float4 v = in[i];
    __half h0 = __float2half_rn(v.x), h1 = __float2half_rn(v.y);
    __half h2 = __float2half_rn(v.z), h3 = __float2half_rn(v.w);
    __half l0 = __float2half_rn(v.x - __half2float(h0));
    __half l1 = __float2half_rn(v.y - __half2float(h1));
    __half l2 = __float2half_rn(v.z - __half2float(h2));
    __half l3 = __float2half_rn(v.w - __half2float(h3));
    *(__half2*)(h + 4*(size_t)i)     = __half2(h0, h1);
    *(__half2*)(h + 4*(size_t)i + 2) = __half2(h2, h3);
    *(__half2*)(l + 4*(size_t)i)     = __half2(l0, l1);
    *(__half2*)(l + 4*(size_t)i + 2) = __half2(l2, l3);
}

__global__ __launch_bounds__(256)
void wround_t(const float* __restrict__ W, __half* __restrict__ Th, int K, int N)
{
    __shared__ float t[32][33];
    const int kk = blockIdx.x * 32, nn = blockIdx.y * 32;
    const int tx = threadIdx.x & 31, ty = threadIdx.x >> 5;
    #pragma unroll
    for (int i = ty; i < 32; i += 8)
        t[i][tx] = W[(size_t)(kk + i) * N + nn + tx];
    __syncthreads();
    #pragma unroll
    for (int i = ty; i < 32; i += 8)
        Th[(size_t)(nn + i) * K + kk + tx] = __float2half_rn(t[tx][i]);
}

// ================= HMMA fp16x2 GEMM, optional fused LN/RoPE epilogue =======
#define GTILE 8192                  // 128 rows x 64 bytes
#define GSTAGE (3*GTILE)            // Ah,Al,Bh = 24 KB
#define GEMM_SMEM (3*GSTAGE)        // 73728

template<bool FUSED>
__global__ __launch_bounds__(256, 2)
void gemm_mma(const __half* __restrict__ Ah, const __half* __restrict__ Al,
              const __half* __restrict__ Bh,
              float* __restrict__ Cm, int Mdim, int Ndim, int Kdim,
              const float* __restrict__ bias,
              const float* __restrict__ cosr, const float* __restrict__ sinr,
              const float* __restrict__ qw, const float* __restrict__ qb,
              const float* __restrict__ kw, const float* __restrict__ kb,
              const int* __restrict__ pP, const int* __restrict__ pL,
              __half* __restrict__ Qh, __half* __restrict__ Ql,
              __half* __restrict__ Kh, __half* __restrict__ Vh)
{
    extern __shared__ char smem[];
    const uint32_t sb = smem_u32(smem);
    const int tid = threadIdx.x;
    const int wid = tid >> 5, lane = tid & 31;
    const int m0 = blockIdx.y * 128, n0 = blockIdx.x * 128;
    const int wm = (wid & 3) * 32, wn = (wid >> 2) * 64;
    const int nchunks = Kdim / 32;

    const __half* tp[3] = {Ah, Al, Bh};

    float acc[2][8][4];
    #pragma unroll
    for (int i = 0; i < 2; i++)
        #pragma unroll
        for (int j = 0; j < 8; j++)
            #pragma unroll
            for (int q = 0; q < 4; q++) acc[i][j][q] = 0.f;

    auto issue = [&](int c) {
        const uint32_t stg = sb + (uint32_t)(c % 3) * GSTAGE;
        const int k0 = c * 32;
        #pragma unroll
        for (int t = 0; t < 6; t++) {
            int e = tid + t * 256;
            int tile = e >> 9;
            int i = e & 511;
            int row = i >> 2, u = i & 3;
            int grow = (tile < 2 ? m0 : n0) + row;
            const __half* src = tp[tile] + (size_t)grow * Kdim + k0 + u * 8;
            uint32_t dst = stg + tile * GTILE + sw64((uint32_t)(row * 64 + u * 16));
            unsigned long long ga = (unsigned long long)__cvta_generic_to_global(src);
            CP_A16(dst, ga);
        }
    };

    issue(0); CP_COMMIT();
    issue(1); CP_COMMIT();

    for (int c = 0; c < nchunks; c++) {
        if (c == nchunks - 1) { CP_WAIT0(); } else { CP_WAIT1(); }
        __syncthreads();
        if (c + 2 < nchunks) { issue(c + 2); CP_COMMIT(); }

        const uint32_t stg = sb + (uint32_t)(c % 3) * GSTAGE;
        const uint32_t sAh = stg, sAl = stg + GTILE, sBh = stg + 2*GTILE;

        #pragma unroll
        for (int ks = 0; ks < 2; ks++) {
            uint32_t ah[2][4], al[2][4];
            #pragma unroll
            for (int mt = 0; mt < 2; mt++) {
                uint32_t off = sw64((uint32_t)((wm + mt*16 + (lane & 15)) * 64
                                               + ks*32 + (lane & 16)));
                LDSM4(ah[mt], sAh + off);
                LDSM4(al[mt], sAl + off);
            }
            uint32_t bh[4][4];
            #pragma unroll
            for (int p = 0; p < 4; p++) {
                uint32_t off = sw64((uint32_t)((wn + p*16 + (lane & 7) + ((lane & 16) >> 1)) * 64
                                               + ks*32 + ((lane & 8) << 1)));
                LDSM4(bh[p], sBh + off);
            }
            #pragma unroll
            for (int mt = 0; mt < 2; mt++)
                #pragma unroll
                for (int p = 0; p < 4; p++)
                    #pragma unroll
                    for (int h2 = 0; h2 < 2; h2++) {
                        int nt = 2*p + h2;
                        mma16816(acc[mt][nt], ah[mt], bh[p][2*h2], bh[p][2*h2+1]);
                        mma16816(acc[mt][nt], al[mt], bh[p][2*h2], bh[p][2*h2+1]);
                    }
        }
    }

    if (!FUSED) {
        #pragma unroll
        for (int mt = 0; mt < 2; mt++)
            #pragma unroll
            for (int nt = 0; nt < 8; nt++) {
                int row = m0 + wm + mt*16 + (lane >> 2);
                int col = n0 + wn + nt*8 + 2*(lane & 3);
                float b0 = 0.f, b1 = 0.f;
                if (bias) { b0 = bias[col]; b1 = bias[col + 1]; }
                float2 v0 = make_float2(acc[mt][nt][0] + b0, acc[mt][nt][1] + b1);
                float2 v1 = make_float2(acc[mt][nt][2] + b0, acc[mt][nt][3] + b1);
                *(float2*)(Cm + (size_t)row * Ndim + col)       = v0;
                *(float2*)(Cm + (size_t)(row + 8) * Ndim + col) = v1;
            }
    } else {
        const int gcol = n0 + wn;
        const int kind = gcol / C_;             // 0=q, 1=k, 2=v
        const int head = (gcol % C_) / D_;
        const int Pp = __ldg(pP), Ll = __ldg(pL);
        const float* lw = (kind == 0) ? qw : kw;
        const float* lb = (kind == 0) ? qb : kb;
        const float QSC = 0.18033688011112042f; // (1/8)*log2(e)

        #pragma unroll
        for (int mt = 0; mt < 2; mt++) {
            const int m1 = m0 + wm + mt*16 + (lane >> 2);
            const int m2 = m1 + 8;
            const int b1i = m1 >> 10, n1 = m1 & (N_-1);
            const int b2i = m2 >> 10, n2 = m2 & (N_-1);
            const size_t o1 = (((size_t)(b1i*H_ + head))*N_ + n1) * D_;
            const size_t o2 = (((size_t)(b2i*H_ + head))*N_ + n2) * D_;

            if (kind == 2) {
                #pragma unroll
                for (int nt = 0; nt < 8; nt++) {
                    int col = nt*8 + 2*(lane & 3);
                    *(uint32_t*)(Vh + o1 + col) = packhf(acc[mt][nt][0], acc[mt][nt][1]);
                    *(uint32_t*)(Vh + o2 + col) = packhf(acc[mt][nt][2], acc[mt][nt][3]);
                }
            } else {
                float s1 = 0.f, s2 = 0.f;
                #pragma unroll
                for (int nt = 0; nt < 8; nt++) {
                    s1 += acc[mt][nt][0] + acc[mt][nt][1];
                    s2 += acc[mt][nt][2] + acc[mt][nt][3];
                }
                s1 += __shfl_xor_sync(~0u, s1, 1); s1 += __shfl_xor_sync(~0u, s1, 2);
                s2 += __shfl_xor_sync(~0u, s2, 1); s2 += __shfl_xor_sync(~0u, s2, 2);
                const float mu1 = s1 * (1.0f/64.0f), mu2 = s2 * (1.0f/64.0f);
                float v1 = 0.f, v2 = 0.f;
                #pragma unroll
                for (int nt = 0; nt < 8; nt++) {
                    float d0 = acc[mt][nt][0] - mu1, d1 = acc[mt][nt][1] - mu1;
                    float d2 = acc[mt][nt][2] - mu2, d3 = acc[mt][nt][3] - mu2;
                    v1 += d0*d0 + d1*d1;
                    v2 += d2*d2 + d3*d3;
                }
                v1 += __shfl_xor_sync(~0u, v1, 1); v1 += __shfl_xor_sync(~0u, v1, 2);
                v2 += __shfl_xor_sync(~0u, v2, 1); v2 += __shfl_xor_sync(~0u, v2, 2);
                const float iv1 = rsqrtf(v1*(1.0f/64.0f) + 1e-5f);
                const float iv2 = rsqrtf(v2*(1.0f/64.0f) + 1e-5f);
                const bool r1 = (n1 >= Pp) && (n1 < N_ - Ll);
                const bool r2 = (n2 >= Pp) && (n2 < N_ - Ll);

                #pragma unroll
                for (int nt = 0; nt < 8; nt++) {
                    const int col  = nt*8 + 2*(lane & 3);
                    const int colp = nt*4 + (lane & 3);
                    float2 w2 = *(const float2*)(lw + col);
                    float2 bb = *(const float2*)(lb + col);
                    float y0 = fmaf((acc[mt][nt][0]-mu1)*iv1, w2.x, bb.x);
                    float y1 = fmaf((acc[mt][nt][1]-mu1)*iv1, w2.y, bb.y);
                    float y2 = fmaf((acc[mt][nt][2]-mu2)*iv2, w2.x, bb.x);
                    float y3 = fmaf((acc[mt][nt][3]-mu2)*iv2, w2.y, bb.y);
                    if (r1) {
                        float rc = cosr[(n1-Pp)*32 + colp], rs = sinr[(n1-Pp)*32 + colp];
                        float t0 = y0*rc - y1*rs, t1 = y0*rs + y1*rc;
                        y0 = t0; y1 = t1;
                    }
                    if (r2) {
                        float rc = cosr[(n2-Pp)*32 + colp], rs = sinr[(n2-Pp)*32 + colp];
                        float t2 = y2*rc - y3*rs, t3 = y2*rs + y3*rc;
                        y2 = t2; y3 = t3;
                    }
                    if (kind == 0) {
                        y0 *= QSC; y1 *= QSC; y2 *= QSC; y3 *= QSC;
                        uint32_t h0 = packhf(y0, y1);
                        uint32_t l0 = packhf(y0 - hflo(h0), y1 - hfhi(h0));
                        uint32_t h1 = packhf(y2, y3);
                        uint32_t l1 = packhf(y2 - hflo(h1), y3 - hfhi(h1));
                        *(uint32_t*)(Qh + o1 + col) = h0;
                        *(uint32_t*)(Ql + o1 + col) = l0;
                        *(uint32_t*)(Qh + o2 + col) = h1;
                        *(uint32_t*)(Ql + o2 + col) = l1;
                    } else {
                        *(uint32_t*)(Kh + o1 + col) = packhf(y0, y1);
                        *(uint32_t*)(Kh + o2 + col) = packhf(y2, y3);
                    }
                }
            }
        }
    }
}

// ================= HMMA flash attention (fp16x2, packed softmax) ==========
#define KTILE 8192                    // 64 rows x 128 bytes
#define ASTAGE (2*KTILE)              // Kh,Vh = 16 KB
#define ATT_SMEM (3*ASTAGE)           // 49152

__global__ __launch_bounds__(256, 2)
void attn_mma(const __half* __restrict__ Qh, const __half* __restrict__ Ql,
              const __half* __restrict__ Kh, const __half* __restrict__ Vh,
              __half* __restrict__ Oh, __half* __restrict__ Ol)
{
    extern __shared__ char smem[];
    const uint32_t sb = smem_u32(smem);
    const int tid = threadIdx.x;
    const int wid = tid >> 5, lane = tid & 31;
    const int b = blockIdx.z, h = blockIdx.y;
    const int q0 = blockIdx.x * 128;
    const size_t base = ((size_t)(b*H_ + h)) * N_;

    ExpC EC; EC.init();

    // ---- stage Q tile (hi at sb, lo at sb+16KB) ----
    {
        const __half* srcs[2] = {Qh, Ql};
        #pragma unroll
        for (int t = 0; t < 8; t++) {
            int e = tid + t * 256;
            int tile = e >> 10;
            int i = e & 1023;
            int row = i >> 3, u = i & 7;
            const __half* src = srcs[tile] + (base + q0 + row) * D_ + u * 8;
            uint4 v = *(const uint4*)src;
            *(uint4*)(smem + tile*16384 + sw128((uint32_t)(row*128 + u*16))) = v;
        }
    }
    __syncthreads();

    uint32_t qh[4][4], ql[4][4];
    #pragma unroll
    for (int ks = 0; ks < 4; ks++) {
        uint32_t off = sw128((uint32_t)((wid*16 + (lane & 15)) * 128 + ks*32 + (lane & 16)));
        LDSM4(qh[ks], sb + off);
        LDSM4(ql[ks], sb + 16384 + off);
    }
    __syncthreads();   // Q reads done; smem reusable for KV stages

    const __half* tp[2] = {Kh, Vh};
    auto issue = [&](int kt) {
        const uint32_t stg = sb + (uint32_t)(kt % 3) * ASTAGE;
        #pragma unroll
        for (int t = 0; t < 4; t++) {
            int e = tid + t * 256;
            int tile = e >> 9;
            int i = e & 511;
            int row = i >> 3, u = i & 7;
            const __half* src = tp[tile] + (base + kt*64 + row) * D_ + u * 8;
            uint32_t dst = stg + tile * KTILE + sw128((uint32_t)(row*128 + u*16));
            unsigned long long ga = (unsigned long long)__cvta_generic_to_global(src);
            CP_A16(dst, ga);
        }
    };

    float o[8][4];
    #pragma unroll
    for (int j = 0; j < 8; j++)
        #pragma unroll
        for (int q = 0; q < 4; q++) o[j][q] = 0.f;
    float mi[2] = {-3.0e38f, -3.0e38f};
    float li[2] = {0.f, 0.f};

    issue(0); CP_COMMIT();
    issue(1); CP_COMMIT();

    for (int kt = 0; kt < 16; kt++) {
        if (kt == 15) { CP_WAIT0(); } else { CP_WAIT1(); }
        __syncthreads();
        if (kt + 2 < 16) { issue(kt + 2); CP_COMMIT(); }

        const uint32_t stg = sb + (uint32_t)(kt % 3) * ASTAGE;
        const uint32_t sKh = stg, sVh = stg + KTILE;

        // ---- S = Q K^T (fp16x2) ----
        float s[8][4];
        #pragma unroll
        for (int j = 0; j < 8; j++)
            #pragma unroll
            for (int q = 0; q < 4; q++) s[j][q] = 0.f;

        #pragma unroll
        for (int ks = 0; ks < 4; ks++) {
            uint32_t kh[4][4];
            #pragma unroll
            for (int p = 0; p < 4; p++) {
                uint32_t off = sw128((uint32_t)((p*16 + (lane & 7) + ((lane & 16) >> 1)) * 128
                                                + ks*32 + ((lane & 8) << 1)));
                LDSM4(kh[p], sKh + off);
            }
            #pragma unroll
            for (int p = 0; p < 4; p++)
                #pragma unroll
                for (int h2 = 0; h2 < 2; h2++) {
                    int nt = 2*p + h2;
                    mma16816(s[nt], qh[ks], kh[p][2*h2], kh[p][2*h2+1]);
                    mma16816(s[nt], ql[ks], kh[p][2*h2], kh[p][2*h2+1]);
                }
        }

        // ---- online softmax (exp2 domain, packed f32x2) ----
        {
            float mx0 = -3.0e38f, mx1 = -3.0e38f;
            #pragma unroll
            for (int nt = 0; nt < 8; nt++) {
                mx0 = fmaxf(mx0, fmaxf(s[nt][0], s[nt][1]));
                mx1 = fmaxf(mx1, fmaxf(s[nt][2], s[nt][3]));
            }
            mx0 = fmaxf(mx0, __shfl_xor_sync(~0u, mx0, 1));
            mx0 = fmaxf(mx0, __shfl_xor_sync(~0u, mx0, 2));
            mx1 = fmaxf(mx1, __shfl_xor_sync(~0u, mx1, 1));
            mx1 = fmaxf(mx1, __shfl_xor_sync(~0u, mx1, 2));
            const float mn0 = fmaxf(mi[0], mx0), mn1 = fmaxf(mi[1], mx1);
            const float d0 = fmaxf(mi[0] - mn0, -120.f);
            const float d1 = fmaxf(mi[1] - mn1, -120.f);
            float c0, c1;
            upk2(exp2x2(pk2(d0, d1), EC), c0, c1);
            mi[0] = mn0; mi[1] = mn1;

            const u64 nm0 = pk2(-mn0, -mn0), nm1 = pk2(-mn1, -mn1);
            u64 rs0 = 0ull, rs1 = 0ull;     // packed {+0,+0}
            #pragma unroll
            for (int nt = 0; nt < 8; nt++) {
                u64 x0, x1;
                ADD2(x0, pk2(s[nt][0], s[nt][1]), nm0);
                ADD2(x1, pk2(s[nt][2], s[nt][3]), nm1);
                u64 e0 = exp2x2(x0, EC);
                u64 e1 = exp2x2(x1, EC);
                upk2(e0, s[nt][0], s[nt][1]);
                upk2(e1, s[nt][2], s[nt][3]);
                ADD2(rs0, rs0, e0);
                ADD2(rs1, rs1, e1);
            }
            float ra, rb;
            upk2(rs0, ra, rb);
            float rsum0 = ra + rb;
            upk2(rs1, ra, rb);
            float rsum1 = ra + rb;
            rsum0 += __shfl_xor_sync(~0u, rsum0, 1);
            rsum0 += __shfl_xor_sync(~0u, rsum0, 2);
            rsum1 += __shfl_xor_sync(~0u, rsum1, 1);
            rsum1 += __shfl_xor_sync(~0u, rsum1, 2);
            li[0] = fmaf(li[0], c0, rsum0);
            li[1] = fmaf(li[1], c1, rsum1);

            const u64 cp0 = pk2(c0, c0), cp1 = pk2(c1, c1);
            #pragma unroll
            for (int dt = 0; dt < 8; dt++) {
                u64 t0 = pk2(o[dt][0], o[dt][1]);
                u64 t1 = pk2(o[dt][2], o[dt][3]);
                MUL2(t0, t0, cp0);
                MUL2(t1, t1, cp1);
                upk2(t0, o[dt][0], o[dt][1]);
                upk2(t1, o[dt][2], o[dt][3]);
            }
        }

        // ---- O += P V (fp16x2), P frags built in registers ----
        #pragma unroll
        for (int ds = 0; ds < 4; ds++) {
            uint32_t ph[4], pl[4];
            #pragma unroll
            for (int half = 0; half < 2; half++) {
                int nt = 2*ds + half;
                uint32_t p0 = packhf(s[nt][0], s[nt][1]);
                uint32_t p1 = packhf(s[nt][2], s[nt][3]);
                ph[2*half]   = p0;
                ph[2*half+1] = p1;
                float r00 = s[nt][0] - hflo(p0), r01 = s[nt][1] - hfhi(p0);
                float r10 = s[nt][2] - hflo(p1), r11 = s[nt][3] - hfhi(p1);
                pl[2*half]   = packhf(r00, r01);
                pl[2*half+1] = packhf(r10, r11);
            }
            uint32_t vh[4][4];
            #pragma unroll
            for (int dj = 0; dj < 4; dj++) {
                uint32_t off = sw128((uint32_t)((ds*16 + (lane & 15)) * 128
                                                + dj*32 + (lane & 16)));
                LDSM4T(vh[dj], sVh + off);
            }
            #pragma unroll
            for (int dj = 0; dj < 4; dj++)
                #pragma unroll
                for (int h2 = 0; h2 < 2; h2++) {
                    int dt = 2*dj + h2;
                    mma16816(o[dt], ph, vh[dj][2*h2], vh[dj][2*h2+1]);
                    mma16816(o[dt], pl, vh[dj][2*h2], vh[dj][2*h2+1]);
                }
        }
    }

    // ---- epilogue: normalize, split hi/lo, store [B,N,C] ----
    const float inv1 = 1.0f / li[0];
    const float inv2 = 1.0f / li[1];
    const int row1 = q0 + wid*16 + (lane >> 2);
    #pragma unroll
    for (int dt = 0; dt < 8; dt++) {
        int col = h*D_ + dt*8 + 2*(lane & 3);
        float a0 = o[dt][0]*inv1, a1 = o[dt][1]*inv1;
        float b0 = o[dt][2]*inv2, b1 = o[dt][3]*inv2;
        uint32_t h0 = packhf(a0, a1);
        uint32_t l0 = packhf(a0 - hflo(h0), a1 - hfhi(h0));
        uint32_t h1 = packhf(b0, b1);
        uint32_t l1 = packhf(b0 - hflo(h1), b1 - hfhi(h1));
        size_t i1 = (size_t)(b*N_ + row1) * C_ + col;
        size_t i2 = (size_t)(b*N_ + row1 + 8) * C_ + col;
        *(uint32_t*)(Oh + i1) = h0;
        *(uint32_t*)(Ol + i1) = l0;
        *(uint32_t*)(Oh + i2) = h1;
        *(uint32_t*)(Ol + i2) = l1;
    }
}

// ================= launch =================
extern "C" void kernel_launch(void* const* d_in, const int* in_sizes, int n_in,
                              void* d_out, int out_size)
{
    const float* x      = (const float*)d_in[0];
    const float* cosr   = (const float*)d_in[1];
    const float* sinr   = (const float*)d_in[2];
    const float* w_qkv  = (const float*)d_in[3];
    const float* q_ln_w = (const float*)d_in[4];
    const float* q_ln_b = (const float*)d_in[5];
    const float* k_ln_w = (const float*)d_in[6];
    const float* k_ln_b = (const float*)d_in[7];
    const float* w_proj = (const float*)d_in[8];
    const float* b_proj = (const float*)d_in[9];
    const int*   pP     = (const int*)d_in[10];
    const int*   pL     = (const int*)d_in[11];
    float* out = (float*)d_out;

    __half *xh, *xl, *wqh, *wph, *qh, *ql, *kh, *vh, *oh, *ol;
    cudaGetSymbolAddress((void**)&xh,  g_xh);
    cudaGetSymbolAddress((void**)&xl,  g_xl);
    cudaGetSymbolAddress((void**)&wqh, g_wqh);
    cudaGetSymbolAddress((void**)&wph, g_wph);
    cudaGetSymbolAddress((void**)&qh,  g_qh);
    cudaGetSymbolAddress((void**)&ql,  g_ql);
    cudaGetSymbolAddress((void**)&kh,  g_kh);
    cudaGetSymbolAddress((void**)&vh,  g_vh);
    cudaGetSymbolAddress((void**)&oh,  g_oh);
    cudaGetSymbolAddress((void**)&ol,  g_ol);

    cudaFuncSetAttribute(gemm_mma<false>, cudaFuncAttributeMaxDynamicSharedMemorySize, GEMM_SMEM);
    cudaFuncSetAttribute(gemm_mma<true>,  cudaFuncAttributeMaxDynamicSharedMemorySize, GEMM_SMEM);
    cudaFuncSetAttribute(attn_mma, cudaFuncAttributeMaxDynamicSharedMemorySize, ATT_SMEM);

    // 0) weight transpose+round, input split
    wround_t<<<dim3(C_/32, QKV_/32), 256>>>(w_qkv, wqh, C_, QKV_);
    wround_t<<<dim3(C_/32, C_/32),   256>>>(w_proj, wph, C_, C_);
    asplit<<<(M_*C_/4)/256, 256>>>((const float4*)x, xh, xl);

    // 1) QKV projection with fused LN+RoPE epilogue -> fp16 Q(hi/lo)/K/V
    gemm_mma<true><<<dim3(QKV_/128, M_/128), 256, GEMM_SMEM>>>(
        xh, xl, wqh, nullptr, M_, QKV_, C_, nullptr,
        cosr, sinr, q_ln_w, q_ln_b, k_ln_w, k_ln_b, pP, pL,
        qh, ql, kh, vh);

    // 2) attention -> fp16 hi/lo [B,N,C]
    attn_mma<<<dim3(N_/128, H_, B_), 256, ATT_SMEM>>>(qh, ql, kh, vh, oh, ol);

    // 3) output projection + bias
    gemm_mma<false><<<dim3(C_/128, M_/128), 256, GEMM_SMEM>>>(
        oh, ol, wph, out, M_, C_, C_, b_proj,
        nullptr, nullptr, nullptr, nullptr, nullptr, nullptr, nullptr, nullptr,
        nullptr, nullptr, nullptr, nullptr);
}

// round 8
// speedup vs baseline: 4.8906x; 1.1766x over previous
#include <cuda_runtime.h>
#include <cuda_fp16.h>
#include <cstdint>

// Problem constants (fixed by setup_inputs)
#define B_   16
#define N_   1024
#define C_   768
#define H_   12
#define D_   64
#define M_   (B_*N_)     // 16384
#define QKV_ (3*C_)      // 2304

// ---------------- scratch (device globals: allocation-free) ----------------
__device__ __align__(16) __half g_xh[M_*C_],  g_xl[M_*C_];
__device__ __align__(16) __half g_wqh[QKV_*C_];        // [N,K] rounded
__device__ __align__(16) __half g_wph[C_*C_];          // [N,K] rounded
__device__ __align__(16) __half g_qh[B_*H_*N_*D_];
__device__ __align__(16) __half g_kh[B_*H_*N_*D_];
__device__ __align__(16) __half g_vh[B_*H_*N_*D_];
__device__ __align__(16) __half g_oh[M_*C_], g_ol[M_*C_];

// ================= low-level helpers =================
__device__ __forceinline__ uint32_t smem_u32(const void* p) {
    uint32_t a;
    asm("{ .reg .u64 t; cvta.to.shared.u64 t, %1; cvt.u32.u64 %0, t; }"
        : "=r"(a) : "l"(p));
    return a;
}
__device__ __forceinline__ uint32_t sw128(uint32_t off) {
    return off ^ ((off >> 3) & 0x70);
}
__device__ __forceinline__ uint32_t sw64(uint32_t off) {
    return off ^ ((off >> 3) & 0x30);
}
#define CP_A16(s, g) \
    asm volatile("cp.async.cg.shared.global [%0], [%1], 16;" :: "r"(s), "l"(g) : "memory")
#define CP_COMMIT() asm volatile("cp.async.commit_group;" ::: "memory")
#define CP_WAIT1()  asm volatile("cp.async.wait_group 1;" ::: "memory")
#define CP_WAIT0()  asm volatile("cp.async.wait_group 0;" ::: "memory")

#define LDSM4(r, addr) \
    asm volatile("ldmatrix.sync.aligned.m8n8.x4.shared.b16 {%0,%1,%2,%3}, [%4];" \
        : "=r"((r)[0]), "=r"((r)[1]), "=r"((r)[2]), "=r"((r)[3]) : "r"(addr))
#define LDSM4T(r, addr) \
    asm volatile("ldmatrix.sync.aligned.m8n8.x4.trans.shared.b16 {%0,%1,%2,%3}, [%4];" \
        : "=r"((r)[0]), "=r"((r)[1]), "=r"((r)[2]), "=r"((r)[3]) : "r"(addr))

__device__ __forceinline__ void mma16816(float* c, const uint32_t* a,
                                         uint32_t b0, uint32_t b1) {
    asm volatile(
        "mma.sync.aligned.m16n8k16.row.col.f32.f16.f16.f32 "
        "{%0,%1,%2,%3}, {%4,%5,%6,%7}, {%8,%9}, {%0,%1,%2,%3};"
        : "+f"(c[0]), "+f"(c[1]), "+f"(c[2]), "+f"(c[3])
        : "r"(a[0]), "r"(a[1]), "r"(a[2]), "r"(a[3]), "r"(b0), "r"(b1));
}
__device__ __forceinline__ uint32_t packhf(float a, float b) {
    __half2 h = __floats2half2_rn(a, b);
    return *reinterpret_cast<uint32_t*>(&h);
}
__device__ __forceinline__ float hflo(uint32_t p) {
    __half2 h = *reinterpret_cast<__half2*>(&p);
    return __low2float(h);
}
__device__ __forceinline__ float hfhi(uint32_t p) {
    __half2 h = *reinterpret_cast<__half2*>(&p);
    return __high2float(h);
}

// ---------- packed f32x2 helpers (sm_100+ base ISA) ----------
typedef unsigned long long u64;
__device__ __forceinline__ u64 pk2(float a, float b) {
    u64 r;
    asm("mov.b64 %0, {%1,%2};" : "=l"(r) : "f"(a), "f"(b));
    return r;
}
__device__ __forceinline__ void upk2(u64 p, float& a, float& b) {
    asm("mov.b64 {%0,%1}, %2;" : "=f"(a), "=f"(b) : "l"(p));
}
#define ADD2(d, a, b) asm("add.rn.f32x2 %0, %1, %2;" : "=l"(d) : "l"(a), "l"(b))
#define MUL2(d, a, b) asm("mul.rn.f32x2 %0, %1, %2;" : "=l"(d) : "l"(a), "l"(b))
#define FMA2(d, a, b, c) \
    asm("fma.rn.f32x2 %0, %1, %2, %3;" : "=l"(d) : "l"(a), "l"(b), "l"(c))

// packed exp2; inputs <= 0, >= ~-126. Degree-4 poly, rel err ~4e-5.
struct ExpC {
    u64 M, NM, C4, C3, C2, C1, C0;
    __device__ __forceinline__ void init() {
        M  = pk2(12582912.0f, 12582912.0f);
        NM = pk2(-12582912.0f, -12582912.0f);
        C4 = pk2(9.6181291e-3f, 9.6181291e-3f);
        C3 = pk2(5.5504109e-2f, 5.5504109e-2f);
        C2 = pk2(2.4022651e-1f, 2.4022651e-1f);
        C1 = pk2(6.9314718e-1f, 6.9314718e-1f);
        C0 = pk2(1.0f, 1.0f);
    }
};
__device__ __forceinline__ u64 exp2x2(u64 x, const ExpC& C) {
    u64 z, t, f, p, sc;
    ADD2(z, x, C.M);
    ADD2(t, z, C.NM);
    t ^= 0x8000000080000000ull;
    ADD2(f, x, t);
    p = C.C4;
    FMA2(p, p, f, C.C3);
    FMA2(p, p, f, C.C2);
    FMA2(p, p, f, C.C1);
    FMA2(p, p, f, C.C0);
    uint32_t elo = (uint32_t)z, ehi = (uint32_t)(z >> 32);
    uint32_t slo = (elo << 23) + 0x3f800000u;
    uint32_t shi = (ehi << 23) + 0x3f800000u;
    asm("mov.b64 %0, {%1,%2};" : "=l"(sc) : "r"(slo), "r"(shi));
    MUL2(p, p, sc);
    return p;
}

// ================= split / transpose prep kernels =================
__global__ __launch_bounds__(256)
void asplit(const float4* __restrict__ in, __half* __restrict__ h,
            __half* __restrict__ l)
{
    const uint32_t i = blockIdx.x * 256 + threadIdx.x;
    float4 v = in[i];
    __half h0 = __float2half_rn(v.x), h1 = __float2half_rn(v.y);
    __half h2 = __float2half_rn(v.z), h3 = __float2half_rn(v.w);
    __half l0 = __float2half_rn(v.x - __half2float(h0));
    __half l1 = __float2half_rn(v.y - __half2float(h1));
    __half l2 = __float2half_rn(v.z - __half2float(h2));
    __half l3 = __float2half_rn(v.w - __half2float(h3));
    *(__half2*)(h + 4*(size_t)i)     = __half2(h0, h1);
    *(__half2*)(h + 4*(size_t)i + 2) = __half2(h2, h3);
    *(__half2*)(l + 4*(size_t)i)     = __half2(l0, l1);
    *(__half2*)(l + 4*(size_t)i + 2) = __half2(l2, l3);
}

__global__ __launch_bounds__(256)
void wround_t(const float* __restrict__ W, __half* __restrict__ Th, int K, int N)
{
    __shared__ float t[32][33];
    const int kk = blockIdx.x * 32, nn = blockIdx.y * 32;
    const int tx = threadIdx.x & 31, ty = threadIdx.x >> 5;
    #pragma unroll
    for (int i = ty; i < 32; i += 8)
        t[i][tx] = W[(size_t)(kk + i) * N + nn + tx];
    __syncthreads();
    #pragma unroll
    for (int i = ty; i < 32; i += 8)
        Th[(size_t)(nn + i) * K + kk + tx] = __float2half_rn(t[tx][i]);
}

// ================= HMMA fp16x2 GEMM, optional fused LN/RoPE epilogue =======
#define GTILE 8192                  // 128 rows x 64 bytes
#define GSTAGE (3*GTILE)            // Ah,Al,Bh = 24 KB
#define GEMM_SMEM (3*GSTAGE)        // 73728

template<bool FUSED>
__global__ __launch_bounds__(256, 2)
void gemm_mma(const __half* __restrict__ Ah, const __half* __restrict__ Al,
              const __half* __restrict__ Bh,
              float* __restrict__ Cm, int Mdim, int Ndim, int Kdim,
              const float* __restrict__ bias,
              const float* __restrict__ cosr, const float* __restrict__ sinr,
              const float* __restrict__ qw, const float* __restrict__ qb,
              const float* __restrict__ kw, const float* __restrict__ kb,
              const int* __restrict__ pP, const int* __restrict__ pL,
              __half* __restrict__ Qh,
              __half* __restrict__ Kh, __half* __restrict__ Vh)
{
    extern __shared__ char smem[];
    const uint32_t sb = smem_u32(smem);
    const int tid = threadIdx.x;
    const int wid = tid >> 5, lane = tid & 31;
    const int m0 = blockIdx.y * 128, n0 = blockIdx.x * 128;
    const int wm = (wid & 3) * 32, wn = (wid >> 2) * 64;
    const int nchunks = Kdim / 32;

    const __half* tp[3] = {Ah, Al, Bh};

    float acc[2][8][4];
    #pragma unroll
    for (int i = 0; i < 2; i++)
        #pragma unroll
        for (int j = 0; j < 8; j++)
            #pragma unroll
            for (int q = 0; q < 4; q++) acc[i][j][q] = 0.f;

    auto issue = [&](int c) {
        const uint32_t stg = sb + (uint32_t)(c % 3) * GSTAGE;
        const int k0 = c * 32;
        #pragma unroll
        for (int t = 0; t < 6; t++) {
            int e = tid + t * 256;
            int tile = e >> 9;
            int i = e & 511;
            int row = i >> 2, u = i & 3;
            int grow = (tile < 2 ? m0 : n0) + row;
            const __half* src = tp[tile] + (size_t)grow * Kdim + k0 + u * 8;
            uint32_t dst = stg + tile * GTILE + sw64((uint32_t)(row * 64 + u * 16));
            unsigned long long ga = (unsigned long long)__cvta_generic_to_global(src);
            CP_A16(dst, ga);
        }
    };

    issue(0); CP_COMMIT();
    issue(1); CP_COMMIT();

    for (int c = 0; c < nchunks; c++) {
        if (c == nchunks - 1) { CP_WAIT0(); } else { CP_WAIT1(); }
        __syncthreads();
        if (c + 2 < nchunks) { issue(c + 2); CP_COMMIT(); }

        const uint32_t stg = sb + (uint32_t)(c % 3) * GSTAGE;
        const uint32_t sAh = stg, sAl = stg + GTILE, sBh = stg + 2*GTILE;

        #pragma unroll
        for (int ks = 0; ks < 2; ks++) {
            uint32_t ah[2][4], al[2][4];
            #pragma unroll
            for (int mt = 0; mt < 2; mt++) {
                uint32_t off = sw64((uint32_t)((wm + mt*16 + (lane & 15)) * 64
                                               + ks*32 + (lane & 16)));
                LDSM4(ah[mt], sAh + off);
                LDSM4(al[mt], sAl + off);
            }
            uint32_t bh[4][4];
            #pragma unroll
            for (int p = 0; p < 4; p++) {
                uint32_t off = sw64((uint32_t)((wn + p*16 + (lane & 7) + ((lane & 16) >> 1)) * 64
                                               + ks*32 + ((lane & 8) << 1)));
                LDSM4(bh[p], sBh + off);
            }
            #pragma unroll
            for (int mt = 0; mt < 2; mt++)
                #pragma unroll
                for (int p = 0; p < 4; p++)
                    #pragma unroll
                    for (int h2 = 0; h2 < 2; h2++) {
                        int nt = 2*p + h2;
                        mma16816(acc[mt][nt], ah[mt], bh[p][2*h2], bh[p][2*h2+1]);
                        mma16816(acc[mt][nt], al[mt], bh[p][2*h2], bh[p][2*h2+1]);
                    }
        }
    }

    if (!FUSED) {
        #pragma unroll
        for (int mt = 0; mt < 2; mt++)
            #pragma unroll
            for (int nt = 0; nt < 8; nt++) {
                int row = m0 + wm + mt*16 + (lane >> 2);
                int col = n0 + wn + nt*8 + 2*(lane & 3);
                float b0 = 0.f, b1 = 0.f;
                if (bias) { b0 = bias[col]; b1 = bias[col + 1]; }
                float2 v0 = make_float2(acc[mt][nt][0] + b0, acc[mt][nt][1] + b1);
                float2 v1 = make_float2(acc[mt][nt][2] + b0, acc[mt][nt][3] + b1);
                *(float2*)(Cm + (size_t)row * Ndim + col)       = v0;
                *(float2*)(Cm + (size_t)(row + 8) * Ndim + col) = v1;
            }
    } else {
        const int gcol = n0 + wn;
        const int kind = gcol / C_;             // 0=q, 1=k, 2=v
        const int head = (gcol % C_) / D_;
        const int Pp = __ldg(pP), Ll = __ldg(pL);
        const float* lw = (kind == 0) ? qw : kw;
        const float* lb = (kind == 0) ? qb : kb;
        const float QSC = 0.18033688011112042f; // (1/8)*log2(e)

        #pragma unroll
        for (int mt = 0; mt < 2; mt++) {
            const int m1 = m0 + wm + mt*16 + (lane >> 2);
            const int m2 = m1 + 8;
            const int b1i = m1 >> 10, n1 = m1 & (N_-1);
            const int b2i = m2 >> 10, n2 = m2 & (N_-1);
            const size_t o1 = (((size_t)(b1i*H_ + head))*N_ + n1) * D_;
            const size_t o2 = (((size_t)(b2i*H_ + head))*N_ + n2) * D_;

            if (kind == 2) {
                #pragma unroll
                for (int nt = 0; nt < 8; nt++) {
                    int col = nt*8 + 2*(lane & 3);
                    *(uint32_t*)(Vh + o1 + col) = packhf(acc[mt][nt][0], acc[mt][nt][1]);
                    *(uint32_t*)(Vh + o2 + col) = packhf(acc[mt][nt][2], acc[mt][nt][3]);
                }
            } else {
                float s1 = 0.f, s2 = 0.f;
                #pragma unroll
                for (int nt = 0; nt < 8; nt++) {
                    s1 += acc[mt][nt][0] + acc[mt][nt][1];
                    s2 += acc[mt][nt][2] + acc[mt][nt][3];
                }
                s1 += __shfl_xor_sync(~0u, s1, 1); s1 += __shfl_xor_sync(~0u, s1, 2);
                s2 += __shfl_xor_sync(~0u, s2, 1); s2 += __shfl_xor_sync(~0u, s2, 2);
                const float mu1 = s1 * (1.0f/64.0f), mu2 = s2 * (1.0f/64.0f);
                float v1 = 0.f, v2 = 0.f;
                #pragma unroll
                for (int nt = 0; nt < 8; nt++) {
                    float d0 = acc[mt][nt][0] - mu1, d1 = acc[mt][nt][1] - mu1;
                    float d2 = acc[mt][nt][2] - mu2, d3 = acc[mt][nt][3] - mu2;
                    v1 += d0*d0 + d1*d1;
                    v2 += d2*d2 + d3*d3;
                }
                v1 += __shfl_xor_sync(~0u, v1, 1); v1 += __shfl_xor_sync(~0u, v1, 2);
                v2 += __shfl_xor_sync(~0u, v2, 1); v2 += __shfl_xor_sync(~0u, v2, 2);
                const float iv1 = rsqrtf(v1*(1.0f/64.0f) + 1e-5f);
                const float iv2 = rsqrtf(v2*(1.0f/64.0f) + 1e-5f);
                const bool r1 = (n1 >= Pp) && (n1 < N_ - Ll);
                const bool r2 = (n2 >= Pp) && (n2 < N_ - Ll);

                #pragma unroll
                for (int nt = 0; nt < 8; nt++) {
                    const int col  = nt*8 + 2*(lane & 3);
                    const int colp = nt*4 + (lane & 3);
                    float2 w2 = *(const float2*)(lw + col);
                    float2 bb = *(const float2*)(lb + col);
                    float y0 = fmaf((acc[mt][nt][0]-mu1)*iv1, w2.x, bb.x);
                    float y1 = fmaf((acc[mt][nt][1]-mu1)*iv1, w2.y, bb.y);
                    float y2 = fmaf((acc[mt][nt][2]-mu2)*iv2, w2.x, bb.x);
                    float y3 = fmaf((acc[mt][nt][3]-mu2)*iv2, w2.y, bb.y);
                    if (r1) {
                        float rc = cosr[(n1-Pp)*32 + colp], rs = sinr[(n1-Pp)*32 + colp];
                        float t0 = y0*rc - y1*rs, t1 = y0*rs + y1*rc;
                        y0 = t0; y1 = t1;
                    }
                    if (r2) {
                        float rc = cosr[(n2-Pp)*32 + colp], rs = sinr[(n2-Pp)*32 + colp];
                        float t2 = y2*rc - y3*rs, t3 = y2*rs + y3*rc;
                        y2 = t2; y3 = t3;
                    }
                    if (kind == 0) {
                        y0 *= QSC; y1 *= QSC; y2 *= QSC; y3 *= QSC;
                        *(uint32_t*)(Qh + o1 + col) = packhf(y0, y1);
                        *(uint32_t*)(Qh + o2 + col) = packhf(y2, y3);
                    } else {
                        *(uint32_t*)(Kh + o1 + col) = packhf(y0, y1);
                        *(uint32_t*)(Kh + o2 + col) = packhf(y2, y3);
                    }
                }
            }
        }
    }
}

// ================= HMMA flash attention (fp16 single-term, packed softmax) =
#define KTILE 8192                    // 64 rows x 128 bytes
#define ASTAGE (2*KTILE)              // Kh,Vh = 16 KB
#define ATT_SMEM (3*ASTAGE)           // 49152

__global__ __launch_bounds__(256, 2)
void attn_mma(const __half* __restrict__ Qh,
              const __half* __restrict__ Kh, const __half* __restrict__ Vh,
              __half* __restrict__ Oh, __half* __restrict__ Ol)
{
    extern __shared__ char smem[];
    const uint32_t sb = smem_u32(smem);
    const int tid = threadIdx.x;
    const int wid = tid >> 5, lane = tid & 31;
    const int b = blockIdx.z, h = blockIdx.y;
    const int q0 = blockIdx.x * 128;
    const size_t base = ((size_t)(b*H_ + h)) * N_;

    ExpC EC; EC.init();

    // ---- stage Q tile (hi only, 16 KB) ----
    #pragma unroll
    for (int t = 0; t < 4; t++) {
        int e = tid + t * 256;
        int row = e >> 3, u = e & 7;
        const __half* src = Qh + (base + q0 + row) * D_ + u * 8;
        uint4 v = *(const uint4*)src;
        *(uint4*)(smem + sw128((uint32_t)(row*128 + u*16))) = v;
    }
    __syncthreads();

    uint32_t qh[4][4];
    #pragma unroll
    for (int ks = 0; ks < 4; ks++) {
        uint32_t off = sw128((uint32_t)((wid*16 + (lane & 15)) * 128 + ks*32 + (lane & 16)));
        LDSM4(qh[ks], sb + off);
    }
    __syncthreads();   // Q reads done; smem reusable for KV stages

    const __half* tp[2] = {Kh, Vh};
    auto issue = [&](int kt) {
        const uint32_t stg = sb + (uint32_t)(kt % 3) * ASTAGE;
        #pragma unroll
        for (int t = 0; t < 4; t++) {
            int e = tid + t * 256;
            int tile = e >> 9;
            int i = e & 511;
            int row = i >> 3, u = i & 7;
            const __half* src = tp[tile] + (base + kt*64 + row) * D_ + u * 8;
            uint32_t dst = stg + tile * KTILE + sw128((uint32_t)(row*128 + u*16));
            unsigned long long ga = (unsigned long long)__cvta_generic_to_global(src);
            CP_A16(dst, ga);
        }
    };

    float o[8][4];
    #pragma unroll
    for (int j = 0; j < 8; j++)
        #pragma unroll
        for (int q = 0; q < 4; q++) o[j][q] = 0.f;
    float mi[2] = {-3.0e38f, -3.0e38f};
    float li[2] = {0.f, 0.f};

    issue(0); CP_COMMIT();
    issue(1); CP_COMMIT();

    for (int kt = 0; kt < 16; kt++) {
        if (kt == 15) { CP_WAIT0(); } else { CP_WAIT1(); }
        __syncthreads();
        if (kt + 2 < 16) { issue(kt + 2); CP_COMMIT(); }

        const uint32_t stg = sb + (uint32_t)(kt % 3) * ASTAGE;
        const uint32_t sKh = stg, sVh = stg + KTILE;

        // ---- S = Q K^T (fp16 single-term) ----
        float s[8][4];
        #pragma unroll
        for (int j = 0; j < 8; j++)
            #pragma unroll
            for (int q = 0; q < 4; q++) s[j][q] = 0.f;

        #pragma unroll
        for (int ks = 0; ks < 4; ks++) {
            uint32_t kh[4][4];
            #pragma unroll
            for (int p = 0; p < 4; p++) {
                uint32_t off = sw128((uint32_t)((p*16 + (lane & 7) + ((lane & 16) >> 1)) * 128
                                                + ks*32 + ((lane & 8) << 1)));
                LDSM4(kh[p], sKh + off);
            }
            #pragma unroll
            for (int p = 0; p < 4; p++)
                #pragma unroll
                for (int h2 = 0; h2 < 2; h2++) {
                    int nt = 2*p + h2;
                    mma16816(s[nt], qh[ks], kh[p][2*h2], kh[p][2*h2+1]);
                }
        }

        // ---- online softmax (exp2 domain, packed f32x2) ----
        {
            float mx0 = -3.0e38f, mx1 = -3.0e38f;
            #pragma unroll
            for (int nt = 0; nt < 8; nt++) {
                mx0 = fmaxf(mx0, fmaxf(s[nt][0], s[nt][1]));
                mx1 = fmaxf(mx1, fmaxf(s[nt][2], s[nt][3]));
            }
            mx0 = fmaxf(mx0, __shfl_xor_sync(~0u, mx0, 1));
            mx0 = fmaxf(mx0, __shfl_xor_sync(~0u, mx0, 2));
            mx1 = fmaxf(mx1, __shfl_xor_sync(~0u, mx1, 1));
            mx1 = fmaxf(mx1, __shfl_xor_sync(~0u, mx1, 2));
            const float mn0 = fmaxf(mi[0], mx0), mn1 = fmaxf(mi[1], mx1);
            const float d0 = fmaxf(mi[0] - mn0, -120.f);
            const float d1 = fmaxf(mi[1] - mn1, -120.f);
            float c0, c1;
            upk2(exp2x2(pk2(d0, d1), EC), c0, c1);
            mi[0] = mn0; mi[1] = mn1;

            const u64 nm0 = pk2(-mn0, -mn0), nm1 = pk2(-mn1, -mn1);
            u64 rs0 = 0ull, rs1 = 0ull;
            #pragma unroll
            for (int nt = 0; nt < 8; nt++) {
                u64 x0, x1;
                ADD2(x0, pk2(s[nt][0], s[nt][1]), nm0);
                ADD2(x1, pk2(s[nt][2], s[nt][3]), nm1);
                u64 e0 = exp2x2(x0, EC);
                u64 e1 = exp2x2(x1, EC);
                upk2(e0, s[nt][0], s[nt][1]);
                upk2(e1, s[nt][2], s[nt][3]);
                ADD2(rs0, rs0, e0);
                ADD2(rs1, rs1, e1);
            }
            float ra, rb;
            upk2(rs0, ra, rb);
            float rsum0 = ra + rb;
            upk2(rs1, ra, rb);
            float rsum1 = ra + rb;
            rsum0 += __shfl_xor_sync(~0u, rsum0, 1);
            rsum0 += __shfl_xor_sync(~0u, rsum0, 2);
            rsum1 += __shfl_xor_sync(~0u, rsum1, 1);
            rsum1 += __shfl_xor_sync(~0u, rsum1, 2);
            li[0] = fmaf(li[0], c0, rsum0);
            li[1] = fmaf(li[1], c1, rsum1);

            const u64 cp0 = pk2(c0, c0), cp1 = pk2(c1, c1);
            #pragma unroll
            for (int dt = 0; dt < 8; dt++) {
                u64 t0 = pk2(o[dt][0], o[dt][1]);
                u64 t1 = pk2(o[dt][2], o[dt][3]);
                MUL2(t0, t0, cp0);
                MUL2(t1, t1, cp1);
                upk2(t0, o[dt][0], o[dt][1]);
                upk2(t1, o[dt][2], o[dt][3]);
            }
        }

        // ---- O += P V (fp16 single-term P) ----
        #pragma unroll
        for (int ds = 0; ds < 4; ds++) {
            uint32_t ph[4];
            #pragma unroll
            for (int half = 0; half < 2; half++) {
                int nt = 2*ds + half;
                ph[2*half]   = packhf(s[nt][0], s[nt][1]);
                ph[2*half+1] = packhf(s[nt][2], s[nt][3]);
            }
            uint32_t vh[4][4];
            #pragma unroll
            for (int dj = 0; dj < 4; dj++) {
                uint32_t off = sw128((uint32_t)((ds*16 + (lane & 15)) * 128
                                                + dj*32 + (lane & 16)));
                LDSM4T(vh[dj], sVh + off);
            }
            #pragma unroll
            for (int dj = 0; dj < 4; dj++)
                #pragma unroll
                for (int h2 = 0; h2 < 2; h2++) {
                    int dt = 2*dj + h2;
                    mma16816(o[dt], ph, vh[dj][2*h2], vh[dj][2*h2+1]);
                }
        }
    }

    // ---- epilogue: normalize, split hi/lo, store [B,N,C] ----
    const float inv1 = 1.0f / li[0];
    const float inv2 = 1.0f / li[1];
    const int row1 = q0 + wid*16 + (lane >> 2);
    #pragma unroll
    for (int dt = 0; dt < 8; dt++) {
        int col = h*D_ + dt*8 + 2*(lane & 3);
        float a0 = o[dt][0]*inv1, a1 = o[dt][1]*inv1;
        float b0 = o[dt][2]*inv2, b1 = o[dt][3]*inv2;
        uint32_t h0 = packhf(a0, a1);
        uint32_t l0 = packhf(a0 - hflo(h0), a1 - hfhi(h0));
        uint32_t h1 = packhf(b0, b1);
        uint32_t l1 = packhf(b0 - hflo(h1), b1 - hfhi(h1));
        size_t i1 = (size_t)(b*N_ + row1) * C_ + col;
        size_t i2 = (size_t)(b*N_ + row1 + 8) * C_ + col;
        *(uint32_t*)(Oh + i1) = h0;
        *(uint32_t*)(Ol + i1) = l0;
        *(uint32_t*)(Oh + i2) = h1;
        *(uint32_t*)(Ol + i2) = l1;
    }
}

// ================= launch =================
extern "C" void kernel_launch(void* const* d_in, const int* in_sizes, int n_in,
                              void* d_out, int out_size)
{
    const float* x      = (const float*)d_in[0];
    const float* cosr   = (const float*)d_in[1];
    const float* sinr   = (const float*)d_in[2];
    const float* w_qkv  = (const float*)d_in[3];
    const float* q_ln_w = (const float*)d_in[4];
    const float* q_ln_b = (const float*)d_in[5];
    const float* k_ln_w = (const float*)d_in[6];
    const float* k_ln_b = (const float*)d_in[7];
    const float* w_proj = (const float*)d_in[8];
    const float* b_proj = (const float*)d_in[9];
    const int*   pP     = (const int*)d_in[10];
    const int*   pL     = (const int*)d_in[11];
    float* out = (float*)d_out;

    __half *xh, *xl, *wqh, *wph, *qh, *kh, *vh, *oh, *ol;
    cudaGetSymbolAddress((void**)&xh,  g_xh);
    cudaGetSymbolAddress((void**)&xl,  g_xl);
    cudaGetSymbolAddress((void**)&wqh, g_wqh);
    cudaGetSymbolAddress((void**)&wph, g_wph);
    cudaGetSymbolAddress((void**)&qh,  g_qh);
    cudaGetSymbolAddress((void**)&kh,  g_kh);
    cudaGetSymbolAddress((void**)&vh,  g_vh);
    cudaGetSymbolAddress((void**)&oh,  g_oh);
    cudaGetSymbolAddress((void**)&ol,  g_ol);

    cudaFuncSetAttribute(gemm_mma<false>, cudaFuncAttributeMaxDynamicSharedMemorySize, GEMM_SMEM);
    cudaFuncSetAttribute(gemm_mma<true>,  cudaFuncAttributeMaxDynamicSharedMemorySize, GEMM_SMEM);
    cudaFuncSetAttribute(attn_mma, cudaFuncAttributeMaxDynamicSharedMemorySize, ATT_SMEM);

    // 0) weight transpose+round, input split
    wround_t<<<dim3(C_/32, QKV_/32), 256>>>(w_qkv, wqh, C_, QKV_);
    wround_t<<<dim3(C_/32, C_/32),   256>>>(w_proj, wph, C_, C_);
    asplit<<<(M_*C_/4)/256, 256>>>((const float4*)x, xh, xl);

    // 1) QKV projection with fused LN+RoPE epilogue -> fp16 Q/K/V
    gemm_mma<true><<<dim3(QKV_/128, M_/128), 256, GEMM_SMEM>>>(
        xh, xl, wqh, nullptr, M_, QKV_, C_, nullptr,
        cosr, sinr, q_ln_w, q_ln_b, k_ln_w, k_ln_b, pP, pL,
        qh, kh, vh);

    // 2) attention -> fp16 hi/lo [B,N,C]
    attn_mma<<<dim3(N_/128, H_, B_), 256, ATT_SMEM>>>(qh, kh, vh, oh, ol);

    // 3) output projection + bias
    gemm_mma<false><<<dim3(C_/128, M_/128), 256, GEMM_SMEM>>>(
        oh, ol, wph, out, M_, C_, C_, b_proj,
        nullptr, nullptr, nullptr, nullptr, nullptr, nullptr, nullptr, nullptr,
        nullptr, nullptr, nullptr);
}

// round 9
// speedup vs baseline: 6.4035x; 1.3093x over previous
#include <cuda_runtime.h>
#include <cuda_fp16.h>
#include <cstdint>

// Problem constants (fixed by setup_inputs)
#define B_   16
#define N_   1024
#define C_   768
#define H_   12
#define D_   64
#define M_   (B_*N_)     // 16384
#define QKV_ (3*C_)      // 2304

// ---------------- scratch (device globals: allocation-free) ----------------
__device__ __align__(16) __half g_xh[M_*C_];
__device__ __align__(16) __half g_wqh[QKV_*C_];        // [N,K] rounded
__device__ __align__(16) __half g_wph[C_*C_];          // [N,K] rounded
__device__ __align__(16) __half g_qh[B_*H_*N_*D_];
__device__ __align__(16) __half g_kh[B_*H_*N_*D_];
__device__ __align__(16) __half g_vh[B_*H_*N_*D_];
__device__ __align__(16) __half g_oh[M_*C_];

// ================= low-level helpers =================
__device__ __forceinline__ uint32_t smem_u32(const void* p) {
    uint32_t a;
    asm("{ .reg .u64 t; cvta.to.shared.u64 t, %1; cvt.u32.u64 %0, t; }"
        : "=r"(a) : "l"(p));
    return a;
}
__device__ __forceinline__ uint32_t sw128(uint32_t off) {
    return off ^ ((off >> 3) & 0x70);
}
__device__ __forceinline__ uint32_t sw64(uint32_t off) {
    return off ^ ((off >> 3) & 0x30);
}
#define CP_A16(s, g) \
    asm volatile("cp.async.cg.shared.global [%0], [%1], 16;" :: "r"(s), "l"(g) : "memory")
#define CP_COMMIT() asm volatile("cp.async.commit_group;" ::: "memory")
#define CP_WAIT1()  asm volatile("cp.async.wait_group 1;" ::: "memory")
#define CP_WAIT0()  asm volatile("cp.async.wait_group 0;" ::: "memory")

#define LDSM4(r, addr) \
    asm volatile("ldmatrix.sync.aligned.m8n8.x4.shared.b16 {%0,%1,%2,%3}, [%4];" \
        : "=r"((r)[0]), "=r"((r)[1]), "=r"((r)[2]), "=r"((r)[3]) : "r"(addr))
#define LDSM4T(r, addr) \
    asm volatile("ldmatrix.sync.aligned.m8n8.x4.trans.shared.b16 {%0,%1,%2,%3}, [%4];" \
        : "=r"((r)[0]), "=r"((r)[1]), "=r"((r)[2]), "=r"((r)[3]) : "r"(addr))

__device__ __forceinline__ void mma16816(float* c, const uint32_t* a,
                                         uint32_t b0, uint32_t b1) {
    asm volatile(
        "mma.sync.aligned.m16n8k16.row.col.f32.f16.f16.f32 "
        "{%0,%1,%2,%3}, {%4,%5,%6,%7}, {%8,%9}, {%0,%1,%2,%3};"
        : "+f"(c[0]), "+f"(c[1]), "+f"(c[2]), "+f"(c[3])
        : "r"(a[0]), "r"(a[1]), "r"(a[2]), "r"(a[3]), "r"(b0), "r"(b1));
}
__device__ __forceinline__ uint32_t packhf(float a, float b) {
    __half2 h = __floats2half2_rn(a, b);
    return *reinterpret_cast<uint32_t*>(&h);
}

// ---------- packed f32x2 helpers (sm_100+ base ISA) ----------
typedef unsigned long long u64;
__device__ __forceinline__ u64 pk2(float a, float b) {
    u64 r;
    asm("mov.b64 %0, {%1,%2};" : "=l"(r) : "f"(a), "f"(b));
    return r;
}
__device__ __forceinline__ void upk2(u64 p, float& a, float& b) {
    asm("mov.b64 {%0,%1}, %2;" : "=f"(a), "=f"(b) : "l"(p));
}
#define ADD2(d, a, b) asm("add.rn.f32x2 %0, %1, %2;" : "=l"(d) : "l"(a), "l"(b))
#define MUL2(d, a, b) asm("mul.rn.f32x2 %0, %1, %2;" : "=l"(d) : "l"(a), "l"(b))
#define FMA2(d, a, b, c) \
    asm("fma.rn.f32x2 %0, %1, %2, %3;" : "=l"(d) : "l"(a), "l"(b), "l"(c))

// packed exp2; inputs <= 0, >= ~-126. Degree-4 poly, rel err ~4e-5.
struct ExpC {
    u64 M, NM, C4, C3, C2, C1, C0;
    __device__ __forceinline__ void init() {
        M  = pk2(12582912.0f, 12582912.0f);
        NM = pk2(-12582912.0f, -12582912.0f);
        C4 = pk2(9.6181291e-3f, 9.6181291e-3f);
        C3 = pk2(5.5504109e-2f, 5.5504109e-2f);
        C2 = pk2(2.4022651e-1f, 2.4022651e-1f);
        C1 = pk2(6.9314718e-1f, 6.9314718e-1f);
        C0 = pk2(1.0f, 1.0f);
    }
};
__device__ __forceinline__ u64 exp2x2(u64 x, const ExpC& C) {
    u64 z, t, f, p, sc;
    ADD2(z, x, C.M);
    ADD2(t, z, C.NM);
    t ^= 0x8000000080000000ull;
    ADD2(f, x, t);
    p = C.C4;
    FMA2(p, p, f, C.C3);
    FMA2(p, p, f, C.C2);
    FMA2(p, p, f, C.C1);
    FMA2(p, p, f, C.C0);
    uint32_t elo = (uint32_t)z, ehi = (uint32_t)(z >> 32);
    uint32_t slo = (elo << 23) + 0x3f800000u;
    uint32_t shi = (ehi << 23) + 0x3f800000u;
    asm("mov.b64 %0, {%1,%2};" : "=l"(sc) : "r"(slo), "r"(shi));
    MUL2(p, p, sc);
    return p;
}

// ================= prep kernels =================
// fp32 -> fp16 round
__global__ __launch_bounds__(256)
void around(const float4* __restrict__ in, __half* __restrict__ h)
{
    const uint32_t i = blockIdx.x * 256 + threadIdx.x;
    float4 v = in[i];
    *(__half2*)(h + 4*(size_t)i)     = __floats2half2_rn(v.x, v.y);
    *(__half2*)(h + 4*(size_t)i + 2) = __floats2half2_rn(v.z, v.w);
}

// W[K,N] fp32 -> Wt[N,K] fp16 (transpose + round)
__global__ __launch_bounds__(256)
void wround_t(const float* __restrict__ W, __half* __restrict__ Th, int K, int N)
{
    __shared__ float t[32][33];
    const int kk = blockIdx.x * 32, nn = blockIdx.y * 32;
    const int tx = threadIdx.x & 31, ty = threadIdx.x >> 5;
    #pragma unroll
    for (int i = ty; i < 32; i += 8)
        t[i][tx] = W[(size_t)(kk + i) * N + nn + tx];
    __syncthreads();
    #pragma unroll
    for (int i = ty; i < 32; i += 8)
        Th[(size_t)(nn + i) * K + kk + tx] = __float2half_rn(t[tx][i]);
}

// ================= fp16 HMMA GEMM, optional fused LN/RoPE epilogue =======
#define GTILE 8192                  // 128 rows x 64 bytes
#define GSTAGE (2*GTILE)            // A,B = 16 KB
#define GEMM_SMEM (3*GSTAGE)        // 49152

template<bool FUSED>
__global__ __launch_bounds__(256, 2)
void gemm_mma(const __half* __restrict__ Ah, const __half* __restrict__ Bh,
              float* __restrict__ Cm, int Mdim, int Ndim, int Kdim,
              const float* __restrict__ bias,
              const float* __restrict__ cosr, const float* __restrict__ sinr,
              const float* __restrict__ qw, const float* __restrict__ qb,
              const float* __restrict__ kw, const float* __restrict__ kb,
              const int* __restrict__ pP, const int* __restrict__ pL,
              __half* __restrict__ Qh,
              __half* __restrict__ Kh, __half* __restrict__ Vh)
{
    extern __shared__ char smem[];
    const uint32_t sb = smem_u32(smem);
    const int tid = threadIdx.x;
    const int wid = tid >> 5, lane = tid & 31;
    const int m0 = blockIdx.y * 128, n0 = blockIdx.x * 128;
    const int wm = (wid & 3) * 32, wn = (wid >> 2) * 64;
    const int nchunks = Kdim / 32;

    const __half* tp[2] = {Ah, Bh};

    float acc[2][8][4];
    #pragma unroll
    for (int i = 0; i < 2; i++)
        #pragma unroll
        for (int j = 0; j < 8; j++)
            #pragma unroll
            for (int q = 0; q < 4; q++) acc[i][j][q] = 0.f;

    auto issue = [&](int c) {
        const uint32_t stg = sb + (uint32_t)(c % 3) * GSTAGE;
        const int k0 = c * 32;
        #pragma unroll
        for (int t = 0; t < 4; t++) {
            int e = tid + t * 256;
            int tile = e >> 9;
            int i = e & 511;
            int row = i >> 2, u = i & 3;
            int grow = (tile == 0 ? m0 : n0) + row;
            const __half* src = tp[tile] + (size_t)grow * Kdim + k0 + u * 8;
            uint32_t dst = stg + tile * GTILE + sw64((uint32_t)(row * 64 + u * 16));
            unsigned long long ga = (unsigned long long)__cvta_generic_to_global(src);
            CP_A16(dst, ga);
        }
    };

    issue(0); CP_COMMIT();
    issue(1); CP_COMMIT();

    for (int c = 0; c < nchunks; c++) {
        if (c == nchunks - 1) { CP_WAIT0(); } else { CP_WAIT1(); }
        __syncthreads();
        if (c + 2 < nchunks) { issue(c + 2); CP_COMMIT(); }

        const uint32_t stg = sb + (uint32_t)(c % 3) * GSTAGE;
        const uint32_t sAh = stg, sBh = stg + GTILE;

        #pragma unroll
        for (int ks = 0; ks < 2; ks++) {
            uint32_t ah[2][4];
            #pragma unroll
            for (int mt = 0; mt < 2; mt++) {
                uint32_t off = sw64((uint32_t)((wm + mt*16 + (lane & 15)) * 64
                                               + ks*32 + (lane & 16)));
                LDSM4(ah[mt], sAh + off);
            }
            uint32_t bh[4][4];
            #pragma unroll
            for (int p = 0; p < 4; p++) {
                uint32_t off = sw64((uint32_t)((wn + p*16 + (lane & 7) + ((lane & 16) >> 1)) * 64
                                               + ks*32 + ((lane & 8) << 1)));
                LDSM4(bh[p], sBh + off);
            }
            #pragma unroll
            for (int mt = 0; mt < 2; mt++)
                #pragma unroll
                for (int p = 0; p < 4; p++)
                    #pragma unroll
                    for (int h2 = 0; h2 < 2; h2++) {
                        int nt = 2*p + h2;
                        mma16816(acc[mt][nt], ah[mt], bh[p][2*h2], bh[p][2*h2+1]);
                    }
        }
    }

    if (!FUSED) {
        #pragma unroll
        for (int mt = 0; mt < 2; mt++)
            #pragma unroll
            for (int nt = 0; nt < 8; nt++) {
                int row = m0 + wm + mt*16 + (lane >> 2);
                int col = n0 + wn + nt*8 + 2*(lane & 3);
                float b0 = 0.f, b1 = 0.f;
                if (bias) { b0 = bias[col]; b1 = bias[col + 1]; }
                float2 v0 = make_float2(acc[mt][nt][0] + b0, acc[mt][nt][1] + b1);
                float2 v1 = make_float2(acc[mt][nt][2] + b0, acc[mt][nt][3] + b1);
                *(float2*)(Cm + (size_t)row * Ndim + col)       = v0;
                *(float2*)(Cm + (size_t)(row + 8) * Ndim + col) = v1;
            }
    } else {
        const int gcol = n0 + wn;
        const int kind = gcol / C_;             // 0=q, 1=k, 2=v
        const int head = (gcol % C_) / D_;
        const int Pp = __ldg(pP), Ll = __ldg(pL);
        const float* lw = (kind == 0) ? qw : kw;
        const float* lb = (kind == 0) ? qb : kb;
        const float QSC = 0.18033688011112042f; // (1/8)*log2(e)

        #pragma unroll
        for (int mt = 0; mt < 2; mt++) {
            const int m1 = m0 + wm + mt*16 + (lane >> 2);
            const int m2 = m1 + 8;
            const int b1i = m1 >> 10, n1 = m1 & (N_-1);
            const int b2i = m2 >> 10, n2 = m2 & (N_-1);
            const size_t o1 = (((size_t)(b1i*H_ + head))*N_ + n1) * D_;
            const size_t o2 = (((size_t)(b2i*H_ + head))*N_ + n2) * D_;

            if (kind == 2) {
                #pragma unroll
                for (int nt = 0; nt < 8; nt++) {
                    int col = nt*8 + 2*(lane & 3);
                    *(uint32_t*)(Vh + o1 + col) = packhf(acc[mt][nt][0], acc[mt][nt][1]);
                    *(uint32_t*)(Vh + o2 + col) = packhf(acc[mt][nt][2], acc[mt][nt][3]);
                }
            } else {
                float s1 = 0.f, s2 = 0.f;
                #pragma unroll
                for (int nt = 0; nt < 8; nt++) {
                    s1 += acc[mt][nt][0] + acc[mt][nt][1];
                    s2 += acc[mt][nt][2] + acc[mt][nt][3];
                }
                s1 += __shfl_xor_sync(~0u, s1, 1); s1 += __shfl_xor_sync(~0u, s1, 2);
                s2 += __shfl_xor_sync(~0u, s2, 1); s2 += __shfl_xor_sync(~0u, s2, 2);
                const float mu1 = s1 * (1.0f/64.0f), mu2 = s2 * (1.0f/64.0f);
                float v1 = 0.f, v2 = 0.f;
                #pragma unroll
                for (int nt = 0; nt < 8; nt++) {
                    float d0 = acc[mt][nt][0] - mu1, d1 = acc[mt][nt][1] - mu1;
                    float d2 = acc[mt][nt][2] - mu2, d3 = acc[mt][nt][3] - mu2;
                    v1 += d0*d0 + d1*d1;
                    v2 += d2*d2 + d3*d3;
                }
                v1 += __shfl_xor_sync(~0u, v1, 1); v1 += __shfl_xor_sync(~0u, v1, 2);
                v2 += __shfl_xor_sync(~0u, v2, 1); v2 += __shfl_xor_sync(~0u, v2, 2);
                const float iv1 = rsqrtf(v1*(1.0f/64.0f) + 1e-5f);
                const float iv2 = rsqrtf(v2*(1.0f/64.0f) + 1e-5f);
                const bool r1 = (n1 >= Pp) && (n1 < N_ - Ll);
                const bool r2 = (n2 >= Pp) && (n2 < N_ - Ll);

                #pragma unroll
                for (int nt = 0; nt < 8; nt++) {
                    const int col  = nt*8 + 2*(lane & 3);
                    const int colp = nt*4 + (lane & 3);
                    float2 w2 = *(const float2*)(lw + col);
                    float2 bb = *(const float2*)(lb + col);
                    float y0 = fmaf((acc[mt][nt][0]-mu1)*iv1, w2.x, bb.x);
                    float y1 = fmaf((acc[mt][nt][1]-mu1)*iv1, w2.y, bb.y);
                    float y2 = fmaf((acc[mt][nt][2]-mu2)*iv2, w2.x, bb.x);
                    float y3 = fmaf((acc[mt][nt][3]-mu2)*iv2, w2.y, bb.y);
                    if (r1) {
                        float rc = cosr[(n1-Pp)*32 + colp], rs = sinr[(n1-Pp)*32 + colp];
                        float t0 = y0*rc - y1*rs, t1 = y0*rs + y1*rc;
                        y0 = t0; y1 = t1;
                    }
                    if (r2) {
                        float rc = cosr[(n2-Pp)*32 + colp], rs = sinr[(n2-Pp)*32 + colp];
                        float t2 = y2*rc - y3*rs, t3 = y2*rs + y3*rc;
                        y2 = t2; y3 = t3;
                    }
                    if (kind == 0) {
                        y0 *= QSC; y1 *= QSC; y2 *= QSC; y3 *= QSC;
                        *(uint32_t*)(Qh + o1 + col) = packhf(y0, y1);
                        *(uint32_t*)(Qh + o2 + col) = packhf(y2, y3);
                    } else {
                        *(uint32_t*)(Kh + o1 + col) = packhf(y0, y1);
                        *(uint32_t*)(Kh + o2 + col) = packhf(y2, y3);
                    }
                }
            }
        }
    }
}

// ================= HMMA flash attention (fp16, packed softmax) =============
#define KTILE 8192                    // 64 rows x 128 bytes
#define ASTAGE (2*KTILE)              // Kh,Vh = 16 KB
#define ATT_SMEM (3*ASTAGE)           // 49152

__global__ __launch_bounds__(256, 2)
void attn_mma(const __half* __restrict__ Qh,
              const __half* __restrict__ Kh, const __half* __restrict__ Vh,
              __half* __restrict__ Oh)
{
    extern __shared__ char smem[];
    const uint32_t sb = smem_u32(smem);
    const int tid = threadIdx.x;
    const int wid = tid >> 5, lane = tid & 31;
    const int b = blockIdx.z, h = blockIdx.y;
    const int q0 = blockIdx.x * 128;
    const size_t base = ((size_t)(b*H_ + h)) * N_;

    ExpC EC; EC.init();

    // ---- stage Q tile (16 KB) ----
    #pragma unroll
    for (int t = 0; t < 4; t++) {
        int e = tid + t * 256;
        int row = e >> 3, u = e & 7;
        const __half* src = Qh + (base + q0 + row) * D_ + u * 8;
        uint4 v = *(const uint4*)src;
        *(uint4*)(smem + sw128((uint32_t)(row*128 + u*16))) = v;
    }
    __syncthreads();

    uint32_t qh[4][4];
    #pragma unroll
    for (int ks = 0; ks < 4; ks++) {
        uint32_t off = sw128((uint32_t)((wid*16 + (lane & 15)) * 128 + ks*32 + (lane & 16)));
        LDSM4(qh[ks], sb + off);
    }
    __syncthreads();   // Q reads done; smem reusable for KV stages

    const __half* tp[2] = {Kh, Vh};
    auto issue = [&](int kt) {
        const uint32_t stg = sb + (uint32_t)(kt % 3) * ASTAGE;
        #pragma unroll
        for (int t = 0; t < 4; t++) {
            int e = tid + t * 256;
            int tile = e >> 9;
            int i = e & 511;
            int row = i >> 3, u = i & 7;
            const __half* src = tp[tile] + (base + kt*64 + row) * D_ + u * 8;
            uint32_t dst = stg + tile * KTILE + sw128((uint32_t)(row*128 + u*16));
            unsigned long long ga = (unsigned long long)__cvta_generic_to_global(src);
            CP_A16(dst, ga);
        }
    };

    float o[8][4];
    #pragma unroll
    for (int j = 0; j < 8; j++)
        #pragma unroll
        for (int q = 0; q < 4; q++) o[j][q] = 0.f;
    float mi[2] = {-3.0e38f, -3.0e38f};
    float li[2] = {0.f, 0.f};

    issue(0); CP_COMMIT();
    issue(1); CP_COMMIT();

    for (int kt = 0; kt < 16; kt++) {
        if (kt == 15) { CP_WAIT0(); } else { CP_WAIT1(); }
        __syncthreads();
        if (kt + 2 < 16) { issue(kt + 2); CP_COMMIT(); }

        const uint32_t stg = sb + (uint32_t)(kt % 3) * ASTAGE;
        const uint32_t sKh = stg, sVh = stg + KTILE;

        // ---- S = Q K^T ----
        float s[8][4];
        #pragma unroll
        for (int j = 0; j < 8; j++)
            #pragma unroll
            for (int q = 0; q < 4; q++) s[j][q] = 0.f;

        #pragma unroll
        for (int ks = 0; ks < 4; ks++) {
            uint32_t kh[4][4];
            #pragma unroll
            for (int p = 0; p < 4; p++) {
                uint32_t off = sw128((uint32_t)((p*16 + (lane & 7) + ((lane & 16) >> 1)) * 128
                                                + ks*32 + ((lane & 8) << 1)));
                LDSM4(kh[p], sKh + off);
            }
            #pragma unroll
            for (int p = 0; p < 4; p++)
                #pragma unroll
                for (int h2 = 0; h2 < 2; h2++) {
                    int nt = 2*p + h2;
                    mma16816(s[nt], qh[ks], kh[p][2*h2], kh[p][2*h2+1]);
                }
        }

        // ---- online softmax (exp2 domain, packed f32x2) ----
        {
            float mx0 = -3.0e38f, mx1 = -3.0e38f;
            #pragma unroll
            for (int nt = 0; nt < 8; nt++) {
                mx0 = fmaxf(mx0, fmaxf(s[nt][0], s[nt][1]));
                mx1 = fmaxf(mx1, fmaxf(s[nt][2], s[nt][3]));
            }
            mx0 = fmaxf(mx0, __shfl_xor_sync(~0u, mx0, 1));
            mx0 = fmaxf(mx0, __shfl_xor_sync(~0u, mx0, 2));
            mx1 = fmaxf(mx1, __shfl_xor_sync(~0u, mx1, 1));
            mx1 = fmaxf(mx1, __shfl_xor_sync(~0u, mx1, 2));
            const float mn0 = fmaxf(mi[0], mx0), mn1 = fmaxf(mi[1], mx1);
            const float d0 = fmaxf(mi[0] - mn0, -120.f);
            const float d1 = fmaxf(mi[1] - mn1, -120.f);
            float c0, c1;
            upk2(exp2x2(pk2(d0, d1), EC), c0, c1);
            mi[0] = mn0; mi[1] = mn1;

            const u64 nm0 = pk2(-mn0, -mn0), nm1 = pk2(-mn1, -mn1);
            u64 rs0 = 0ull, rs1 = 0ull;
            #pragma unroll
            for (int nt = 0; nt < 8; nt++) {
                u64 x0, x1;
                ADD2(x0, pk2(s[nt][0], s[nt][1]), nm0);
                ADD2(x1, pk2(s[nt][2], s[nt][3]), nm1);
                u64 e0 = exp2x2(x0, EC);
                u64 e1 = exp2x2(x1, EC);
                upk2(e0, s[nt][0], s[nt][1]);
                upk2(e1, s[nt][2], s[nt][3]);
                ADD2(rs0, rs0, e0);
                ADD2(rs1, rs1, e1);
            }
            float ra, rb;
            upk2(rs0, ra, rb);
            float rsum0 = ra + rb;
            upk2(rs1, ra, rb);
            float rsum1 = ra + rb;
            rsum0 += __shfl_xor_sync(~0u, rsum0, 1);
            rsum0 += __shfl_xor_sync(~0u, rsum0, 2);
            rsum1 += __shfl_xor_sync(~0u, rsum1, 1);
            rsum1 += __shfl_xor_sync(~0u, rsum1, 2);
            li[0] = fmaf(li[0], c0, rsum0);
            li[1] = fmaf(li[1], c1, rsum1);

            const u64 cp0 = pk2(c0, c0), cp1 = pk2(c1, c1);
            #pragma unroll
            for (int dt = 0; dt < 8; dt++) {
                u64 t0 = pk2(o[dt][0], o[dt][1]);
                u64 t1 = pk2(o[dt][2], o[dt][3]);
                MUL2(t0, t0, cp0);
                MUL2(t1, t1, cp1);
                upk2(t0, o[dt][0], o[dt][1]);
                upk2(t1, o[dt][2], o[dt][3]);
            }
        }

        // ---- O += P V ----
        #pragma unroll
        for (int ds = 0; ds < 4; ds++) {
            uint32_t ph[4];
            #pragma unroll
            for (int half = 0; half < 2; half++) {
                int nt = 2*ds + half;
                ph[2*half]   = packhf(s[nt][0], s[nt][1]);
                ph[2*half+1] = packhf(s[nt][2], s[nt][3]);
            }
            uint32_t vh[4][4];
            #pragma unroll
            for (int dj = 0; dj < 4; dj++) {
                uint32_t off = sw128((uint32_t)((ds*16 + (lane & 15)) * 128
                                                + dj*32 + (lane & 16)));
                LDSM4T(vh[dj], sVh + off);
            }
            #pragma unroll
            for (int dj = 0; dj < 4; dj++)
                #pragma unroll
                for (int h2 = 0; h2 < 2; h2++) {
                    int dt = 2*dj + h2;
                    mma16816(o[dt], ph, vh[dj][2*h2], vh[dj][2*h2+1]);
                }
        }
    }

    // ---- epilogue: normalize, round fp16, store [B,N,C] ----
    const float inv1 = 1.0f / li[0];
    const float inv2 = 1.0f / li[1];
    const int row1 = q0 + wid*16 + (lane >> 2);
    #pragma unroll
    for (int dt = 0; dt < 8; dt++) {
        int col = h*D_ + dt*8 + 2*(lane & 3);
        size_t i1 = (size_t)(b*N_ + row1) * C_ + col;
        size_t i2 = (size_t)(b*N_ + row1 + 8) * C_ + col;
        *(uint32_t*)(Oh + i1) = packhf(o[dt][0]*inv1, o[dt][1]*inv1);
        *(uint32_t*)(Oh + i2) = packhf(o[dt][2]*inv2, o[dt][3]*inv2);
    }
}

// ================= launch =================
extern "C" void kernel_launch(void* const* d_in, const int* in_sizes, int n_in,
                              void* d_out, int out_size)
{
    const float* x      = (const float*)d_in[0];
    const float* cosr   = (const float*)d_in[1];
    const float* sinr   = (const float*)d_in[2];
    const float* w_qkv  = (const float*)d_in[3];
    const float* q_ln_w = (const float*)d_in[4];
    const float* q_ln_b = (const float*)d_in[5];
    const float* k_ln_w = (const float*)d_in[6];
    const float* k_ln_b = (const float*)d_in[7];
    const float* w_proj = (const float*)d_in[8];
    const float* b_proj = (const float*)d_in[9];
    const int*   pP     = (const int*)d_in[10];
    const int*   pL     = (const int*)d_in[11];
    float* out = (float*)d_out;

    __half *xh, *wqh, *wph, *qh, *kh, *vh, *oh;
    cudaGetSymbolAddress((void**)&xh,  g_xh);
    cudaGetSymbolAddress((void**)&wqh, g_wqh);
    cudaGetSymbolAddress((void**)&wph, g_wph);
    cudaGetSymbolAddress((void**)&qh,  g_qh);
    cudaGetSymbolAddress((void**)&kh,  g_kh);
    cudaGetSymbolAddress((void**)&vh,  g_vh);
    cudaGetSymbolAddress((void**)&oh,  g_oh);

    cudaFuncSetAttribute(gemm_mma<false>, cudaFuncAttributeMaxDynamicSharedMemorySize, GEMM_SMEM);
    cudaFuncSetAttribute(gemm_mma<true>,  cudaFuncAttributeMaxDynamicSharedMemorySize, GEMM_SMEM);
    cudaFuncSetAttribute(attn_mma, cudaFuncAttributeMaxDynamicSharedMemorySize, ATT_SMEM);

    // 0) weight transpose+round, input round
    wround_t<<<dim3(C_/32, QKV_/32), 256>>>(w_qkv, wqh, C_, QKV_);
    wround_t<<<dim3(C_/32, C_/32),   256>>>(w_proj, wph, C_, C_);
    around<<<(M_*C_/4)/256, 256>>>((const float4*)x, xh);

    // 1) QKV projection with fused LN+RoPE epilogue -> fp16 Q/K/V
    gemm_mma<true><<<dim3(QKV_/128, M_/128), 256, GEMM_SMEM>>>(
        xh, wqh, nullptr, M_, QKV_, C_, nullptr,
        cosr, sinr, q_ln_w, q_ln_b, k_ln_w, k_ln_b, pP, pL,
        qh, kh, vh);

    // 2) attention -> fp16 [B,N,C]
    attn_mma<<<dim3(N_/128, H_, B_), 256, ATT_SMEM>>>(qh, kh, vh, oh);

    // 3) output projection + bias
    gemm_mma<false><<<dim3(C_/128, M_/128), 256, GEMM_SMEM>>>(
        oh, wph, out, M_, C_, C_, b_proj,
        nullptr, nullptr, nullptr, nullptr, nullptr, nullptr, nullptr, nullptr,
        nullptr, nullptr, nullptr);
}

// round 10
// speedup vs baseline: 6.6612x; 1.0402x over previous
#include <cuda_runtime.h>
#include <cuda_fp16.h>
#include <cstdint>

// Problem constants (fixed by setup_inputs)
#define B_   16
#define N_   1024
#define C_   768
#define H_   12
#define D_   64
#define M_   (B_*N_)     // 16384
#define QKV_ (3*C_)      // 2304

// ---------------- scratch (device globals: allocation-free) ----------------
__device__ __align__(16) __half g_xh[M_*C_];
__device__ __align__(16) __half g_wqh[QKV_*C_];        // [N,K] rounded
__device__ __align__(16) __half g_wph[C_*C_];          // [N,K] rounded
__device__ __align__(16) __half g_qh[B_*H_*N_*D_];
__device__ __align__(16) __half g_kh[B_*H_*N_*D_];
__device__ __align__(16) __half g_vh[B_*H_*N_*D_];
__device__ __align__(16) __half g_oh[M_*C_];

// ================= low-level helpers =================
__device__ __forceinline__ uint32_t smem_u32(const void* p) {
    uint32_t a;
    asm("{ .reg .u64 t; cvta.to.shared.u64 t, %1; cvt.u32.u64 %0, t; }"
        : "=r"(a) : "l"(p));
    return a;
}
__device__ __forceinline__ uint32_t sw128(uint32_t off) {
    return off ^ ((off >> 3) & 0x70);
}
#define CP_A16(s, g) \
    asm volatile("cp.async.cg.shared.global [%0], [%1], 16;" :: "r"(s), "l"(g) : "memory")
#define CP_COMMIT() asm volatile("cp.async.commit_group;" ::: "memory")
#define CP_WAIT1()  asm volatile("cp.async.wait_group 1;" ::: "memory")
#define CP_WAIT0()  asm volatile("cp.async.wait_group 0;" ::: "memory")

#define LDSM4(r, addr) \
    asm volatile("ldmatrix.sync.aligned.m8n8.x4.shared.b16 {%0,%1,%2,%3}, [%4];" \
        : "=r"((r)[0]), "=r"((r)[1]), "=r"((r)[2]), "=r"((r)[3]) : "r"(addr))
#define LDSM4T(r, addr) \
    asm volatile("ldmatrix.sync.aligned.m8n8.x4.trans.shared.b16 {%0,%1,%2,%3}, [%4];" \
        : "=r"((r)[0]), "=r"((r)[1]), "=r"((r)[2]), "=r"((r)[3]) : "r"(addr))

__device__ __forceinline__ void mma16816(float* c, const uint32_t* a,
                                         uint32_t b0, uint32_t b1) {
    asm volatile(
        "mma.sync.aligned.m16n8k16.row.col.f32.f16.f16.f32 "
        "{%0,%1,%2,%3}, {%4,%5,%6,%7}, {%8,%9}, {%0,%1,%2,%3};"
        : "+f"(c[0]), "+f"(c[1]), "+f"(c[2]), "+f"(c[3])
        : "r"(a[0]), "r"(a[1]), "r"(a[2]), "r"(a[3]), "r"(b0), "r"(b1));
}
__device__ __forceinline__ uint32_t packhf(float a, float b) {
    __half2 h = __floats2half2_rn(a, b);
    return *reinterpret_cast<uint32_t*>(&h);
}

// ---------- packed f32x2 helpers (sm_100+ base ISA) ----------
typedef unsigned long long u64;
__device__ __forceinline__ u64 pk2(float a, float b) {
    u64 r;
    asm("mov.b64 %0, {%1,%2};" : "=l"(r) : "f"(a), "f"(b));
    return r;
}
__device__ __forceinline__ void upk2(u64 p, float& a, float& b) {
    asm("mov.b64 {%0,%1}, %2;" : "=f"(a), "=f"(b) : "l"(p));
}
#define ADD2(d, a, b) asm("add.rn.f32x2 %0, %1, %2;" : "=l"(d) : "l"(a), "l"(b))
#define MUL2(d, a, b) asm("mul.rn.f32x2 %0, %1, %2;" : "=l"(d) : "l"(a), "l"(b))
#define FMA2(d, a, b, c) \
    asm("fma.rn.f32x2 %0, %1, %2, %3;" : "=l"(d) : "l"(a), "l"(b), "l"(c))

// packed exp2; inputs <= 0, >= ~-126. Degree-4 poly, rel err ~4e-5.
struct ExpC {
    u64 M, NM, C4, C3, C2, C1, C0;
    __device__ __forceinline__ void init() {
        M  = pk2(12582912.0f, 12582912.0f);
        NM = pk2(-12582912.0f, -12582912.0f);
        C4 = pk2(9.6181291e-3f, 9.6181291e-3f);
        C3 = pk2(5.5504109e-2f, 5.5504109e-2f);
        C2 = pk2(2.4022651e-1f, 2.4022651e-1f);
        C1 = pk2(6.9314718e-1f, 6.9314718e-1f);
        C0 = pk2(1.0f, 1.0f);
    }
};
__device__ __forceinline__ u64 exp2x2(u64 x, const ExpC& C) {
    u64 z, t, f, p, sc;
    ADD2(z, x, C.M);
    ADD2(t, z, C.NM);
    t ^= 0x8000000080000000ull;
    ADD2(f, x, t);
    p = C.C4;
    FMA2(p, p, f, C.C3);
    FMA2(p, p, f, C.C2);
    FMA2(p, p, f, C.C1);
    FMA2(p, p, f, C.C0);
    uint32_t elo = (uint32_t)z, ehi = (uint32_t)(z >> 32);
    uint32_t slo = (elo << 23) + 0x3f800000u;
    uint32_t shi = (ehi << 23) + 0x3f800000u;
    asm("mov.b64 %0, {%1,%2};" : "=l"(sc) : "r"(slo), "r"(shi));
    MUL2(p, p, sc);
    return p;
}

// ================= prep kernels =================
__global__ __launch_bounds__(256)
void around(const float4* __restrict__ in, __half* __restrict__ h)
{
    const uint32_t i = blockIdx.x * 256 + threadIdx.x;
    float4 v = in[i];
    *(__half2*)(h + 4*(size_t)i)     = __floats2half2_rn(v.x, v.y);
    *(__half2*)(h + 4*(size_t)i + 2) = __floats2half2_rn(v.z, v.w);
}

__global__ __launch_bounds__(256)
void wround_t(const float* __restrict__ W, __half* __restrict__ Th, int K, int N)
{
    __shared__ float t[32][33];
    const int kk = blockIdx.x * 32, nn = blockIdx.y * 32;
    const int tx = threadIdx.x & 31, ty = threadIdx.x >> 5;
    #pragma unroll
    for (int i = ty; i < 32; i += 8)
        t[i][tx] = W[(size_t)(kk + i) * N + nn + tx];
    __syncthreads();
    #pragma unroll
    for (int i = ty; i < 32; i += 8)
        Th[(size_t)(nn + i) * K + kk + tx] = __float2half_rn(t[tx][i]);
}

// ================= fp16 HMMA GEMM, optional fused LN/RoPE epilogue =======
// KC=64, 3-stage pipeline, 32 KB/stage, 96 KB smem, 2 CTAs/SM.
#define GTILE 16384                 // 128 rows x 128 bytes
#define GSTAGE (2*GTILE)            // A,B = 32 KB
#define GEMM_SMEM (3*GSTAGE)        // 98304

template<bool FUSED>
__global__ __launch_bounds__(256, 2)
void gemm_mma(const __half* __restrict__ Ah, const __half* __restrict__ Bh,
              float* __restrict__ Cm, int Mdim, int Ndim, int Kdim,
              const float* __restrict__ bias,
              const float* __restrict__ cosr, const float* __restrict__ sinr,
              const float* __restrict__ qw, const float* __restrict__ qb,
              const float* __restrict__ kw, const float* __restrict__ kb,
              const int* __restrict__ pP, const int* __restrict__ pL,
              __half* __restrict__ Qh,
              __half* __restrict__ Kh, __half* __restrict__ Vh)
{
    extern __shared__ char smem[];
    const uint32_t sb = smem_u32(smem);
    const int tid = threadIdx.x;
    const int wid = tid >> 5, lane = tid & 31;
    const int m0 = blockIdx.y * 128, n0 = blockIdx.x * 128;
    const int wm = (wid & 3) * 32, wn = (wid >> 2) * 64;
    const int nchunks = Kdim / 64;   // 12

    const __half* tp[2] = {Ah, Bh};

    float acc[2][8][4];
    #pragma unroll
    for (int i = 0; i < 2; i++)
        #pragma unroll
        for (int j = 0; j < 8; j++)
            #pragma unroll
            for (int q = 0; q < 4; q++) acc[i][j][q] = 0.f;

    auto issue = [&](int c) {
        const uint32_t stg = sb + (uint32_t)(c % 3) * GSTAGE;
        const int k0 = c * 64;
        #pragma unroll
        for (int t = 0; t < 8; t++) {
            int e = tid + t * 256;
            int tile = e >> 10;
            int i = e & 1023;
            int row = i >> 3, u = i & 7;
            int grow = (tile == 0 ? m0 : n0) + row;
            const __half* src = tp[tile] + (size_t)grow * Kdim + k0 + u * 8;
            uint32_t dst = stg + tile * GTILE + sw128((uint32_t)(row * 128 + u * 16));
            unsigned long long ga = (unsigned long long)__cvta_generic_to_global(src);
            CP_A16(dst, ga);
        }
    };

    issue(0); CP_COMMIT();
    issue(1); CP_COMMIT();

    for (int c = 0; c < nchunks; c++) {
        if (c == nchunks - 1) { CP_WAIT0(); } else { CP_WAIT1(); }
        __syncthreads();
        if (c + 2 < nchunks) { issue(c + 2); CP_COMMIT(); }

        const uint32_t stg = sb + (uint32_t)(c % 3) * GSTAGE;
        const uint32_t sAh = stg, sBh = stg + GTILE;

        #pragma unroll
        for (int ks = 0; ks < 4; ks++) {
            uint32_t ah[2][4];
            #pragma unroll
            for (int mt = 0; mt < 2; mt++) {
                uint32_t off = sw128((uint32_t)((wm + mt*16 + (lane & 15)) * 128
                                                + ks*32 + (lane & 16)));
                LDSM4(ah[mt], sAh + off);
            }
            uint32_t bh[4][4];
            #pragma unroll
            for (int p = 0; p < 4; p++) {
                uint32_t off = sw128((uint32_t)((wn + p*16 + (lane & 7) + ((lane & 16) >> 1)) * 128
                                                + ks*32 + ((lane & 8) << 1)));
                LDSM4(bh[p], sBh + off);
            }
            #pragma unroll
            for (int mt = 0; mt < 2; mt++)
                #pragma unroll
                for (int p = 0; p < 4; p++)
                    #pragma unroll
                    for (int h2 = 0; h2 < 2; h2++) {
                        int nt = 2*p + h2;
                        mma16816(acc[mt][nt], ah[mt], bh[p][2*h2], bh[p][2*h2+1]);
                    }
        }
    }

    if (!FUSED) {
        #pragma unroll
        for (int mt = 0; mt < 2; mt++)
            #pragma unroll
            for (int nt = 0; nt < 8; nt++) {
                int row = m0 + wm + mt*16 + (lane >> 2);
                int col = n0 + wn + nt*8 + 2*(lane & 3);
                float b0 = 0.f, b1 = 0.f;
                if (bias) { b0 = bias[col]; b1 = bias[col + 1]; }
                float2 v0 = make_float2(acc[mt][nt][0] + b0, acc[mt][nt][1] + b1);
                float2 v1 = make_float2(acc[mt][nt][2] + b0, acc[mt][nt][3] + b1);
                *(float2*)(Cm + (size_t)row * Ndim + col)       = v0;
                *(float2*)(Cm + (size_t)(row + 8) * Ndim + col) = v1;
            }
    } else {
        const int gcol = n0 + wn;
        const int kind = gcol / C_;             // 0=q, 1=k, 2=v
        const int head = (gcol % C_) / D_;
        const int Pp = __ldg(pP), Ll = __ldg(pL);
        const float* lw = (kind == 0) ? qw : kw;
        const float* lb = (kind == 0) ? qb : kb;
        const float QSC = 0.18033688011112042f; // (1/8)*log2(e)

        #pragma unroll
        for (int mt = 0; mt < 2; mt++) {
            const int m1 = m0 + wm + mt*16 + (lane >> 2);
            const int m2 = m1 + 8;
            const int b1i = m1 >> 10, n1 = m1 & (N_-1);
            const int b2i = m2 >> 10, n2 = m2 & (N_-1);
            const size_t o1 = (((size_t)(b1i*H_ + head))*N_ + n1) * D_;
            const size_t o2 = (((size_t)(b2i*H_ + head))*N_ + n2) * D_;

            if (kind == 2) {
                #pragma unroll
                for (int nt = 0; nt < 8; nt++) {
                    int col = nt*8 + 2*(lane & 3);
                    *(uint32_t*)(Vh + o1 + col) = packhf(acc[mt][nt][0], acc[mt][nt][1]);
                    *(uint32_t*)(Vh + o2 + col) = packhf(acc[mt][nt][2], acc[mt][nt][3]);
                }
            } else {
                float s1 = 0.f, s2 = 0.f;
                #pragma unroll
                for (int nt = 0; nt < 8; nt++) {
                    s1 += acc[mt][nt][0] + acc[mt][nt][1];
                    s2 += acc[mt][nt][2] + acc[mt][nt][3];
                }
                s1 += __shfl_xor_sync(~0u, s1, 1); s1 += __shfl_xor_sync(~0u, s1, 2);
                s2 += __shfl_xor_sync(~0u, s2, 1); s2 += __shfl_xor_sync(~0u, s2, 2);
                const float mu1 = s1 * (1.0f/64.0f), mu2 = s2 * (1.0f/64.0f);
                float v1 = 0.f, v2 = 0.f;
                #pragma unroll
                for (int nt = 0; nt < 8; nt++) {
                    float d0 = acc[mt][nt][0] - mu1, d1 = acc[mt][nt][1] - mu1;
                    float d2 = acc[mt][nt][2] - mu2, d3 = acc[mt][nt][3] - mu2;
                    v1 += d0*d0 + d1*d1;
                    v2 += d2*d2 + d3*d3;
                }
                v1 += __shfl_xor_sync(~0u, v1, 1); v1 += __shfl_xor_sync(~0u, v1, 2);
                v2 += __shfl_xor_sync(~0u, v2, 1); v2 += __shfl_xor_sync(~0u, v2, 2);
                const float iv1 = rsqrtf(v1*(1.0f/64.0f) + 1e-5f);
                const float iv2 = rsqrtf(v2*(1.0f/64.0f) + 1e-5f);
                const bool r1 = (n1 >= Pp) && (n1 < N_ - Ll);
                const bool r2 = (n2 >= Pp) && (n2 < N_ - Ll);

                #pragma unroll
                for (int nt = 0; nt < 8; nt++) {
                    const int col  = nt*8 + 2*(lane & 3);
                    const int colp = nt*4 + (lane & 3);
                    float2 w2 = *(const float2*)(lw + col);
                    float2 bb = *(const float2*)(lb + col);
                    float y0 = fmaf((acc[mt][nt][0]-mu1)*iv1, w2.x, bb.x);
                    float y1 = fmaf((acc[mt][nt][1]-mu1)*iv1, w2.y, bb.y);
                    float y2 = fmaf((acc[mt][nt][2]-mu2)*iv2, w2.x, bb.x);
                    float y3 = fmaf((acc[mt][nt][3]-mu2)*iv2, w2.y, bb.y);
                    if (r1) {
                        float rc = cosr[(n1-Pp)*32 + colp], rs = sinr[(n1-Pp)*32 + colp];
                        float t0 = y0*rc - y1*rs, t1 = y0*rs + y1*rc;
                        y0 = t0; y1 = t1;
                    }
                    if (r2) {
                        float rc = cosr[(n2-Pp)*32 + colp], rs = sinr[(n2-Pp)*32 + colp];
                        float t2 = y2*rc - y3*rs, t3 = y2*rs + y3*rc;
                        y2 = t2; y3 = t3;
                    }
                    if (kind == 0) {
                        y0 *= QSC; y1 *= QSC; y2 *= QSC; y3 *= QSC;
                        *(uint32_t*)(Qh + o1 + col) = packhf(y0, y1);
                        *(uint32_t*)(Qh + o2 + col) = packhf(y2, y3);
                    } else {
                        *(uint32_t*)(Kh + o1 + col) = packhf(y0, y1);
                        *(uint32_t*)(Kh + o2 + col) = packhf(y2, y3);
                    }
                }
            }
        }
    }
}

// ================= HMMA flash attention (fp16, packed softmax) =============
// KV chunk = 128 rows/stage (two 64-row sub-bodies), 3 stages, 96 KB, 2 CTA/SM.
#define KTILE2 16384                  // 128 rows x 128 bytes
#define ASTAGE (2*KTILE2)             // Kh,Vh = 32 KB
#define ATT_SMEM (3*ASTAGE)           // 98304

__global__ __launch_bounds__(256, 2)
void attn_mma(const __half* __restrict__ Qh,
              const __half* __restrict__ Kh, const __half* __restrict__ Vh,
              __half* __restrict__ Oh)
{
    extern __shared__ char smem[];
    const uint32_t sb = smem_u32(smem);
    const int tid = threadIdx.x;
    const int wid = tid >> 5, lane = tid & 31;
    const int b = blockIdx.z, h = blockIdx.y;
    const int q0 = blockIdx.x * 128;
    const size_t base = ((size_t)(b*H_ + h)) * N_;

    ExpC EC; EC.init();

    // ---- stage Q tile (16 KB, in stage-0 area) ----
    #pragma unroll
    for (int t = 0; t < 4; t++) {
        int e = tid + t * 256;
        int row = e >> 3, u = e & 7;
        const __half* src = Qh + (base + q0 + row) * D_ + u * 8;
        uint4 v = *(const uint4*)src;
        *(uint4*)(smem + sw128((uint32_t)(row*128 + u*16))) = v;
    }
    __syncthreads();

    uint32_t qh[4][4];
    #pragma unroll
    for (int ks = 0; ks < 4; ks++) {
        uint32_t off = sw128((uint32_t)((wid*16 + (lane & 15)) * 128 + ks*32 + (lane & 16)));
        LDSM4(qh[ks], sb + off);
    }
    __syncthreads();   // Q reads done; smem reusable for KV stages

    const __half* tp[2] = {Kh, Vh};
    auto issue = [&](int kt) {
        const uint32_t stg = sb + (uint32_t)(kt % 3) * ASTAGE;
        #pragma unroll
        for (int t = 0; t < 8; t++) {
            int e = tid + t * 256;
            int tile = e >> 10;
            int i = e & 1023;
            int row = i >> 3, u = i & 7;
            const __half* src = tp[tile] + (base + kt*128 + row) * D_ + u * 8;
            uint32_t dst = stg + tile * KTILE2 + sw128((uint32_t)(row*128 + u*16));
            unsigned long long ga = (unsigned long long)__cvta_generic_to_global(src);
            CP_A16(dst, ga);
        }
    };

    float o[8][4];
    #pragma unroll
    for (int j = 0; j < 8; j++)
        #pragma unroll
        for (int q = 0; q < 4; q++) o[j][q] = 0.f;
    float mi[2] = {-3.0e38f, -3.0e38f};
    float li[2] = {0.f, 0.f};

    issue(0); CP_COMMIT();
    issue(1); CP_COMMIT();

    for (int kt = 0; kt < 8; kt++) {
        if (kt == 7) { CP_WAIT0(); } else { CP_WAIT1(); }
        __syncthreads();
        if (kt + 2 < 8) { issue(kt + 2); CP_COMMIT(); }

        const uint32_t stg = sb + (uint32_t)(kt % 3) * ASTAGE;

        #pragma unroll
        for (int sub = 0; sub < 2; sub++) {
            const uint32_t sKh = stg + (uint32_t)sub * 8192;
            const uint32_t sVh = stg + KTILE2 + (uint32_t)sub * 8192;

            // ---- S = Q K^T ----
            float s[8][4];
            #pragma unroll
            for (int j = 0; j < 8; j++)
                #pragma unroll
                for (int q = 0; q < 4; q++) s[j][q] = 0.f;

            #pragma unroll
            for (int ks = 0; ks < 4; ks++) {
                uint32_t kh[4][4];
                #pragma unroll
                for (int p = 0; p < 4; p++) {
                    uint32_t off = sw128((uint32_t)((p*16 + (lane & 7) + ((lane & 16) >> 1)) * 128
                                                    + ks*32 + ((lane & 8) << 1)));
                    LDSM4(kh[p], sKh + off);
                }
                #pragma unroll
                for (int p = 0; p < 4; p++)
                    #pragma unroll
                    for (int h2 = 0; h2 < 2; h2++) {
                        int nt = 2*p + h2;
                        mma16816(s[nt], qh[ks], kh[p][2*h2], kh[p][2*h2+1]);
                    }
            }

            // ---- online softmax (exp2 domain, packed f32x2) ----
            {
                float mx0 = -3.0e38f, mx1 = -3.0e38f;
                #pragma unroll
                for (int nt = 0; nt < 8; nt++) {
                    mx0 = fmaxf(mx0, fmaxf(s[nt][0], s[nt][1]));
                    mx1 = fmaxf(mx1, fmaxf(s[nt][2], s[nt][3]));
                }
                mx0 = fmaxf(mx0, __shfl_xor_sync(~0u, mx0, 1));
                mx0 = fmaxf(mx0, __shfl_xor_sync(~0u, mx0, 2));
                mx1 = fmaxf(mx1, __shfl_xor_sync(~0u, mx1, 1));
                mx1 = fmaxf(mx1, __shfl_xor_sync(~0u, mx1, 2));
                const float mn0 = fmaxf(mi[0], mx0), mn1 = fmaxf(mi[1], mx1);
                const float d0 = fmaxf(mi[0] - mn0, -120.f);
                const float d1 = fmaxf(mi[1] - mn1, -120.f);
                float c0, c1;
                upk2(exp2x2(pk2(d0, d1), EC), c0, c1);
                mi[0] = mn0; mi[1] = mn1;

                const u64 nm0 = pk2(-mn0, -mn0), nm1 = pk2(-mn1, -mn1);
                u64 rs0 = 0ull, rs1 = 0ull;
                #pragma unroll
                for (int nt = 0; nt < 8; nt++) {
                    u64 x0, x1;
                    ADD2(x0, pk2(s[nt][0], s[nt][1]), nm0);
                    ADD2(x1, pk2(s[nt][2], s[nt][3]), nm1);
                    u64 e0 = exp2x2(x0, EC);
                    u64 e1 = exp2x2(x1, EC);
                    upk2(e0, s[nt][0], s[nt][1]);
                    upk2(e1, s[nt][2], s[nt][3]);
                    ADD2(rs0, rs0, e0);
                    ADD2(rs1, rs1, e1);
                }
                float ra, rb;
                upk2(rs0, ra, rb);
                float rsum0 = ra + rb;
                upk2(rs1, ra, rb);
                float rsum1 = ra + rb;
                rsum0 += __shfl_xor_sync(~0u, rsum0, 1);
                rsum0 += __shfl_xor_sync(~0u, rsum0, 2);
                rsum1 += __shfl_xor_sync(~0u, rsum1, 1);
                rsum1 += __shfl_xor_sync(~0u, rsum1, 2);
                li[0] = fmaf(li[0], c0, rsum0);
                li[1] = fmaf(li[1], c1, rsum1);

                const u64 cp0 = pk2(c0, c0), cp1 = pk2(c1, c1);
                #pragma unroll
                for (int dt = 0; dt < 8; dt++) {
                    u64 t0 = pk2(o[dt][0], o[dt][1]);
                    u64 t1 = pk2(o[dt][2], o[dt][3]);
                    MUL2(t0, t0, cp0);
                    MUL2(t1, t1, cp1);
                    upk2(t0, o[dt][0], o[dt][1]);
                    upk2(t1, o[dt][2], o[dt][3]);
                }
            }

            // ---- O += P V ----
            #pragma unroll
            for (int ds = 0; ds < 4; ds++) {
                uint32_t ph[4];
                #pragma unroll
                for (int half = 0; half < 2; half++) {
                    int nt = 2*ds + half;
                    ph[2*half]   = packhf(s[nt][0], s[nt][1]);
                    ph[2*half+1] = packhf(s[nt][2], s[nt][3]);
                }
                uint32_t vh[4][4];
                #pragma unroll
                for (int dj = 0; dj < 4; dj++) {
                    uint32_t off = sw128((uint32_t)((ds*16 + (lane & 15)) * 128
                                                    + dj*32 + (lane & 16)));
                    LDSM4T(vh[dj], sVh + off);
                }
                #pragma unroll
                for (int dj = 0; dj < 4; dj++)
                    #pragma unroll
                    for (int h2 = 0; h2 < 2; h2++) {
                        int dt = 2*dj + h2;
                        mma16816(o[dt], ph, vh[dj][2*h2], vh[dj][2*h2+1]);
                    }
            }
        }
    }

    // ---- epilogue: normalize, round fp16, store [B,N,C] ----
    const float inv1 = 1.0f / li[0];
    const float inv2 = 1.0f / li[1];
    const int row1 = q0 + wid*16 + (lane >> 2);
    #pragma unroll
    for (int dt = 0; dt < 8; dt++) {
        int col = h*D_ + dt*8 + 2*(lane & 3);
        size_t i1 = (size_t)(b*N_ + row1) * C_ + col;
        size_t i2 = (size_t)(b*N_ + row1 + 8) * C_ + col;
        *(uint32_t*)(Oh + i1) = packhf(o[dt][0]*inv1, o[dt][1]*inv1);
        *(uint32_t*)(Oh + i2) = packhf(o[dt][2]*inv2, o[dt][3]*inv2);
    }
}

// ================= launch =================
extern "C" void kernel_launch(void* const* d_in, const int* in_sizes, int n_in,
                              void* d_out, int out_size)
{
    const float* x      = (const float*)d_in[0];
    const float* cosr   = (const float*)d_in[1];
    const float* sinr   = (const float*)d_in[2];
    const float* w_qkv  = (const float*)d_in[3];
    const float* q_ln_w = (const float*)d_in[4];
    const float* q_ln_b = (const float*)d_in[5];
    const float* k_ln_w = (const float*)d_in[6];
    const float* k_ln_b = (const float*)d_in[7];
    const float* w_proj = (const float*)d_in[8];
    const float* b_proj = (const float*)d_in[9];
    const int*   pP     = (const int*)d_in[10];
    const int*   pL     = (const int*)d_in[11];
    float* out = (float*)d_out;

    __half *xh, *wqh, *wph, *qh, *kh, *vh, *oh;
    cudaGetSymbolAddress((void**)&xh,  g_xh);
    cudaGetSymbolAddress((void**)&wqh, g_wqh);
    cudaGetSymbolAddress((void**)&wph, g_wph);
    cudaGetSymbolAddress((void**)&qh,  g_qh);
    cudaGetSymbolAddress((void**)&kh,  g_kh);
    cudaGetSymbolAddress((void**)&vh,  g_vh);
    cudaGetSymbolAddress((void**)&oh,  g_oh);

    cudaFuncSetAttribute(gemm_mma<false>, cudaFuncAttributeMaxDynamicSharedMemorySize, GEMM_SMEM);
    cudaFuncSetAttribute(gemm_mma<true>,  cudaFuncAttributeMaxDynamicSharedMemorySize, GEMM_SMEM);
    cudaFuncSetAttribute(attn_mma, cudaFuncAttributeMaxDynamicSharedMemorySize, ATT_SMEM);

    // 0) weight transpose+round, input round
    wround_t<<<dim3(C_/32, QKV_/32), 256>>>(w_qkv, wqh, C_, QKV_);
    wround_t<<<dim3(C_/32, C_/32),   256>>>(w_proj, wph, C_, C_);
    around<<<(M_*C_/4)/256, 256>>>((const float4*)x, xh);

    // 1) QKV projection with fused LN+RoPE epilogue -> fp16 Q/K/V
    gemm_mma<true><<<dim3(QKV_/128, M_/128), 256, GEMM_SMEM>>>(
        xh, wqh, nullptr, M_, QKV_, C_, nullptr,
        cosr, sinr, q_ln_w, q_ln_b, k_ln_w, k_ln_b, pP, pL,
        qh, kh, vh);

    // 2) attention -> fp16 [B,N,C]
    attn_mma<<<dim3(N_/128, H_, B_), 256, ATT_SMEM>>>(qh, kh, vh, oh);

    // 3) output projection + bias
    gemm_mma<false><<<dim3(C_/128, M_/128), 256, GEMM_SMEM>>>(
        oh, wph, out, M_, C_, C_, b_proj,
        nullptr, nullptr, nullptr, nullptr, nullptr, nullptr, nullptr, nullptr,
        nullptr, nullptr, nullptr);
}

// round 11
// speedup vs baseline: 6.7794x; 1.0177x over previous
#include <cuda_runtime.h>
#include <cuda_fp16.h>
#include <cstdint>

// Problem constants (fixed by setup_inputs)
#define B_   16
#define N_   1024
#define C_   768
#define H_   12
#define D_   64
#define M_   (B_*N_)     // 16384
#define QKV_ (3*C_)      // 2304

// ---------------- scratch (device globals: allocation-free) ----------------
__device__ __align__(16) __half g_xh[M_*C_];
__device__ __align__(16) __half g_wqh[QKV_*C_];        // [N,K] rounded
__device__ __align__(16) __half g_wph[C_*C_];          // [N,K] rounded
__device__ __align__(16) __half g_qh[B_*H_*N_*D_];
__device__ __align__(16) __half g_kh[B_*H_*N_*D_];
__device__ __align__(16) __half g_vh[B_*H_*N_*D_];
__device__ __align__(16) __half g_oh[M_*C_];

// ================= low-level helpers =================
__device__ __forceinline__ uint32_t smem_u32(const void* p) {
    uint32_t a;
    asm("{ .reg .u64 t; cvta.to.shared.u64 t, %1; cvt.u32.u64 %0, t; }"
        : "=r"(a) : "l"(p));
    return a;
}
__device__ __forceinline__ uint32_t sw128(uint32_t off) {
    return off ^ ((off >> 3) & 0x70);
}
// swizzle base for a row-part R (multiple of 128): col bits get XORed in later
__device__ __forceinline__ uint32_t swbase(uint32_t R) {
    return R ^ ((R >> 3) & 0x70);
}
#define CP_A16(s, g) \
    asm volatile("cp.async.cg.shared.global [%0], [%1], 16;" :: "r"(s), "l"(g) : "memory")
#define CP_COMMIT() asm volatile("cp.async.commit_group;" ::: "memory")
#define CP_WAIT1()  asm volatile("cp.async.wait_group 1;" ::: "memory")
#define CP_WAIT0()  asm volatile("cp.async.wait_group 0;" ::: "memory")

#define LDSM4(r, addr) \
    asm volatile("ldmatrix.sync.aligned.m8n8.x4.shared.b16 {%0,%1,%2,%3}, [%4];" \
        : "=r"((r)[0]), "=r"((r)[1]), "=r"((r)[2]), "=r"((r)[3]) : "r"(addr))
#define LDSM4T(r, addr) \
    asm volatile("ldmatrix.sync.aligned.m8n8.x4.trans.shared.b16 {%0,%1,%2,%3}, [%4];" \
        : "=r"((r)[0]), "=r"((r)[1]), "=r"((r)[2]), "=r"((r)[3]) : "r"(addr))

__device__ __forceinline__ void mma16816(float* c, const uint32_t* a,
                                         uint32_t b0, uint32_t b1) {
    asm volatile(
        "mma.sync.aligned.m16n8k16.row.col.f32.f16.f16.f32 "
        "{%0,%1,%2,%3}, {%4,%5,%6,%7}, {%8,%9}, {%0,%1,%2,%3};"
        : "+f"(c[0]), "+f"(c[1]), "+f"(c[2]), "+f"(c[3])
        : "r"(a[0]), "r"(a[1]), "r"(a[2]), "r"(a[3]), "r"(b0), "r"(b1));
}
__device__ __forceinline__ uint32_t packhf(float a, float b) {
    __half2 h = __floats2half2_rn(a, b);
    return *reinterpret_cast<uint32_t*>(&h);
}

// ---------- packed f32x2 helpers (sm_100+ base ISA) ----------
typedef unsigned long long u64;
__device__ __forceinline__ u64 pk2(float a, float b) {
    u64 r;
    asm("mov.b64 %0, {%1,%2};" : "=l"(r) : "f"(a), "f"(b));
    return r;
}
__device__ __forceinline__ void upk2(u64 p, float& a, float& b) {
    asm("mov.b64 {%0,%1}, %2;" : "=f"(a), "=f"(b) : "l"(p));
}
#define ADD2(d, a, b) asm("add.rn.f32x2 %0, %1, %2;" : "=l"(d) : "l"(a), "l"(b))
#define MUL2(d, a, b) asm("mul.rn.f32x2 %0, %1, %2;" : "=l"(d) : "l"(a), "l"(b))
#define FMA2(d, a, b, c) \
    asm("fma.rn.f32x2 %0, %1, %2, %3;" : "=l"(d) : "l"(a), "l"(b), "l"(c))

// packed exp2; inputs <= 0, >= ~-126. Degree-4 poly, rel err ~4e-5.
struct ExpC {
    u64 M, NM, C4, C3, C2, C1, C0;
    __device__ __forceinline__ void init() {
        M  = pk2(12582912.0f, 12582912.0f);
        NM = pk2(-12582912.0f, -12582912.0f);
        C4 = pk2(9.6181291e-3f, 9.6181291e-3f);
        C3 = pk2(5.5504109e-2f, 5.5504109e-2f);
        C2 = pk2(2.4022651e-1f, 2.4022651e-1f);
        C1 = pk2(6.9314718e-1f, 6.9314718e-1f);
        C0 = pk2(1.0f, 1.0f);
    }
};
__device__ __forceinline__ u64 exp2x2(u64 x, const ExpC& C) {
    u64 z, t, f, p, sc;
    ADD2(z, x, C.M);
    ADD2(t, z, C.NM);
    t ^= 0x8000000080000000ull;
    ADD2(f, x, t);
    p = C.C4;
    FMA2(p, p, f, C.C3);
    FMA2(p, p, f, C.C2);
    FMA2(p, p, f, C.C1);
    FMA2(p, p, f, C.C0);
    uint32_t elo = (uint32_t)z, ehi = (uint32_t)(z >> 32);
    uint32_t slo = (elo << 23) + 0x3f800000u;
    uint32_t shi = (ehi << 23) + 0x3f800000u;
    asm("mov.b64 %0, {%1,%2};" : "=l"(sc) : "r"(slo), "r"(shi));
    MUL2(p, p, sc);
    return p;
}

// ================= prep kernels =================
__global__ __launch_bounds__(256)
void around(const float4* __restrict__ in, __half* __restrict__ h)
{
    const uint32_t i = blockIdx.x * 256 + threadIdx.x;
    float4 v = in[i];
    *(__half2*)(h + 4*(size_t)i)     = __floats2half2_rn(v.x, v.y);
    *(__half2*)(h + 4*(size_t)i + 2) = __floats2half2_rn(v.z, v.w);
}

__global__ __launch_bounds__(256)
void wround_t(const float* __restrict__ W, __half* __restrict__ Th, int K, int N)
{
    __shared__ float t[32][33];
    const int kk = blockIdx.x * 32, nn = blockIdx.y * 32;
    const int tx = threadIdx.x & 31, ty = threadIdx.x >> 5;
    #pragma unroll
    for (int i = ty; i < 32; i += 8)
        t[i][tx] = W[(size_t)(kk + i) * N + nn + tx];
    __syncthreads();
    #pragma unroll
    for (int i = ty; i < 32; i += 8)
        Th[(size_t)(nn + i) * K + kk + tx] = __float2half_rn(t[tx][i]);
}

// ================= fp16 HMMA GEMM, optional fused LN/RoPE epilogue =======
// KC=64, 3-stage pipeline, 32 KB/stage, 96 KB smem, 2 CTAs/SM.
#define GTILE 16384                 // 128 rows x 128 bytes
#define GSTAGE (2*GTILE)            // A,B = 32 KB
#define GEMM_SMEM (3*GSTAGE)        // 98304

template<bool FUSED>
__global__ __launch_bounds__(256, 2)
void gemm_mma(const __half* __restrict__ Ah, const __half* __restrict__ Bh,
              float* __restrict__ Cm, int Mdim, int Ndim, int Kdim,
              const float* __restrict__ bias,
              const float* __restrict__ cosr, const float* __restrict__ sinr,
              const float* __restrict__ qw, const float* __restrict__ qb,
              const float* __restrict__ kw, const float* __restrict__ kb,
              const int* __restrict__ pP, const int* __restrict__ pL,
              __half* __restrict__ Qh,
              __half* __restrict__ Kh, __half* __restrict__ Vh)
{
    extern __shared__ char smem[];
    const uint32_t sb = smem_u32(smem);
    const int tid = threadIdx.x;
    const int wid = tid >> 5, lane = tid & 31;
    const int m0 = blockIdx.y * 128, n0 = blockIdx.x * 128;
    const int wm = (wid & 3) * 32, wn = (wid >> 2) * 64;
    const int nchunks = Kdim / 64;   // 12

    // ---- hoisted loader addressing: thread covers (row0 + t*32, u) ----
    const int r0 = tid >> 3, u8 = tid & 7;
    const __half* pA = Ah + (size_t)(m0 + r0) * Kdim + u8 * 8;
    const __half* pB = Bh + (size_t)(n0 + r0) * Kdim + u8 * 8;
    const uint32_t d0 = sw128((uint32_t)(r0 * 128 + u8 * 16));
    const size_t rstr = (size_t)32 * Kdim;

    auto issue = [&](int c) {
        const uint32_t stg = sb + (uint32_t)(c % 3) * GSTAGE;
        const int k0 = c * 64;
        const __half* a = pA + k0;
        const __half* b = pB + k0;
        #pragma unroll
        for (int t = 0; t < 4; t++) {
            CP_A16(stg + d0 + t*4096,
                   (u64)__cvta_generic_to_global(a + t*rstr));
            CP_A16(stg + GTILE + d0 + t*4096,
                   (u64)__cvta_generic_to_global(b + t*rstr));
        }
    };

    // ---- hoisted LDSM swizzle bases (col bits XORed per k-step) ----
    uint32_t offA[2], offB[4];
    #pragma unroll
    for (int mt = 0; mt < 2; mt++)
        offA[mt] = swbase((uint32_t)((wm + mt*16 + (lane & 15)) * 128)) ^ (lane & 16);
    #pragma unroll
    for (int p = 0; p < 4; p++)
        offB[p] = swbase((uint32_t)((wn + p*16 + (lane & 7) + ((lane & 16) >> 1)) * 128))
                  ^ ((lane & 8) << 1);

    float acc[2][8][4];
    #pragma unroll
    for (int i = 0; i < 2; i++)
        #pragma unroll
        for (int j = 0; j < 8; j++)
            #pragma unroll
            for (int q = 0; q < 4; q++) acc[i][j][q] = 0.f;

    issue(0); CP_COMMIT();
    issue(1); CP_COMMIT();

    for (int c = 0; c < nchunks; c++) {
        if (c == nchunks - 1) { CP_WAIT0(); } else { CP_WAIT1(); }
        __syncthreads();
        if (c + 2 < nchunks) { issue(c + 2); CP_COMMIT(); }

        const uint32_t sAh = sb + (uint32_t)(c % 3) * GSTAGE;
        const uint32_t sBh = sAh + GTILE;

        #pragma unroll
        for (int ks = 0; ks < 4; ks++) {
            const uint32_t kx = (uint32_t)(ks << 5);
            uint32_t ah[2][4];
            #pragma unroll
            for (int mt = 0; mt < 2; mt++)
                LDSM4(ah[mt], sAh + (offA[mt] ^ kx));
            uint32_t bh[4][4];
            #pragma unroll
            for (int p = 0; p < 4; p++)
                LDSM4(bh[p], sBh + (offB[p] ^ kx));
            #pragma unroll
            for (int mt = 0; mt < 2; mt++)
                #pragma unroll
                for (int p = 0; p < 4; p++)
                    #pragma unroll
                    for (int h2 = 0; h2 < 2; h2++) {
                        int nt = 2*p + h2;
                        mma16816(acc[mt][nt], ah[mt], bh[p][2*h2], bh[p][2*h2+1]);
                    }
        }
    }

    if (!FUSED) {
        #pragma unroll
        for (int mt = 0; mt < 2; mt++)
            #pragma unroll
            for (int nt = 0; nt < 8; nt++) {
                int row = m0 + wm + mt*16 + (lane >> 2);
                int col = n0 + wn + nt*8 + 2*(lane & 3);
                float b0 = 0.f, b1 = 0.f;
                if (bias) { b0 = bias[col]; b1 = bias[col + 1]; }
                float2 v0 = make_float2(acc[mt][nt][0] + b0, acc[mt][nt][1] + b1);
                float2 v1 = make_float2(acc[mt][nt][2] + b0, acc[mt][nt][3] + b1);
                *(float2*)(Cm + (size_t)row * Ndim + col)       = v0;
                *(float2*)(Cm + (size_t)(row + 8) * Ndim + col) = v1;
            }
    } else {
        const int gcol = n0 + wn;
        const int kind = gcol / C_;             // 0=q, 1=k, 2=v
        const int head = (gcol % C_) / D_;
        const int Pp = __ldg(pP), Ll = __ldg(pL);
        const float* lw = (kind == 0) ? qw : kw;
        const float* lb = (kind == 0) ? qb : kb;
        const float QSC = 0.18033688011112042f; // (1/8)*log2(e)

        #pragma unroll
        for (int mt = 0; mt < 2; mt++) {
            const int m1 = m0 + wm + mt*16 + (lane >> 2);
            const int m2 = m1 + 8;
            const int b1i = m1 >> 10, n1 = m1 & (N_-1);
            const int b2i = m2 >> 10, n2 = m2 & (N_-1);
            const size_t o1 = (((size_t)(b1i*H_ + head))*N_ + n1) * D_;
            const size_t o2 = (((size_t)(b2i*H_ + head))*N_ + n2) * D_;

            if (kind == 2) {
                #pragma unroll
                for (int nt = 0; nt < 8; nt++) {
                    int col = nt*8 + 2*(lane & 3);
                    *(uint32_t*)(Vh + o1 + col) = packhf(acc[mt][nt][0], acc[mt][nt][1]);
                    *(uint32_t*)(Vh + o2 + col) = packhf(acc[mt][nt][2], acc[mt][nt][3]);
                }
            } else {
                float s1 = 0.f, s2 = 0.f;
                #pragma unroll
                for (int nt = 0; nt < 8; nt++) {
                    s1 += acc[mt][nt][0] + acc[mt][nt][1];
                    s2 += acc[mt][nt][2] + acc[mt][nt][3];
                }
                s1 += __shfl_xor_sync(~0u, s1, 1); s1 += __shfl_xor_sync(~0u, s1, 2);
                s2 += __shfl_xor_sync(~0u, s2, 1); s2 += __shfl_xor_sync(~0u, s2, 2);
                const float mu1 = s1 * (1.0f/64.0f), mu2 = s2 * (1.0f/64.0f);
                float v1 = 0.f, v2 = 0.f;
                #pragma unroll
                for (int nt = 0; nt < 8; nt++) {
                    float d0f = acc[mt][nt][0] - mu1, d1f = acc[mt][nt][1] - mu1;
                    float d2f = acc[mt][nt][2] - mu2, d3f = acc[mt][nt][3] - mu2;
                    v1 += d0f*d0f + d1f*d1f;
                    v2 += d2f*d2f + d3f*d3f;
                }
                v1 += __shfl_xor_sync(~0u, v1, 1); v1 += __shfl_xor_sync(~0u, v1, 2);
                v2 += __shfl_xor_sync(~0u, v2, 1); v2 += __shfl_xor_sync(~0u, v2, 2);
                const float iv1 = rsqrtf(v1*(1.0f/64.0f) + 1e-5f);
                const float iv2 = rsqrtf(v2*(1.0f/64.0f) + 1e-5f);
                const bool r1 = (n1 >= Pp) && (n1 < N_ - Ll);
                const bool r2 = (n2 >= Pp) && (n2 < N_ - Ll);

                #pragma unroll
                for (int nt = 0; nt < 8; nt++) {
                    const int col  = nt*8 + 2*(lane & 3);
                    const int colp = nt*4 + (lane & 3);
                    float2 w2 = *(const float2*)(lw + col);
                    float2 bb = *(const float2*)(lb + col);
                    float y0 = fmaf((acc[mt][nt][0]-mu1)*iv1, w2.x, bb.x);
                    float y1 = fmaf((acc[mt][nt][1]-mu1)*iv1, w2.y, bb.y);
                    float y2 = fmaf((acc[mt][nt][2]-mu2)*iv2, w2.x, bb.x);
                    float y3 = fmaf((acc[mt][nt][3]-mu2)*iv2, w2.y, bb.y);
                    if (r1) {
                        float rc = cosr[(n1-Pp)*32 + colp], rs = sinr[(n1-Pp)*32 + colp];
                        float t0 = y0*rc - y1*rs, t1 = y0*rs + y1*rc;
                        y0 = t0; y1 = t1;
                    }
                    if (r2) {
                        float rc = cosr[(n2-Pp)*32 + colp], rs = sinr[(n2-Pp)*32 + colp];
                        float t2 = y2*rc - y3*rs, t3 = y2*rs + y3*rc;
                        y2 = t2; y3 = t3;
                    }
                    if (kind == 0) {
                        y0 *= QSC; y1 *= QSC; y2 *= QSC; y3 *= QSC;
                        *(uint32_t*)(Qh + o1 + col) = packhf(y0, y1);
                        *(uint32_t*)(Qh + o2 + col) = packhf(y2, y3);
                    } else {
                        *(uint32_t*)(Kh + o1 + col) = packhf(y0, y1);
                        *(uint32_t*)(Kh + o2 + col) = packhf(y2, y3);
                    }
                }
            }
        }
    }
}

// ================= HMMA flash attention (fp16, packed softmax) =============
// KV chunk = 128 rows/stage (two 64-row sub-bodies), 3 stages, 96 KB, 2 CTA/SM.
#define KTILE2 16384                  // 128 rows x 128 bytes
#define ASTAGE (2*KTILE2)             // Kh,Vh = 32 KB
#define ATT_SMEM (3*ASTAGE)           // 98304

__global__ __launch_bounds__(256, 2)
void attn_mma(const __half* __restrict__ Qh,
              const __half* __restrict__ Kh, const __half* __restrict__ Vh,
              __half* __restrict__ Oh)
{
    extern __shared__ char smem[];
    const uint32_t sb = smem_u32(smem);
    const int tid = threadIdx.x;
    const int wid = tid >> 5, lane = tid & 31;
    const int b = blockIdx.z, h = blockIdx.y;
    const int q0 = blockIdx.x * 128;
    const size_t base = ((size_t)(b*H_ + h)) * N_;

    ExpC EC; EC.init();

    // ---- hoisted loader addressing ----
    const int r0 = tid >> 3, u8 = tid & 7;
    const uint32_t d0 = sw128((uint32_t)(r0 * 128 + u8 * 16));
    const __half* pK = Kh + (base + r0) * D_ + u8 * 8;
    const __half* pV = Vh + (base + r0) * D_ + u8 * 8;

    // ---- stage Q tile (16 KB, in stage-0 area) ----
    {
        const __half* pQ = Qh + (base + q0 + r0) * D_ + u8 * 8;
        #pragma unroll
        for (int t = 0; t < 4; t++) {
            uint4 v = *(const uint4*)(pQ + t * 32 * D_);
            *(uint4*)(smem + d0 + t*4096) = v;
        }
    }
    __syncthreads();

    uint32_t qh[4][4];
    {
        const uint32_t offQ = swbase((uint32_t)((wid*16 + (lane & 15)) * 128)) ^ (lane & 16);
        #pragma unroll
        for (int ks = 0; ks < 4; ks++)
            LDSM4(qh[ks], sb + (offQ ^ (uint32_t)(ks << 5)));
    }
    __syncthreads();   // Q reads done; smem reusable for KV stages

    // ---- hoisted LDSM swizzle bases ----
    uint32_t offK[4], offV[4];
    #pragma unroll
    for (int p = 0; p < 4; p++)
        offK[p] = swbase((uint32_t)((p*16 + (lane & 7) + ((lane & 16) >> 1)) * 128))
                  ^ ((lane & 8) << 1);
    #pragma unroll
    for (int ds = 0; ds < 4; ds++)
        offV[ds] = swbase((uint32_t)((ds*16 + (lane & 15)) * 128)) ^ (lane & 16);

    auto issue = [&](int kt) {
        const uint32_t stg = sb + (uint32_t)(kt % 3) * ASTAGE;
        const int koff = kt * 128 * D_;
        const __half* k = pK + koff;
        const __half* v = pV + koff;
        #pragma unroll
        for (int t = 0; t < 4; t++) {
            CP_A16(stg + d0 + t*4096,
                   (u64)__cvta_generic_to_global(k + t * 32 * D_));
            CP_A16(stg + KTILE2 + d0 + t*4096,
                   (u64)__cvta_generic_to_global(v + t * 32 * D_));
        }
    };

    float o[8][4];
    #pragma unroll
    for (int j = 0; j < 8; j++)
        #pragma unroll
        for (int q = 0; q < 4; q++) o[j][q] = 0.f;
    float mi[2] = {-3.0e38f, -3.0e38f};
    float li[2] = {0.f, 0.f};

    issue(0); CP_COMMIT();
    issue(1); CP_COMMIT();

    for (int kt = 0; kt < 8; kt++) {
        if (kt == 7) { CP_WAIT0(); } else { CP_WAIT1(); }
        __syncthreads();
        if (kt + 2 < 8) { issue(kt + 2); CP_COMMIT(); }

        const uint32_t stg = sb + (uint32_t)(kt % 3) * ASTAGE;

        #pragma unroll
        for (int sub = 0; sub < 2; sub++) {
            const uint32_t sKh = stg + (uint32_t)sub * 8192;
            const uint32_t sVh = stg + KTILE2 + (uint32_t)sub * 8192;

            // ---- S = Q K^T ----
            float s[8][4];
            #pragma unroll
            for (int j = 0; j < 8; j++)
                #pragma unroll
                for (int q = 0; q < 4; q++) s[j][q] = 0.f;

            #pragma unroll
            for (int ks = 0; ks < 4; ks++) {
                const uint32_t kx = (uint32_t)(ks << 5);
                uint32_t kh[4][4];
                #pragma unroll
                for (int p = 0; p < 4; p++)
                    LDSM4(kh[p], sKh + (offK[p] ^ kx));
                #pragma unroll
                for (int p = 0; p < 4; p++)
                    #pragma unroll
                    for (int h2 = 0; h2 < 2; h2++) {
                        int nt = 2*p + h2;
                        mma16816(s[nt], qh[ks], kh[p][2*h2], kh[p][2*h2+1]);
                    }
            }

            // ---- online softmax (exp2 domain, packed f32x2) ----
            {
                float mx0 = -3.0e38f, mx1 = -3.0e38f;
                #pragma unroll
                for (int nt = 0; nt < 8; nt++) {
                    mx0 = fmaxf(mx0, fmaxf(s[nt][0], s[nt][1]));
                    mx1 = fmaxf(mx1, fmaxf(s[nt][2], s[nt][3]));
                }
                mx0 = fmaxf(mx0, __shfl_xor_sync(~0u, mx0, 1));
                mx0 = fmaxf(mx0, __shfl_xor_sync(~0u, mx0, 2));
                mx1 = fmaxf(mx1, __shfl_xor_sync(~0u, mx1, 1));
                mx1 = fmaxf(mx1, __shfl_xor_sync(~0u, mx1, 2));
                const float mn0 = fmaxf(mi[0], mx0), mn1 = fmaxf(mi[1], mx1);
                const float dd0 = fmaxf(mi[0] - mn0, -120.f);
                const float dd1 = fmaxf(mi[1] - mn1, -120.f);
                float c0, c1;
                upk2(exp2x2(pk2(dd0, dd1), EC), c0, c1);
                mi[0] = mn0; mi[1] = mn1;

                const u64 nm0 = pk2(-mn0, -mn0), nm1 = pk2(-mn1, -mn1);
                u64 rs0 = 0ull, rs1 = 0ull;
                #pragma unroll
                for (int nt = 0; nt < 8; nt++) {
                    u64 x0, x1;
                    ADD2(x0, pk2(s[nt][0], s[nt][1]), nm0);
                    ADD2(x1, pk2(s[nt][2], s[nt][3]), nm1);
                    u64 e0 = exp2x2(x0, EC);
                    u64 e1 = exp2x2(x1, EC);
                    upk2(e0, s[nt][0], s[nt][1]);
                    upk2(e1, s[nt][2], s[nt][3]);
                    ADD2(rs0, rs0, e0);
                    ADD2(rs1, rs1, e1);
                }
                float ra, rb;
                upk2(rs0, ra, rb);
                float rsum0 = ra + rb;
                upk2(rs1, ra, rb);
                float rsum1 = ra + rb;
                rsum0 += __shfl_xor_sync(~0u, rsum0, 1);
                rsum0 += __shfl_xor_sync(~0u, rsum0, 2);
                rsum1 += __shfl_xor_sync(~0u, rsum1, 1);
                rsum1 += __shfl_xor_sync(~0u, rsum1, 2);
                li[0] = fmaf(li[0], c0, rsum0);
                li[1] = fmaf(li[1], c1, rsum1);

                const u64 cp0 = pk2(c0, c0), cp1 = pk2(c1, c1);
                #pragma unroll
                for (int dt = 0; dt < 8; dt++) {
                    u64 t0 = pk2(o[dt][0], o[dt][1]);
                    u64 t1 = pk2(o[dt][2], o[dt][3]);
                    MUL2(t0, t0, cp0);
                    MUL2(t1, t1, cp1);
                    upk2(t0, o[dt][0], o[dt][1]);
                    upk2(t1, o[dt][2], o[dt][3]);
                }
            }

            // ---- O += P V ----
            #pragma unroll
            for (int ds = 0; ds < 4; ds++) {
                uint32_t ph[4];
                #pragma unroll
                for (int half = 0; half < 2; half++) {
                    int nt = 2*ds + half;
                    ph[2*half]   = packhf(s[nt][0], s[nt][1]);
                    ph[2*half+1] = packhf(s[nt][2], s[nt][3]);
                }
                uint32_t vh[4][4];
                #pragma unroll
                for (int dj = 0; dj < 4; dj++)
                    LDSM4T(vh[dj], sVh + (offV[ds] ^ (uint32_t)(dj << 5)));
                #pragma unroll
                for (int dj = 0; dj < 4; dj++)
                    #pragma unroll
                    for (int h2 = 0; h2 < 2; h2++) {
                        int dt = 2*dj + h2;
                        mma16816(o[dt], ph, vh[dj][2*h2], vh[dj][2*h2+1]);
                    }
            }
        }
    }

    // ---- epilogue: normalize, round fp16, store [B,N,C] ----
    const float inv1 = 1.0f / li[0];
    const float inv2 = 1.0f / li[1];
    const int row1 = q0 + wid*16 + (lane >> 2);
    #pragma unroll
    for (int dt = 0; dt < 8; dt++) {
        int col = h*D_ + dt*8 + 2*(lane & 3);
        size_t i1 = (size_t)(b*N_ + row1) * C_ + col;
        size_t i2 = (size_t)(b*N_ + row1 + 8) * C_ + col;
        *(uint32_t*)(Oh + i1) = packhf(o[dt][0]*inv1, o[dt][1]*inv1);
        *(uint32_t*)(Oh + i2) = packhf(o[dt][2]*inv2, o[dt][3]*inv2);
    }
}

// ================= launch =================
extern "C" void kernel_launch(void* const* d_in, const int* in_sizes, int n_in,
                              void* d_out, int out_size)
{
    const float* x      = (const float*)d_in[0];
    const float* cosr   = (const float*)d_in[1];
    const float* sinr   = (const float*)d_in[2];
    const float* w_qkv  = (const float*)d_in[3];
    const float* q_ln_w = (const float*)d_in[4];
    const float* q_ln_b = (const float*)d_in[5];
    const float* k_ln_w = (const float*)d_in[6];
    const float* k_ln_b = (const float*)d_in[7];
    const float* w_proj = (const float*)d_in[8];
    const float* b_proj = (const float*)d_in[9];
    const int*   pP     = (const int*)d_in[10];
    const int*   pL     = (const int*)d_in[11];
    float* out = (float*)d_out;

    __half *xh, *wqh, *wph, *qh, *kh, *vh, *oh;
    cudaGetSymbolAddress((void**)&xh,  g_xh);
    cudaGetSymbolAddress((void**)&wqh, g_wqh);
    cudaGetSymbolAddress((void**)&wph, g_wph);
    cudaGetSymbolAddress((void**)&qh,  g_qh);
    cudaGetSymbolAddress((void**)&kh,  g_kh);
    cudaGetSymbolAddress((void**)&vh,  g_vh);
    cudaGetSymbolAddress((void**)&oh,  g_oh);

    cudaFuncSetAttribute(gemm_mma<false>, cudaFuncAttributeMaxDynamicSharedMemorySize, GEMM_SMEM);
    cudaFuncSetAttribute(gemm_mma<true>,  cudaFuncAttributeMaxDynamicSharedMemorySize, GEMM_SMEM);
    cudaFuncSetAttribute(attn_mma, cudaFuncAttributeMaxDynamicSharedMemorySize, ATT_SMEM);

    // 0) weight transpose+round, input round
    wround_t<<<dim3(C_/32, QKV_/32), 256>>>(w_qkv, wqh, C_, QKV_);
    wround_t<<<dim3(C_/32, C_/32),   256>>>(w_proj, wph, C_, C_);
    around<<<(M_*C_/4)/256, 256>>>((const float4*)x, xh);

    // 1) QKV projection with fused LN+RoPE epilogue -> fp16 Q/K/V
    gemm_mma<true><<<dim3(QKV_/128, M_/128), 256, GEMM_SMEM>>>(
        xh, wqh, nullptr, M_, QKV_, C_, nullptr,
        cosr, sinr, q_ln_w, q_ln_b, k_ln_w, k_ln_b, pP, pL,
        qh, kh, vh);

    // 2) attention -> fp16 [B,N,C]
    attn_mma<<<dim3(N_/128, H_, B_), 256, ATT_SMEM>>>(qh, kh, vh, oh);

    // 3) output projection + bias
    gemm_mma<false><<<dim3(C_/128, M_/128), 256, GEMM_SMEM>>>(
        oh, wph, out, M_, C_, C_, b_proj,
        nullptr, nullptr, nullptr, nullptr, nullptr, nullptr, nullptr, nullptr,
        nullptr, nullptr, nullptr);
}

// round 12
// speedup vs baseline: 6.8628x; 1.0123x over previous
#include <cuda_runtime.h>
#include <cuda_fp16.h>
#include <cstdint>

// Problem constants (fixed by setup_inputs)
#define B_   16
#define N_   1024
#define C_   768
#define H_   12
#define D_   64
#define M_   (B_*N_)     // 16384
#define QKV_ (3*C_)      // 2304

// ---------------- scratch (device globals: allocation-free) ----------------
__device__ __align__(16) __half g_xh[M_*C_];
__device__ __align__(16) __half g_wqh[QKV_*C_];        // [N,K] rounded
__device__ __align__(16) __half g_wph[C_*C_];          // [N,K] rounded
__device__ __align__(16) __half g_qh[B_*H_*N_*D_];
__device__ __align__(16) __half g_kh[B_*H_*N_*D_];
__device__ __align__(16) __half g_vh[B_*H_*N_*D_];
__device__ __align__(16) __half g_oh[M_*C_];

// ================= low-level helpers =================
__device__ __forceinline__ uint32_t smem_u32(const void* p) {
    uint32_t a;
    asm("{ .reg .u64 t; cvta.to.shared.u64 t, %1; cvt.u32.u64 %0, t; }"
        : "=r"(a) : "l"(p));
    return a;
}
__device__ __forceinline__ uint32_t sw128(uint32_t off) {
    return off ^ ((off >> 3) & 0x70);
}
__device__ __forceinline__ uint32_t swbase(uint32_t R) {
    return R ^ ((R >> 3) & 0x70);
}
#define CP_A16(s, g) \
    asm volatile("cp.async.cg.shared.global [%0], [%1], 16;" :: "r"(s), "l"(g) : "memory")
#define CP_COMMIT() asm volatile("cp.async.commit_group;" ::: "memory")
#define CP_WAIT1()  asm volatile("cp.async.wait_group 1;" ::: "memory")
#define CP_WAIT0()  asm volatile("cp.async.wait_group 0;" ::: "memory")

#define LDSM4(r, addr) \
    asm volatile("ldmatrix.sync.aligned.m8n8.x4.shared.b16 {%0,%1,%2,%3}, [%4];" \
        : "=r"((r)[0]), "=r"((r)[1]), "=r"((r)[2]), "=r"((r)[3]) : "r"(addr))
#define LDSM4T(r, addr) \
    asm volatile("ldmatrix.sync.aligned.m8n8.x4.trans.shared.b16 {%0,%1,%2,%3}, [%4];" \
        : "=r"((r)[0]), "=r"((r)[1]), "=r"((r)[2]), "=r"((r)[3]) : "r"(addr))

__device__ __forceinline__ void mma16816(float* c, const uint32_t* a,
                                         uint32_t b0, uint32_t b1) {
    asm volatile(
        "mma.sync.aligned.m16n8k16.row.col.f32.f16.f16.f32 "
        "{%0,%1,%2,%3}, {%4,%5,%6,%7}, {%8,%9}, {%0,%1,%2,%3};"
        : "+f"(c[0]), "+f"(c[1]), "+f"(c[2]), "+f"(c[3])
        : "r"(a[0]), "r"(a[1]), "r"(a[2]), "r"(a[3]), "r"(b0), "r"(b1));
}
__device__ __forceinline__ uint32_t packhf(float a, float b) {
    __half2 h = __floats2half2_rn(a, b);
    return *reinterpret_cast<uint32_t*>(&h);
}

// ---------- packed f32x2 helpers (sm_100+ base ISA) ----------
typedef unsigned long long u64;
__device__ __forceinline__ u64 pk2(float a, float b) {
    u64 r;
    asm("mov.b64 %0, {%1,%2};" : "=l"(r) : "f"(a), "f"(b));
    return r;
}
__device__ __forceinline__ void upk2(u64 p, float& a, float& b) {
    asm("mov.b64 {%0,%1}, %2;" : "=f"(a), "=f"(b) : "l"(p));
}
#define ADD2(d, a, b) asm("add.rn.f32x2 %0, %1, %2;" : "=l"(d) : "l"(a), "l"(b))
#define MUL2(d, a, b) asm("mul.rn.f32x2 %0, %1, %2;" : "=l"(d) : "l"(a), "l"(b))
#define FMA2(d, a, b, c) \
    asm("fma.rn.f32x2 %0, %1, %2, %3;" : "=l"(d) : "l"(a), "l"(b), "l"(c))

// packed exp2; inputs <= 0, >= ~-126. Degree-4 poly, rel err ~4e-5.
struct ExpC {
    u64 M, NM, C4, C3, C2, C1, C0;
    __device__ __forceinline__ void init() {
        M  = pk2(12582912.0f, 12582912.0f);
        NM = pk2(-12582912.0f, -12582912.0f);
        C4 = pk2(9.6181291e-3f, 9.6181291e-3f);
        C3 = pk2(5.5504109e-2f, 5.5504109e-2f);
        C2 = pk2(2.4022651e-1f, 2.4022651e-1f);
        C1 = pk2(6.9314718e-1f, 6.9314718e-1f);
        C0 = pk2(1.0f, 1.0f);
    }
};
__device__ __forceinline__ u64 exp2x2(u64 x, const ExpC& C) {
    u64 z, t, f, p, sc;
    ADD2(z, x, C.M);
    ADD2(t, z, C.NM);
    t ^= 0x8000000080000000ull;
    ADD2(f, x, t);
    p = C.C4;
    FMA2(p, p, f, C.C3);
    FMA2(p, p, f, C.C2);
    FMA2(p, p, f, C.C1);
    FMA2(p, p, f, C.C0);
    uint32_t elo = (uint32_t)z, ehi = (uint32_t)(z >> 32);
    uint32_t slo = (elo << 23) + 0x3f800000u;
    uint32_t shi = (ehi << 23) + 0x3f800000u;
    asm("mov.b64 %0, {%1,%2};" : "=l"(sc) : "r"(slo), "r"(shi));
    MUL2(p, p, sc);
    return p;
}

// ================= fused prep kernel =================
// blocks [0, XBLK)              : x fp32 -> fp16 round
// blocks [XBLK, XBLK+1728)      : w_qkv transpose+round  (24 x 72 tiles)
// blocks [XBLK+1728, XBLK+2304) : w_proj transpose+round (24 x 24 tiles)
#define XBLK (M_*C_/4/256)       // 12288

__global__ __launch_bounds__(256)
void prep_all(const float4* __restrict__ x, __half* __restrict__ xh,
              const float* __restrict__ wq, __half* __restrict__ wqh,
              const float* __restrict__ wp, __half* __restrict__ wph)
{
    __shared__ float t[32][33];
    const int bx = blockIdx.x;
    if (bx < XBLK) {
        const uint32_t i = bx * 256 + threadIdx.x;
        float4 v = x[i];
        *(__half2*)(xh + 4*(size_t)i)     = __floats2half2_rn(v.x, v.y);
        *(__half2*)(xh + 4*(size_t)i + 2) = __floats2half2_rn(v.z, v.w);
        return;
    }
    const float* W;
    __half* Th;
    int idx, Ndim;
    if (bx < XBLK + 1728) {
        idx = bx - XBLK; W = wq; Th = wqh; Ndim = QKV_;
    } else {
        idx = bx - XBLK - 1728; W = wp; Th = wph; Ndim = C_;
    }
    const int kk = (idx % 24) * 32, nn = (idx / 24) * 32;
    const int tx = threadIdx.x & 31, ty = threadIdx.x >> 5;
    #pragma unroll
    for (int i = ty; i < 32; i += 8)
        t[i][tx] = W[(size_t)(kk + i) * Ndim + nn + tx];
    __syncthreads();
    #pragma unroll
    for (int i = ty; i < 32; i += 8)
        Th[(size_t)(nn + i) * C_ + kk + tx] = __float2half_rn(t[tx][i]);
}

// ================= fp16 HMMA GEMM, optional fused LN/RoPE epilogue =======
// KC=64, 3-stage pipeline, 32 KB/stage, 96 KB smem, 2 CTAs/SM.
#define GTILE 16384                 // 128 rows x 128 bytes
#define GSTAGE (2*GTILE)            // A,B = 32 KB
#define GEMM_SMEM (3*GSTAGE)        // 98304

template<bool FUSED>
__global__ __launch_bounds__(256, 2)
void gemm_mma(const __half* __restrict__ Ah, const __half* __restrict__ Bh,
              float* __restrict__ Cm, int Mdim, int Ndim, int Kdim,
              const float* __restrict__ bias,
              const float* __restrict__ cosr, const float* __restrict__ sinr,
              const float* __restrict__ qw, const float* __restrict__ qb,
              const float* __restrict__ kw, const float* __restrict__ kb,
              const int* __restrict__ pP, const int* __restrict__ pL,
              __half* __restrict__ Qh,
              __half* __restrict__ Kh, __half* __restrict__ Vh)
{
    extern __shared__ char smem[];
    const uint32_t sb = smem_u32(smem);
    const int tid = threadIdx.x;
    const int wid = tid >> 5, lane = tid & 31;
    const int m0 = blockIdx.y * 128, n0 = blockIdx.x * 128;
    const int wm = (wid & 3) * 32, wn = (wid >> 2) * 64;
    const int nchunks = Kdim / 64;   // 12

    const int r0 = tid >> 3, u8 = tid & 7;
    const __half* pA = Ah + (size_t)(m0 + r0) * Kdim + u8 * 8;
    const __half* pB = Bh + (size_t)(n0 + r0) * Kdim + u8 * 8;
    const uint32_t d0 = sw128((uint32_t)(r0 * 128 + u8 * 16));
    const size_t rstr = (size_t)32 * Kdim;

    auto issue = [&](int c) {
        const uint32_t stg = sb + (uint32_t)(c % 3) * GSTAGE;
        const int k0 = c * 64;
        const __half* a = pA + k0;
        const __half* b = pB + k0;
        #pragma unroll
        for (int t = 0; t < 4; t++) {
            CP_A16(stg + d0 + t*4096,
                   (u64)__cvta_generic_to_global(a + t*rstr));
            CP_A16(stg + GTILE + d0 + t*4096,
                   (u64)__cvta_generic_to_global(b + t*rstr));
        }
    };

    uint32_t offA[2], offB[4];
    #pragma unroll
    for (int mt = 0; mt < 2; mt++)
        offA[mt] = swbase((uint32_t)((wm + mt*16 + (lane & 15)) * 128)) ^ (lane & 16);
    #pragma unroll
    for (int p = 0; p < 4; p++)
        offB[p] = swbase((uint32_t)((wn + p*16 + (lane & 7) + ((lane & 16) >> 1)) * 128))
                  ^ ((lane & 8) << 1);

    float acc[2][8][4];
    #pragma unroll
    for (int i = 0; i < 2; i++)
        #pragma unroll
        for (int j = 0; j < 8; j++)
            #pragma unroll
            for (int q = 0; q < 4; q++) acc[i][j][q] = 0.f;

    issue(0); CP_COMMIT();
    issue(1); CP_COMMIT();

    for (int c = 0; c < nchunks; c++) {
        if (c == nchunks - 1) { CP_WAIT0(); } else { CP_WAIT1(); }
        __syncthreads();
        if (c + 2 < nchunks) { issue(c + 2); CP_COMMIT(); }

        const uint32_t sAh = sb + (uint32_t)(c % 3) * GSTAGE;
        const uint32_t sBh = sAh + GTILE;

        #pragma unroll
        for (int ks = 0; ks < 4; ks++) {
            const uint32_t kx = (uint32_t)(ks << 5);
            uint32_t ah[2][4];
            #pragma unroll
            for (int mt = 0; mt < 2; mt++)
                LDSM4(ah[mt], sAh + (offA[mt] ^ kx));
            uint32_t bh[4][4];
            #pragma unroll
            for (int p = 0; p < 4; p++)
                LDSM4(bh[p], sBh + (offB[p] ^ kx));
            #pragma unroll
            for (int mt = 0; mt < 2; mt++)
                #pragma unroll
                for (int p = 0; p < 4; p++)
                    #pragma unroll
                    for (int h2 = 0; h2 < 2; h2++) {
                        int nt = 2*p + h2;
                        mma16816(acc[mt][nt], ah[mt], bh[p][2*h2], bh[p][2*h2+1]);
                    }
        }
    }

    if (!FUSED) {
        #pragma unroll
        for (int mt = 0; mt < 2; mt++)
            #pragma unroll
            for (int nt = 0; nt < 8; nt++) {
                int row = m0 + wm + mt*16 + (lane >> 2);
                int col = n0 + wn + nt*8 + 2*(lane & 3);
                float b0 = 0.f, b1 = 0.f;
                if (bias) { b0 = bias[col]; b1 = bias[col + 1]; }
                float2 v0 = make_float2(acc[mt][nt][0] + b0, acc[mt][nt][1] + b1);
                float2 v1 = make_float2(acc[mt][nt][2] + b0, acc[mt][nt][3] + b1);
                *(float2*)(Cm + (size_t)row * Ndim + col)       = v0;
                *(float2*)(Cm + (size_t)(row + 8) * Ndim + col) = v1;
            }
    } else {
        const int gcol = n0 + wn;
        const int kind = gcol / C_;             // 0=q, 1=k, 2=v
        const int head = (gcol % C_) / D_;
        const int Pp = __ldg(pP), Ll = __ldg(pL);
        const float* lw = (kind == 0) ? qw : kw;
        const float* lb = (kind == 0) ? qb : kb;
        const float QSC = 0.18033688011112042f; // (1/8)*log2(e)

        #pragma unroll
        for (int mt = 0; mt < 2; mt++) {
            const int m1 = m0 + wm + mt*16 + (lane >> 2);
            const int m2 = m1 + 8;
            const int b1i = m1 >> 10, n1 = m1 & (N_-1);
            const int b2i = m2 >> 10, n2 = m2 & (N_-1);
            const size_t o1 = (((size_t)(b1i*H_ + head))*N_ + n1) * D_;
            const size_t o2 = (((size_t)(b2i*H_ + head))*N_ + n2) * D_;

            if (kind == 2) {
                #pragma unroll
                for (int nt = 0; nt < 8; nt++) {
                    int col = nt*8 + 2*(lane & 3);
                    *(uint32_t*)(Vh + o1 + col) = packhf(acc[mt][nt][0], acc[mt][nt][1]);
                    *(uint32_t*)(Vh + o2 + col) = packhf(acc[mt][nt][2], acc[mt][nt][3]);
                }
            } else {
                float s1 = 0.f, s2 = 0.f;
                #pragma unroll
                for (int nt = 0; nt < 8; nt++) {
                    s1 += acc[mt][nt][0] + acc[mt][nt][1];
                    s2 += acc[mt][nt][2] + acc[mt][nt][3];
                }
                s1 += __shfl_xor_sync(~0u, s1, 1); s1 += __shfl_xor_sync(~0u, s1, 2);
                s2 += __shfl_xor_sync(~0u, s2, 1); s2 += __shfl_xor_sync(~0u, s2, 2);
                const float mu1 = s1 * (1.0f/64.0f), mu2 = s2 * (1.0f/64.0f);
                float v1 = 0.f, v2 = 0.f;
                #pragma unroll
                for (int nt = 0; nt < 8; nt++) {
                    float d0f = acc[mt][nt][0] - mu1, d1f = acc[mt][nt][1] - mu1;
                    float d2f = acc[mt][nt][2] - mu2, d3f = acc[mt][nt][3] - mu2;
                    v1 += d0f*d0f + d1f*d1f;
                    v2 += d2f*d2f + d3f*d3f;
                }
                v1 += __shfl_xor_sync(~0u, v1, 1); v1 += __shfl_xor_sync(~0u, v1, 2);
                v2 += __shfl_xor_sync(~0u, v2, 1); v2 += __shfl_xor_sync(~0u, v2, 2);
                const float iv1 = rsqrtf(v1*(1.0f/64.0f) + 1e-5f);
                const float iv2 = rsqrtf(v2*(1.0f/64.0f) + 1e-5f);
                const bool r1 = (n1 >= Pp) && (n1 < N_ - Ll);
                const bool r2 = (n2 >= Pp) && (n2 < N_ - Ll);

                #pragma unroll
                for (int nt = 0; nt < 8; nt++) {
                    const int col  = nt*8 + 2*(lane & 3);
                    const int colp = nt*4 + (lane & 3);
                    float2 w2 = *(const float2*)(lw + col);
                    float2 bb = *(const float2*)(lb + col);
                    float y0 = fmaf((acc[mt][nt][0]-mu1)*iv1, w2.x, bb.x);
                    float y1 = fmaf((acc[mt][nt][1]-mu1)*iv1, w2.y, bb.y);
                    float y2 = fmaf((acc[mt][nt][2]-mu2)*iv2, w2.x, bb.x);
                    float y3 = fmaf((acc[mt][nt][3]-mu2)*iv2, w2.y, bb.y);
                    if (r1) {
                        float rc = cosr[(n1-Pp)*32 + colp], rs = sinr[(n1-Pp)*32 + colp];
                        float t0 = y0*rc - y1*rs, t1 = y0*rs + y1*rc;
                        y0 = t0; y1 = t1;
                    }
                    if (r2) {
                        float rc = cosr[(n2-Pp)*32 + colp], rs = sinr[(n2-Pp)*32 + colp];
                        float t2 = y2*rc - y3*rs, t3 = y2*rs + y3*rc;
                        y2 = t2; y3 = t3;
                    }
                    if (kind == 0) {
                        y0 *= QSC; y1 *= QSC; y2 *= QSC; y3 *= QSC;
                        *(uint32_t*)(Qh + o1 + col) = packhf(y0, y1);
                        *(uint32_t*)(Qh + o2 + col) = packhf(y2, y3);
                    } else {
                        *(uint32_t*)(Kh + o1 + col) = packhf(y0, y1);
                        *(uint32_t*)(Kh + o2 + col) = packhf(y2, y3);
                    }
                }
            }
        }
    }
}

// ================= HMMA flash attention (fp16, packed softmax) =============
// KV chunk = 128 rows/stage (two 64-row sub-bodies), 3 stages, 96 KB, 2 CTA/SM.
// V fragments prefetched across the softmax phase and pipelined in the PV loop.
#define KTILE2 16384                  // 128 rows x 128 bytes
#define ASTAGE (2*KTILE2)             // Kh,Vh = 32 KB
#define ATT_SMEM (3*ASTAGE)           // 98304

__global__ __launch_bounds__(256, 2)
void attn_mma(const __half* __restrict__ Qh,
              const __half* __restrict__ Kh, const __half* __restrict__ Vh,
              __half* __restrict__ Oh)
{
    extern __shared__ char smem[];
    const uint32_t sb = smem_u32(smem);
    const int tid = threadIdx.x;
    const int wid = tid >> 5, lane = tid & 31;
    const int b = blockIdx.z, h = blockIdx.y;
    const int q0 = blockIdx.x * 128;
    const size_t base = ((size_t)(b*H_ + h)) * N_;

    ExpC EC; EC.init();

    const int r0 = tid >> 3, u8 = tid & 7;
    const uint32_t d0 = sw128((uint32_t)(r0 * 128 + u8 * 16));
    const __half* pK = Kh + (base + r0) * D_ + u8 * 8;
    const __half* pV = Vh + (base + r0) * D_ + u8 * 8;

    // ---- stage Q tile (16 KB, in stage-0 area) ----
    {
        const __half* pQ = Qh + (base + q0 + r0) * D_ + u8 * 8;
        #pragma unroll
        for (int t = 0; t < 4; t++) {
            uint4 v = *(const uint4*)(pQ + t * 32 * D_);
            *(uint4*)(smem + d0 + t*4096) = v;
        }
    }
    __syncthreads();

    uint32_t qh[4][4];
    {
        const uint32_t offQ = swbase((uint32_t)((wid*16 + (lane & 15)) * 128)) ^ (lane & 16);
        #pragma unroll
        for (int ks = 0; ks < 4; ks++)
            LDSM4(qh[ks], sb + (offQ ^ (uint32_t)(ks << 5)));
    }
    __syncthreads();   // Q reads done; smem reusable for KV stages

    uint32_t offK[4], offV[4];
    #pragma unroll
    for (int p = 0; p < 4; p++)
        offK[p] = swbase((uint32_t)((p*16 + (lane & 7) + ((lane & 16) >> 1)) * 128))
                  ^ ((lane & 8) << 1);
    #pragma unroll
    for (int ds = 0; ds < 4; ds++)
        offV[ds] = swbase((uint32_t)((ds*16 + (lane & 15)) * 128)) ^ (lane & 16);

    auto issue = [&](int kt) {
        const uint32_t stg = sb + (uint32_t)(kt % 3) * ASTAGE;
        const int koff = kt * 128 * D_;
        const __half* k = pK + koff;
        const __half* v = pV + koff;
        #pragma unroll
        for (int t = 0; t < 4; t++) {
            CP_A16(stg + d0 + t*4096,
                   (u64)__cvta_generic_to_global(k + t * 32 * D_));
            CP_A16(stg + KTILE2 + d0 + t*4096,
                   (u64)__cvta_generic_to_global(v + t * 32 * D_));
        }
    };

    float o[8][4];
    #pragma unroll
    for (int j = 0; j < 8; j++)
        #pragma unroll
        for (int q = 0; q < 4; q++) o[j][q] = 0.f;
    float mi[2] = {-3.0e38f, -3.0e38f};
    float li[2] = {0.f, 0.f};

    issue(0); CP_COMMIT();
    issue(1); CP_COMMIT();

    for (int kt = 0; kt < 8; kt++) {
        if (kt == 7) { CP_WAIT0(); } else { CP_WAIT1(); }
        __syncthreads();
        if (kt + 2 < 8) { issue(kt + 2); CP_COMMIT(); }

        const uint32_t stg = sb + (uint32_t)(kt % 3) * ASTAGE;

        #pragma unroll
        for (int sub = 0; sub < 2; sub++) {
            const uint32_t sKh = stg + (uint32_t)sub * 8192;
            const uint32_t sVh = stg + KTILE2 + (uint32_t)sub * 8192;

            // ---- S = Q K^T ----
            float s[8][4];
            #pragma unroll
            for (int j = 0; j < 8; j++)
                #pragma unroll
                for (int q = 0; q < 4; q++) s[j][q] = 0.f;

            #pragma unroll
            for (int ks = 0; ks < 4; ks++) {
                const uint32_t kx = (uint32_t)(ks << 5);
                uint32_t kh[4][4];
                #pragma unroll
                for (int p = 0; p < 4; p++)
                    LDSM4(kh[p], sKh + (offK[p] ^ kx));
                #pragma unroll
                for (int p = 0; p < 4; p++)
                    #pragma unroll
                    for (int h2 = 0; h2 < 2; h2++) {
                        int nt = 2*p + h2;
                        mma16816(s[nt], qh[ks], kh[p][2*h2], kh[p][2*h2+1]);
                    }
            }

            // ---- prefetch V fragments for ds=0 (latency hidden by softmax) ----
            uint32_t vh[4][4];
            #pragma unroll
            for (int dj = 0; dj < 4; dj++)
                LDSM4T(vh[dj], sVh + (offV[0] ^ (uint32_t)(dj << 5)));

            // ---- online softmax (exp2 domain, packed f32x2) ----
            {
                float mx0 = -3.0e38f, mx1 = -3.0e38f;
                #pragma unroll
                for (int nt = 0; nt < 8; nt++) {
                    mx0 = fmaxf(mx0, fmaxf(s[nt][0], s[nt][1]));
                    mx1 = fmaxf(mx1, fmaxf(s[nt][2], s[nt][3]));
                }
                mx0 = fmaxf(mx0, __shfl_xor_sync(~0u, mx0, 1));
                mx0 = fmaxf(mx0, __shfl_xor_sync(~0u, mx0, 2));
                mx1 = fmaxf(mx1, __shfl_xor_sync(~0u, mx1, 1));
                mx1 = fmaxf(mx1, __shfl_xor_sync(~0u, mx1, 2));
                const float mn0 = fmaxf(mi[0], mx0), mn1 = fmaxf(mi[1], mx1);
                const float dd0 = fmaxf(mi[0] - mn0, -120.f);
                const float dd1 = fmaxf(mi[1] - mn1, -120.f);
                float c0, c1;
                upk2(exp2x2(pk2(dd0, dd1), EC), c0, c1);
                mi[0] = mn0; mi[1] = mn1;

                const u64 nm0 = pk2(-mn0, -mn0), nm1 = pk2(-mn1, -mn1);
                u64 rs0 = 0ull, rs1 = 0ull;
                #pragma unroll
                for (int nt = 0; nt < 8; nt++) {
                    u64 x0, x1;
                    ADD2(x0, pk2(s[nt][0], s[nt][1]), nm0);
                    ADD2(x1, pk2(s[nt][2], s[nt][3]), nm1);
                    u64 e0 = exp2x2(x0, EC);
                    u64 e1 = exp2x2(x1, EC);
                    upk2(e0, s[nt][0], s[nt][1]);
                    upk2(e1, s[nt][2], s[nt][3]);
                    ADD2(rs0, rs0, e0);
                    ADD2(rs1, rs1, e1);
                }
                float ra, rb;
                upk2(rs0, ra, rb);
                float rsum0 = ra + rb;
                upk2(rs1, ra, rb);
                float rsum1 = ra + rb;
                rsum0 += __shfl_xor_sync(~0u, rsum0, 1);
                rsum0 += __shfl_xor_sync(~0u, rsum0, 2);
                rsum1 += __shfl_xor_sync(~0u, rsum1, 1);
                rsum1 += __shfl_xor_sync(~0u, rsum1, 2);
                li[0] = fmaf(li[0], c0, rsum0);
                li[1] = fmaf(li[1], c1, rsum1);

                const u64 cp0 = pk2(c0, c0), cp1 = pk2(c1, c1);
                #pragma unroll
                for (int dt = 0; dt < 8; dt++) {
                    u64 t0 = pk2(o[dt][0], o[dt][1]);
                    u64 t1 = pk2(o[dt][2], o[dt][3]);
                    MUL2(t0, t0, cp0);
                    MUL2(t1, t1, cp1);
                    upk2(t0, o[dt][0], o[dt][1]);
                    upk2(t1, o[dt][2], o[dt][3]);
                }
            }

            // ---- O += P V (V fragments pipelined) ----
            #pragma unroll
            for (int ds = 0; ds < 4; ds++) {
                uint32_t ph[4];
                #pragma unroll
                for (int half = 0; half < 2; half++) {
                    int nt = 2*ds + half;
                    ph[2*half]   = packhf(s[nt][0], s[nt][1]);
                    ph[2*half+1] = packhf(s[nt][2], s[nt][3]);
                }
                uint32_t vhn[4][4];
                if (ds < 3) {
                    #pragma unroll
                    for (int dj = 0; dj < 4; dj++)
                        LDSM4T(vhn[dj], sVh + (offV[ds+1] ^ (uint32_t)(dj << 5)));
                }
                #pragma unroll
                for (int dj = 0; dj < 4; dj++)
                    #pragma unroll
                    for (int h2 = 0; h2 < 2; h2++) {
                        int dt = 2*dj + h2;
                        mma16816(o[dt], ph, vh[dj][2*h2], vh[dj][2*h2+1]);
                    }
                if (ds < 3) {
                    #pragma unroll
                    for (int dj = 0; dj < 4; dj++)
                        #pragma unroll
                        for (int q = 0; q < 4; q++)
                            vh[dj][q] = vhn[dj][q];
                }
            }
        }
    }

    // ---- epilogue: normalize, round fp16, store [B,N,C] ----
    const float inv1 = 1.0f / li[0];
    const float inv2 = 1.0f / li[1];
    const int row1 = q0 + wid*16 + (lane >> 2);
    #pragma unroll
    for (int dt = 0; dt < 8; dt++) {
        int col = h*D_ + dt*8 + 2*(lane & 3);
        size_t i1 = (size_t)(b*N_ + row1) * C_ + col;
        size_t i2 = (size_t)(b*N_ + row1 + 8) * C_ + col;
        *(uint32_t*)(Oh + i1) = packhf(o[dt][0]*inv1, o[dt][1]*inv1);
        *(uint32_t*)(Oh + i2) = packhf(o[dt][2]*inv2, o[dt][3]*inv2);
    }
}

// ================= launch =================
extern "C" void kernel_launch(void* const* d_in, const int* in_sizes, int n_in,
                              void* d_out, int out_size)
{
    const float* x      = (const float*)d_in[0];
    const float* cosr   = (const float*)d_in[1];
    const float* sinr   = (const float*)d_in[2];
    const float* w_qkv  = (const float*)d_in[3];
    const float* q_ln_w = (const float*)d_in[4];
    const float* q_ln_b = (const float*)d_in[5];
    const float* k_ln_w = (const float*)d_in[6];
    const float* k_ln_b = (const float*)d_in[7];
    const float* w_proj = (const float*)d_in[8];
    const float* b_proj = (const float*)d_in[9];
    const int*   pP     = (const int*)d_in[10];
    const int*   pL     = (const int*)d_in[11];
    float* out = (float*)d_out;

    __half *xh, *wqh, *wph, *qh, *kh, *vh, *oh;
    cudaGetSymbolAddress((void**)&xh,  g_xh);
    cudaGetSymbolAddress((void**)&wqh, g_wqh);
    cudaGetSymbolAddress((void**)&wph, g_wph);
    cudaGetSymbolAddress((void**)&qh,  g_qh);
    cudaGetSymbolAddress((void**)&kh,  g_kh);
    cudaGetSymbolAddress((void**)&vh,  g_vh);
    cudaGetSymbolAddress((void**)&oh,  g_oh);

    cudaFuncSetAttribute(gemm_mma<false>, cudaFuncAttributeMaxDynamicSharedMemorySize, GEMM_SMEM);
    cudaFuncSetAttribute(gemm_mma<true>,  cudaFuncAttributeMaxDynamicSharedMemorySize, GEMM_SMEM);
    cudaFuncSetAttribute(attn_mma, cudaFuncAttributeMaxDynamicSharedMemorySize, ATT_SMEM);

    // 0) fused prep: x round + both weight transposes
    prep_all<<<XBLK + 1728 + 576, 256>>>((const float4*)x, xh,
                                         w_qkv, wqh, w_proj, wph);

    // 1) QKV projection with fused LN+RoPE epilogue -> fp16 Q/K/V
    gemm_mma<true><<<dim3(QKV_/128, M_/128), 256, GEMM_SMEM>>>(
        xh, wqh, nullptr, M_, QKV_, C_, nullptr,
        cosr, sinr, q_ln_w, q_ln_b, k_ln_w, k_ln_b, pP, pL,
        qh, kh, vh);

    // 2) attention -> fp16 [B,N,C]
    attn_mma<<<dim3(N_/128, H_, B_), 256, ATT_SMEM>>>(qh, kh, vh, oh);

    // 3) output projection + bias
    gemm_mma<false><<<dim3(C_/128, M_/128), 256, GEMM_SMEM>>>(
        oh, wph, out, M_, C_, C_, b_proj,
        nullptr, nullptr, nullptr, nullptr, nullptr, nullptr, nullptr, nullptr,
        nullptr, nullptr, nullptr);
}

// round 13
// speedup vs baseline: 7.1617x; 1.0436x over previous
#include <cuda_runtime.h>
#include <cuda_fp16.h>
#include <cstdint>

// Problem constants (fixed by setup_inputs)
#define B_   16
#define N_   1024
#define C_   768
#define H_   12
#define D_   64
#define M_   (B_*N_)     // 16384
#define QKV_ (3*C_)      // 2304

// ---------------- scratch (device globals: allocation-free) ----------------
__device__ __align__(16) __half g_xh[M_*C_];
__device__ __align__(16) __half g_wqh[QKV_*C_];        // [N,K] rounded
__device__ __align__(16) __half g_wph[C_*C_];          // [N,K] rounded
__device__ __align__(16) __half g_qh[B_*H_*N_*D_];
__device__ __align__(16) __half g_kh[B_*H_*N_*D_];
__device__ __align__(16) __half g_vh[B_*H_*N_*D_];
__device__ __align__(16) __half g_oh[M_*C_];

// ================= low-level helpers =================
__device__ __forceinline__ uint32_t smem_u32(const void* p) {
    uint32_t a;
    asm("{ .reg .u64 t; cvta.to.shared.u64 t, %1; cvt.u32.u64 %0, t; }"
        : "=r"(a) : "l"(p));
    return a;
}
__device__ __forceinline__ uint32_t sw128(uint32_t off) {
    return off ^ ((off >> 3) & 0x70);
}
__device__ __forceinline__ uint32_t swbase(uint32_t R) {
    return R ^ ((R >> 3) & 0x70);
}
#define CP_A16(s, g) \
    asm volatile("cp.async.cg.shared.global [%0], [%1], 16;" :: "r"(s), "l"(g) : "memory")
#define CP_COMMIT() asm volatile("cp.async.commit_group;" ::: "memory")
#define CP_WAIT1()  asm volatile("cp.async.wait_group 1;" ::: "memory")
#define CP_WAIT0()  asm volatile("cp.async.wait_group 0;" ::: "memory")

#define LDSM4(r, addr) \
    asm volatile("ldmatrix.sync.aligned.m8n8.x4.shared.b16 {%0,%1,%2,%3}, [%4];" \
        : "=r"((r)[0]), "=r"((r)[1]), "=r"((r)[2]), "=r"((r)[3]) : "r"(addr))
#define LDSM4T(r, addr) \
    asm volatile("ldmatrix.sync.aligned.m8n8.x4.trans.shared.b16 {%0,%1,%2,%3}, [%4];" \
        : "=r"((r)[0]), "=r"((r)[1]), "=r"((r)[2]), "=r"((r)[3]) : "r"(addr))

__device__ __forceinline__ void mma16816(float* c, const uint32_t* a,
                                         uint32_t b0, uint32_t b1) {
    asm volatile(
        "mma.sync.aligned.m16n8k16.row.col.f32.f16.f16.f32 "
        "{%0,%1,%2,%3}, {%4,%5,%6,%7}, {%8,%9}, {%0,%1,%2,%3};"
        : "+f"(c[0]), "+f"(c[1]), "+f"(c[2]), "+f"(c[3])
        : "r"(a[0]), "r"(a[1]), "r"(a[2]), "r"(a[3]), "r"(b0), "r"(b1));
}
__device__ __forceinline__ uint32_t packhf(float a, float b) {
    __half2 h = __floats2half2_rn(a, b);
    return *reinterpret_cast<uint32_t*>(&h);
}

// ---------- packed f32x2 helpers (sm_100+ base ISA) ----------
typedef unsigned long long u64;
__device__ __forceinline__ u64 pk2(float a, float b) {
    u64 r;
    asm("mov.b64 %0, {%1,%2};" : "=l"(r) : "f"(a), "f"(b));
    return r;
}
__device__ __forceinline__ void upk2(u64 p, float& a, float& b) {
    asm("mov.b64 {%0,%1}, %2;" : "=f"(a), "=f"(b) : "l"(p));
}
#define ADD2(d, a, b) asm("add.rn.f32x2 %0, %1, %2;" : "=l"(d) : "l"(a), "l"(b))
#define MUL2(d, a, b) asm("mul.rn.f32x2 %0, %1, %2;" : "=l"(d) : "l"(a), "l"(b))
#define FMA2(d, a, b, c) \
    asm("fma.rn.f32x2 %0, %1, %2, %3;" : "=l"(d) : "l"(a), "l"(b), "l"(c))

// packed exp2; inputs <= 0, >= ~-126. Degree-4 poly, rel err ~4e-5.
struct ExpC {
    u64 M, NM, C4, C3, C2, C1, C0;
    __device__ __forceinline__ void init() {
        M  = pk2(12582912.0f, 12582912.0f);
        NM = pk2(-12582912.0f, -12582912.0f);
        C4 = pk2(9.6181291e-3f, 9.6181291e-3f);
        C3 = pk2(5.5504109e-2f, 5.5504109e-2f);
        C2 = pk2(2.4022651e-1f, 2.4022651e-1f);
        C1 = pk2(6.9314718e-1f, 6.9314718e-1f);
        C0 = pk2(1.0f, 1.0f);
    }
};
__device__ __forceinline__ u64 exp2x2(u64 x, const ExpC& C) {
    u64 z, t, f, p, sc;
    ADD2(z, x, C.M);
    ADD2(t, z, C.NM);
    t ^= 0x8000000080000000ull;
    ADD2(f, x, t);
    p = C.C4;
    FMA2(p, p, f, C.C3);
    FMA2(p, p, f, C.C2);
    FMA2(p, p, f, C.C1);
    FMA2(p, p, f, C.C0);
    uint32_t elo = (uint32_t)z, ehi = (uint32_t)(z >> 32);
    uint32_t slo = (elo << 23) + 0x3f800000u;
    uint32_t shi = (ehi << 23) + 0x3f800000u;
    asm("mov.b64 %0, {%1,%2};" : "=l"(sc) : "r"(slo), "r"(shi));
    MUL2(p, p, sc);
    return p;
}

// ================= fused prep kernel =================
#define XBLK (M_*C_/4/256)       // 12288

__global__ __launch_bounds__(256)
void prep_all(const float4* __restrict__ x, __half* __restrict__ xh,
              const float* __restrict__ wq, __half* __restrict__ wqh,
              const float* __restrict__ wp, __half* __restrict__ wph)
{
    __shared__ float t[32][33];
    const int bx = blockIdx.x;
    if (bx < XBLK) {
        const uint32_t i = bx * 256 + threadIdx.x;
        float4 v = x[i];
        *(__half2*)(xh + 4*(size_t)i)     = __floats2half2_rn(v.x, v.y);
        *(__half2*)(xh + 4*(size_t)i + 2) = __floats2half2_rn(v.z, v.w);
        return;
    }
    const float* W;
    __half* Th;
    int idx, Ndim;
    if (bx < XBLK + 1728) {
        idx = bx - XBLK; W = wq; Th = wqh; Ndim = QKV_;
    } else {
        idx = bx - XBLK - 1728; W = wp; Th = wph; Ndim = C_;
    }
    const int kk = (idx % 24) * 32, nn = (idx / 24) * 32;
    const int tx = threadIdx.x & 31, ty = threadIdx.x >> 5;
    #pragma unroll
    for (int i = ty; i < 32; i += 8)
        t[i][tx] = W[(size_t)(kk + i) * Ndim + nn + tx];
    __syncthreads();
    #pragma unroll
    for (int i = ty; i < 32; i += 8)
        Th[(size_t)(nn + i) * C_ + kk + tx] = __float2half_rn(t[tx][i]);
}

// ================= fp16 HMMA GEMM, optional fused LN/RoPE epilogue =======
#define GTILE 16384                 // 128 rows x 128 bytes
#define GSTAGE (2*GTILE)            // A,B = 32 KB
#define GEMM_SMEM (3*GSTAGE)        // 98304

template<bool FUSED>
__global__ __launch_bounds__(256, 2)
void gemm_mma(const __half* __restrict__ Ah, const __half* __restrict__ Bh,
              float* __restrict__ Cm, int Mdim, int Ndim, int Kdim,
              const float* __restrict__ bias,
              const float* __restrict__ cosr, const float* __restrict__ sinr,
              const float* __restrict__ qw, const float* __restrict__ qb,
              const float* __restrict__ kw, const float* __restrict__ kb,
              const int* __restrict__ pP, const int* __restrict__ pL,
              __half* __restrict__ Qh,
              __half* __restrict__ Kh, __half* __restrict__ Vh)
{
    extern __shared__ char smem[];
    const uint32_t sb = smem_u32(smem);
    const int tid = threadIdx.x;
    const int wid = tid >> 5, lane = tid & 31;
    const int m0 = blockIdx.y * 128, n0 = blockIdx.x * 128;
    const int wm = (wid & 3) * 32, wn = (wid >> 2) * 64;
    const int nchunks = Kdim / 64;   // 12

    const int r0 = tid >> 3, u8 = tid & 7;
    const __half* pA = Ah + (size_t)(m0 + r0) * Kdim + u8 * 8;
    const __half* pB = Bh + (size_t)(n0 + r0) * Kdim + u8 * 8;
    const uint32_t d0 = sw128((uint32_t)(r0 * 128 + u8 * 16));
    const size_t rstr = (size_t)32 * Kdim;

    auto issue = [&](int c) {
        const uint32_t stg = sb + (uint32_t)(c % 3) * GSTAGE;
        const int k0 = c * 64;
        const __half* a = pA + k0;
        const __half* b = pB + k0;
        #pragma unroll
        for (int t = 0; t < 4; t++) {
            CP_A16(stg + d0 + t*4096,
                   (u64)__cvta_generic_to_global(a + t*rstr));
            CP_A16(stg + GTILE + d0 + t*4096,
                   (u64)__cvta_generic_to_global(b + t*rstr));
        }
    };

    uint32_t offA[2], offB[4];
    #pragma unroll
    for (int mt = 0; mt < 2; mt++)
        offA[mt] = swbase((uint32_t)((wm + mt*16 + (lane & 15)) * 128)) ^ (lane & 16);
    #pragma unroll
    for (int p = 0; p < 4; p++)
        offB[p] = swbase((uint32_t)((wn + p*16 + (lane & 7) + ((lane & 16) >> 1)) * 128))
                  ^ ((lane & 8) << 1);

    float acc[2][8][4];
    #pragma unroll
    for (int i = 0; i < 2; i++)
        #pragma unroll
        for (int j = 0; j < 8; j++)
            #pragma unroll
            for (int q = 0; q < 4; q++) acc[i][j][q] = 0.f;

    issue(0); CP_COMMIT();
    issue(1); CP_COMMIT();

    for (int c = 0; c < nchunks; c++) {
        if (c == nchunks - 1) { CP_WAIT0(); } else { CP_WAIT1(); }
        __syncthreads();
        if (c + 2 < nchunks) { issue(c + 2); CP_COMMIT(); }

        const uint32_t sAh = sb + (uint32_t)(c % 3) * GSTAGE;
        const uint32_t sBh = sAh + GTILE;

        #pragma unroll
        for (int ks = 0; ks < 4; ks++) {
            const uint32_t kx = (uint32_t)(ks << 5);
            uint32_t ah[2][4];
            #pragma unroll
            for (int mt = 0; mt < 2; mt++)
                LDSM4(ah[mt], sAh + (offA[mt] ^ kx));
            uint32_t bh[4][4];
            #pragma unroll
            for (int p = 0; p < 4; p++)
                LDSM4(bh[p], sBh + (offB[p] ^ kx));
            #pragma unroll
            for (int mt = 0; mt < 2; mt++)
                #pragma unroll
                for (int p = 0; p < 4; p++)
                    #pragma unroll
                    for (int h2 = 0; h2 < 2; h2++) {
                        int nt = 2*p + h2;
                        mma16816(acc[mt][nt], ah[mt], bh[p][2*h2], bh[p][2*h2+1]);
                    }
        }
    }

    if (!FUSED) {
        #pragma unroll
        for (int mt = 0; mt < 2; mt++)
            #pragma unroll
            for (int nt = 0; nt < 8; nt++) {
                int row = m0 + wm + mt*16 + (lane >> 2);
                int col = n0 + wn + nt*8 + 2*(lane & 3);
                float b0 = 0.f, b1 = 0.f;
                if (bias) { b0 = bias[col]; b1 = bias[col + 1]; }
                float2 v0 = make_float2(acc[mt][nt][0] + b0, acc[mt][nt][1] + b1);
                float2 v1 = make_float2(acc[mt][nt][2] + b0, acc[mt][nt][3] + b1);
                *(float2*)(Cm + (size_t)row * Ndim + col)       = v0;
                *(float2*)(Cm + (size_t)(row + 8) * Ndim + col) = v1;
            }
    } else {
        const int gcol = n0 + wn;
        const int kind = gcol / C_;             // 0=q, 1=k, 2=v
        const int head = (gcol % C_) / D_;
        const int Pp = __ldg(pP), Ll = __ldg(pL);
        const float* lw = (kind == 0) ? qw : kw;
        const float* lb = (kind == 0) ? qb : kb;
        const float QSC = 0.18033688011112042f; // (1/8)*log2(e)

        #pragma unroll
        for (int mt = 0; mt < 2; mt++) {
            const int m1 = m0 + wm + mt*16 + (lane >> 2);
            const int m2 = m1 + 8;
            const int b1i = m1 >> 10, n1 = m1 & (N_-1);
            const int b2i = m2 >> 10, n2 = m2 & (N_-1);
            const size_t o1 = (((size_t)(b1i*H_ + head))*N_ + n1) * D_;
            const size_t o2 = (((size_t)(b2i*H_ + head))*N_ + n2) * D_;

            if (kind == 2) {
                #pragma unroll
                for (int nt = 0; nt < 8; nt++) {
                    int col = nt*8 + 2*(lane & 3);
                    *(uint32_t*)(Vh + o1 + col) = packhf(acc[mt][nt][0], acc[mt][nt][1]);
                    *(uint32_t*)(Vh + o2 + col) = packhf(acc[mt][nt][2], acc[mt][nt][3]);
                }
            } else {
                float s1 = 0.f, s2 = 0.f;
                #pragma unroll
                for (int nt = 0; nt < 8; nt++) {
                    s1 += acc[mt][nt][0] + acc[mt][nt][1];
                    s2 += acc[mt][nt][2] + acc[mt][nt][3];
                }
                s1 += __shfl_xor_sync(~0u, s1, 1); s1 += __shfl_xor_sync(~0u, s1, 2);
                s2 += __shfl_xor_sync(~0u, s2, 1); s2 += __shfl_xor_sync(~0u, s2, 2);
                const float mu1 = s1 * (1.0f/64.0f), mu2 = s2 * (1.0f/64.0f);
                float v1 = 0.f, v2 = 0.f;
                #pragma unroll
                for (int nt = 0; nt < 8; nt++) {
                    float d0f = acc[mt][nt][0] - mu1, d1f = acc[mt][nt][1] - mu1;
                    float d2f = acc[mt][nt][2] - mu2, d3f = acc[mt][nt][3] - mu2;
                    v1 += d0f*d0f + d1f*d1f;
                    v2 += d2f*d2f + d3f*d3f;
                }
                v1 += __shfl_xor_sync(~0u, v1, 1); v1 += __shfl_xor_sync(~0u, v1, 2);
                v2 += __shfl_xor_sync(~0u, v2, 1); v2 += __shfl_xor_sync(~0u, v2, 2);
                const float iv1 = rsqrtf(v1*(1.0f/64.0f) + 1e-5f);
                const float iv2 = rsqrtf(v2*(1.0f/64.0f) + 1e-5f);
                const bool r1 = (n1 >= Pp) && (n1 < N_ - Ll);
                const bool r2 = (n2 >= Pp) && (n2 < N_ - Ll);

                #pragma unroll
                for (int nt = 0; nt < 8; nt++) {
                    const int col  = nt*8 + 2*(lane & 3);
                    const int colp = nt*4 + (lane & 3);
                    float2 w2 = *(const float2*)(lw + col);
                    float2 bb = *(const float2*)(lb + col);
                    float y0 = fmaf((acc[mt][nt][0]-mu1)*iv1, w2.x, bb.x);
                    float y1 = fmaf((acc[mt][nt][1]-mu1)*iv1, w2.y, bb.y);
                    float y2 = fmaf((acc[mt][nt][2]-mu2)*iv2, w2.x, bb.x);
                    float y3 = fmaf((acc[mt][nt][3]-mu2)*iv2, w2.y, bb.y);
                    if (r1) {
                        float rc = cosr[(n1-Pp)*32 + colp], rs = sinr[(n1-Pp)*32 + colp];
                        float t0 = y0*rc - y1*rs, t1 = y0*rs + y1*rc;
                        y0 = t0; y1 = t1;
                    }
                    if (r2) {
                        float rc = cosr[(n2-Pp)*32 + colp], rs = sinr[(n2-Pp)*32 + colp];
                        float t2 = y2*rc - y3*rs, t3 = y2*rs + y3*rc;
                        y2 = t2; y3 = t3;
                    }
                    if (kind == 0) {
                        y0 *= QSC; y1 *= QSC; y2 *= QSC; y3 *= QSC;
                        *(uint32_t*)(Qh + o1 + col) = packhf(y0, y1);
                        *(uint32_t*)(Qh + o2 + col) = packhf(y2, y3);
                    } else {
                        *(uint32_t*)(Kh + o1 + col) = packhf(y0, y1);
                        *(uint32_t*)(Kh + o2 + col) = packhf(y2, y3);
                    }
                }
            }
        }
    }
}

// ================= HMMA flash attention (fixed-max softmax) =============
// |S_log2| <= ||q_scaled||*||k|| = 11.54 (Cauchy-Schwarz, LN gives unit rows)
// -> subtract constant 12.5; softmax shift-invariance makes this exact.
// No running max, no corr, no o-rescale; li reduced once at the end.
#define KTILE2 16384                  // 128 rows x 128 bytes
#define ASTAGE (2*KTILE2)             // Kh,Vh = 32 KB
#define ATT_SMEM (3*ASTAGE)           // 98304

__global__ __launch_bounds__(256, 2)
void attn_mma(const __half* __restrict__ Qh,
              const __half* __restrict__ Kh, const __half* __restrict__ Vh,
              __half* __restrict__ Oh)
{
    extern __shared__ char smem[];
    const uint32_t sb = smem_u32(smem);
    const int tid = threadIdx.x;
    const int wid = tid >> 5, lane = tid & 31;
    const int b = blockIdx.z, h = blockIdx.y;
    const int q0 = blockIdx.x * 128;
    const size_t base = ((size_t)(b*H_ + h)) * N_;

    ExpC EC; EC.init();
    const u64 FM = pk2(-12.5f, -12.5f);    // fixed softmax shift

    const int r0 = tid >> 3, u8 = tid & 7;
    const uint32_t d0 = sw128((uint32_t)(r0 * 128 + u8 * 16));
    const __half* pK = Kh + (base + r0) * D_ + u8 * 8;
    const __half* pV = Vh + (base + r0) * D_ + u8 * 8;

    // ---- stage Q tile (16 KB, in stage-0 area) ----
    {
        const __half* pQ = Qh + (base + q0 + r0) * D_ + u8 * 8;
        #pragma unroll
        for (int t = 0; t < 4; t++) {
            uint4 v = *(const uint4*)(pQ + t * 32 * D_);
            *(uint4*)(smem + d0 + t*4096) = v;
        }
    }
    __syncthreads();

    uint32_t qh[4][4];
    {
        const uint32_t offQ = swbase((uint32_t)((wid*16 + (lane & 15)) * 128)) ^ (lane & 16);
        #pragma unroll
        for (int ks = 0; ks < 4; ks++)
            LDSM4(qh[ks], sb + (offQ ^ (uint32_t)(ks << 5)));
    }
    __syncthreads();   // Q reads done; smem reusable for KV stages

    uint32_t offK[4], offV[4];
    #pragma unroll
    for (int p = 0; p < 4; p++)
        offK[p] = swbase((uint32_t)((p*16 + (lane & 7) + ((lane & 16) >> 1)) * 128))
                  ^ ((lane & 8) << 1);
    #pragma unroll
    for (int ds = 0; ds < 4; ds++)
        offV[ds] = swbase((uint32_t)((ds*16 + (lane & 15)) * 128)) ^ (lane & 16);

    auto issue = [&](int kt) {
        const uint32_t stg = sb + (uint32_t)(kt % 3) * ASTAGE;
        const int koff = kt * 128 * D_;
        const __half* k = pK + koff;
        const __half* v = pV + koff;
        #pragma unroll
        for (int t = 0; t < 4; t++) {
            CP_A16(stg + d0 + t*4096,
                   (u64)__cvta_generic_to_global(k + t * 32 * D_));
            CP_A16(stg + KTILE2 + d0 + t*4096,
                   (u64)__cvta_generic_to_global(v + t * 32 * D_));
        }
    };

    float o[8][4];
    #pragma unroll
    for (int j = 0; j < 8; j++)
        #pragma unroll
        for (int q = 0; q < 4; q++) o[j][q] = 0.f;
    u64 ls0 = 0ull, ls1 = 0ull;            // packed li accumulators

    issue(0); CP_COMMIT();
    issue(1); CP_COMMIT();

    for (int kt = 0; kt < 8; kt++) {
        if (kt == 7) { CP_WAIT0(); } else { CP_WAIT1(); }
        __syncthreads();
        if (kt + 2 < 8) { issue(kt + 2); CP_COMMIT(); }

        const uint32_t stg = sb + (uint32_t)(kt % 3) * ASTAGE;

        #pragma unroll
        for (int sub = 0; sub < 2; sub++) {
            const uint32_t sKh = stg + (uint32_t)sub * 8192;
            const uint32_t sVh = stg + KTILE2 + (uint32_t)sub * 8192;

            // ---- S = Q K^T ----
            float s[8][4];
            #pragma unroll
            for (int j = 0; j < 8; j++)
                #pragma unroll
                for (int q = 0; q < 4; q++) s[j][q] = 0.f;

            #pragma unroll
            for (int ks = 0; ks < 4; ks++) {
                const uint32_t kx = (uint32_t)(ks << 5);
                uint32_t kh[4][4];
                #pragma unroll
                for (int p = 0; p < 4; p++)
                    LDSM4(kh[p], sKh + (offK[p] ^ kx));
                #pragma unroll
                for (int p = 0; p < 4; p++)
                    #pragma unroll
                    for (int h2 = 0; h2 < 2; h2++) {
                        int nt = 2*p + h2;
                        mma16816(s[nt], qh[ks], kh[p][2*h2], kh[p][2*h2+1]);
                    }
            }

            // ---- prefetch V fragments for ds=0 (latency hidden by exp work) ----
            uint32_t vh[4][4];
            #pragma unroll
            for (int dj = 0; dj < 4; dj++)
                LDSM4T(vh[dj], sVh + (offV[0] ^ (uint32_t)(dj << 5)));

            // ---- fixed-max softmax: p = exp2(s - 12.5), accumulate li ----
            #pragma unroll
            for (int nt = 0; nt < 8; nt++) {
                u64 x0, x1;
                ADD2(x0, pk2(s[nt][0], s[nt][1]), FM);
                ADD2(x1, pk2(s[nt][2], s[nt][3]), FM);
                u64 e0 = exp2x2(x0, EC);
                u64 e1 = exp2x2(x1, EC);
                upk2(e0, s[nt][0], s[nt][1]);
                upk2(e1, s[nt][2], s[nt][3]);
                ADD2(ls0, ls0, e0);
                ADD2(ls1, ls1, e1);
            }

            // ---- O += P V (V fragments pipelined) ----
            #pragma unroll
            for (int ds = 0; ds < 4; ds++) {
                uint32_t ph[4];
                #pragma unroll
                for (int half = 0; half < 2; half++) {
                    int nt = 2*ds + half;
                    ph[2*half]   = packhf(s[nt][0], s[nt][1]);
                    ph[2*half+1] = packhf(s[nt][2], s[nt][3]);
                }
                uint32_t vhn[4][4];
                if (ds < 3) {
                    #pragma unroll
                    for (int dj = 0; dj < 4; dj++)
                        LDSM4T(vhn[dj], sVh + (offV[ds+1] ^ (uint32_t)(dj << 5)));
                }
                #pragma unroll
                for (int dj = 0; dj < 4; dj++)
                    #pragma unroll
                    for (int h2 = 0; h2 < 2; h2++) {
                        int dt = 2*dj + h2;
                        mma16816(o[dt], ph, vh[dj][2*h2], vh[dj][2*h2+1]);
                    }
                if (ds < 3) {
                    #pragma unroll
                    for (int dj = 0; dj < 4; dj++)
                        #pragma unroll
                        for (int q = 0; q < 4; q++)
                            vh[dj][q] = vhn[dj][q];
                }
            }
        }
    }

    // ---- reduce li once, normalize, round fp16, store [B,N,C] ----
    float la, lb2, li0, li1;
    upk2(ls0, la, lb2); li0 = la + lb2;
    upk2(ls1, la, lb2); li1 = la + lb2;
    li0 += __shfl_xor_sync(~0u, li0, 1);
    li0 += __shfl_xor_sync(~0u, li0, 2);
    li1 += __shfl_xor_sync(~0u, li1, 1);
    li1 += __shfl_xor_sync(~0u, li1, 2);
    const float inv1 = 1.0f / li0;
    const float inv2 = 1.0f / li1;
    const int row1 = q0 + wid*16 + (lane >> 2);
    #pragma unroll
    for (int dt = 0; dt < 8; dt++) {
        int col = h*D_ + dt*8 + 2*(lane & 3);
        size_t i1 = (size_t)(b*N_ + row1) * C_ + col;
        size_t i2 = (size_t)(b*N_ + row1 + 8) * C_ + col;
        *(uint32_t*)(Oh + i1) = packhf(o[dt][0]*inv1, o[dt][1]*inv1);
        *(uint32_t*)(Oh + i2) = packhf(o[dt][2]*inv2, o[dt][3]*inv2);
    }
}

// ================= launch =================
extern "C" void kernel_launch(void* const* d_in, const int* in_sizes, int n_in,
                              void* d_out, int out_size)
{
    const float* x      = (const float*)d_in[0];
    const float* cosr   = (const float*)d_in[1];
    const float* sinr   = (const float*)d_in[2];
    const float* w_qkv  = (const float*)d_in[3];
    const float* q_ln_w = (const float*)d_in[4];
    const float* q_ln_b = (const float*)d_in[5];
    const float* k_ln_w = (const float*)d_in[6];
    const float* k_ln_b = (const float*)d_in[7];
    const float* w_proj = (const float*)d_in[8];
    const float* b_proj = (const float*)d_in[9];
    const int*   pP     = (const int*)d_in[10];
    const int*   pL     = (const int*)d_in[11];
    float* out = (float*)d_out;

    __half *xh, *wqh, *wph, *qh, *kh, *vh, *oh;
    cudaGetSymbolAddress((void**)&xh,  g_xh);
    cudaGetSymbolAddress((void**)&wqh, g_wqh);
    cudaGetSymbolAddress((void**)&wph, g_wph);
    cudaGetSymbolAddress((void**)&qh,  g_qh);
    cudaGetSymbolAddress((void**)&kh,  g_kh);
    cudaGetSymbolAddress((void**)&vh,  g_vh);
    cudaGetSymbolAddress((void**)&oh,  g_oh);

    cudaFuncSetAttribute(gemm_mma<false>, cudaFuncAttributeMaxDynamicSharedMemorySize, GEMM_SMEM);
    cudaFuncSetAttribute(gemm_mma<true>,  cudaFuncAttributeMaxDynamicSharedMemorySize, GEMM_SMEM);
    cudaFuncSetAttribute(attn_mma, cudaFuncAttributeMaxDynamicSharedMemorySize, ATT_SMEM);

    // 0) fused prep: x round + both weight transposes
    prep_all<<<XBLK + 1728 + 576, 256>>>((const float4*)x, xh,
                                         w_qkv, wqh, w_proj, wph);

    // 1) QKV projection with fused LN+RoPE epilogue -> fp16 Q/K/V
    gemm_mma<true><<<dim3(QKV_/128, M_/128), 256, GEMM_SMEM>>>(
        xh, wqh, nullptr, M_, QKV_, C_, nullptr,
        cosr, sinr, q_ln_w, q_ln_b, k_ln_w, k_ln_b, pP, pL,
        qh, kh, vh);

    // 2) attention -> fp16 [B,N,C]
    attn_mma<<<dim3(N_/128, H_, B_), 256, ATT_SMEM>>>(qh, kh, vh, oh);

    // 3) output projection + bias
    gemm_mma<false><<<dim3(C_/128, M_/128), 256, GEMM_SMEM>>>(
        oh, wph, out, M_, C_, C_, b_proj,
        nullptr, nullptr, nullptr, nullptr, nullptr, nullptr, nullptr, nullptr,
        nullptr, nullptr, nullptr);
}

// round 14
// speedup vs baseline: 7.2105x; 1.0068x over previous
#include <cuda_runtime.h>
#include <cuda_fp16.h>
#include <cstdint>

// Problem constants (fixed by setup_inputs)
#define B_   16
#define N_   1024
#define C_   768
#define H_   12
#define D_   64
#define M_   (B_*N_)     // 16384
#define QKV_ (3*C_)      // 2304

// ---------------- scratch (device globals: allocation-free) ----------------
__device__ __align__(16) __half g_xh[M_*C_];
__device__ __align__(16) __half g_wqh[QKV_*C_];        // [N,K] rounded
__device__ __align__(16) __half g_wph[C_*C_];          // [N,K] rounded
__device__ __align__(16) __half g_qh[B_*H_*N_*D_];
__device__ __align__(16) __half g_kh[B_*H_*N_*D_];
__device__ __align__(16) __half g_vh[B_*H_*N_*D_];
__device__ __align__(16) __half g_oh[M_*C_];

// ================= low-level helpers =================
__device__ __forceinline__ uint32_t smem_u32(const void* p) {
    uint32_t a;
    asm("{ .reg .u64 t; cvta.to.shared.u64 t, %1; cvt.u32.u64 %0, t; }"
        : "=r"(a) : "l"(p));
    return a;
}
__device__ __forceinline__ uint32_t sw128(uint32_t off) {
    return off ^ ((off >> 3) & 0x70);
}
__device__ __forceinline__ uint32_t swbase(uint32_t R) {
    return R ^ ((R >> 3) & 0x70);
}
#define CP_A16(s, g) \
    asm volatile("cp.async.cg.shared.global [%0], [%1], 16;" :: "r"(s), "l"(g) : "memory")
#define CP_COMMIT() asm volatile("cp.async.commit_group;" ::: "memory")
#define CP_WAIT1()  asm volatile("cp.async.wait_group 1;" ::: "memory")
#define CP_WAIT0()  asm volatile("cp.async.wait_group 0;" ::: "memory")

#define LDSM4(r, addr) \
    asm volatile("ldmatrix.sync.aligned.m8n8.x4.shared.b16 {%0,%1,%2,%3}, [%4];" \
        : "=r"((r)[0]), "=r"((r)[1]), "=r"((r)[2]), "=r"((r)[3]) : "r"(addr))
#define LDSM4T(r, addr) \
    asm volatile("ldmatrix.sync.aligned.m8n8.x4.trans.shared.b16 {%0,%1,%2,%3}, [%4];" \
        : "=r"((r)[0]), "=r"((r)[1]), "=r"((r)[2]), "=r"((r)[3]) : "r"(addr))

__device__ __forceinline__ void mma16816(float* c, const uint32_t* a,
                                         uint32_t b0, uint32_t b1) {
    asm volatile(
        "mma.sync.aligned.m16n8k16.row.col.f32.f16.f16.f32 "
        "{%0,%1,%2,%3}, {%4,%5,%6,%7}, {%8,%9}, {%0,%1,%2,%3};"
        : "+f"(c[0]), "+f"(c[1]), "+f"(c[2]), "+f"(c[3])
        : "r"(a[0]), "r"(a[1]), "r"(a[2]), "r"(a[3]), "r"(b0), "r"(b1));
}
__device__ __forceinline__ uint32_t packhf(float a, float b) {
    __half2 h = __floats2half2_rn(a, b);
    return *reinterpret_cast<uint32_t*>(&h);
}

// ---------- packed f32x2 helpers (sm_100+ base ISA) ----------
typedef unsigned long long u64;
__device__ __forceinline__ u64 pk2(float a, float b) {
    u64 r;
    asm("mov.b64 %0, {%1,%2};" : "=l"(r) : "f"(a), "f"(b));
    return r;
}
__device__ __forceinline__ void upk2(u64 p, float& a, float& b) {
    asm("mov.b64 {%0,%1}, %2;" : "=f"(a), "=f"(b) : "l"(p));
}
#define ADD2(d, a, b) asm("add.rn.f32x2 %0, %1, %2;" : "=l"(d) : "l"(a), "l"(b))
#define MUL2(d, a, b) asm("mul.rn.f32x2 %0, %1, %2;" : "=l"(d) : "l"(a), "l"(b))
#define FMA2(d, a, b, c) \
    asm("fma.rn.f32x2 %0, %1, %2, %3;" : "=l"(d) : "l"(a), "l"(b), "l"(c))

// packed exp2; inputs <= 0, >= ~-126. Degree-4 poly, rel err ~4e-5.
struct ExpC {
    u64 M, NM, C4, C3, C2, C1, C0;
    __device__ __forceinline__ void init() {
        M  = pk2(12582912.0f, 12582912.0f);
        NM = pk2(-12582912.0f, -12582912.0f);
        C4 = pk2(9.6181291e-3f, 9.6181291e-3f);
        C3 = pk2(5.5504109e-2f, 5.5504109e-2f);
        C2 = pk2(2.4022651e-1f, 2.4022651e-1f);
        C1 = pk2(6.9314718e-1f, 6.9314718e-1f);
        C0 = pk2(1.0f, 1.0f);
    }
};
__device__ __forceinline__ u64 exp2x2(u64 x, const ExpC& C) {
    u64 z, t, f, p, sc;
    ADD2(z, x, C.M);
    ADD2(t, z, C.NM);
    t ^= 0x8000000080000000ull;
    ADD2(f, x, t);
    p = C.C4;
    FMA2(p, p, f, C.C3);
    FMA2(p, p, f, C.C2);
    FMA2(p, p, f, C.C1);
    FMA2(p, p, f, C.C0);
    uint32_t elo = (uint32_t)z, ehi = (uint32_t)(z >> 32);
    uint32_t slo = (elo << 23) + 0x3f800000u;
    uint32_t shi = (ehi << 23) + 0x3f800000u;
    asm("mov.b64 %0, {%1,%2};" : "=l"(sc) : "r"(slo), "r"(shi));
    MUL2(p, p, sc);
    return p;
}

// ================= fused prep kernel =================
#define XBLK (M_*C_/4/256)       // 12288

__global__ __launch_bounds__(256)
void prep_all(const float4* __restrict__ x, __half* __restrict__ xh,
              const float* __restrict__ wq, __half* __restrict__ wqh,
              const float* __restrict__ wp, __half* __restrict__ wph)
{
    __shared__ float t[32][33];
    const int bx = blockIdx.x;
    if (bx < XBLK) {
        const uint32_t i = bx * 256 + threadIdx.x;
        float4 v = x[i];
        *(__half2*)(xh + 4*(size_t)i)     = __floats2half2_rn(v.x, v.y);
        *(__half2*)(xh + 4*(size_t)i + 2) = __floats2half2_rn(v.z, v.w);
        return;
    }
    const float* W;
    __half* Th;
    int idx, Ndim;
    if (bx < XBLK + 1728) {
        idx = bx - XBLK; W = wq; Th = wqh; Ndim = QKV_;
    } else {
        idx = bx - XBLK - 1728; W = wp; Th = wph; Ndim = C_;
    }
    const int kk = (idx % 24) * 32, nn = (idx / 24) * 32;
    const int tx = threadIdx.x & 31, ty = threadIdx.x >> 5;
    #pragma unroll
    for (int i = ty; i < 32; i += 8)
        t[i][tx] = W[(size_t)(kk + i) * Ndim + nn + tx];
    __syncthreads();
    #pragma unroll
    for (int i = ty; i < 32; i += 8)
        Th[(size_t)(nn + i) * C_ + kk + tx] = __float2half_rn(t[tx][i]);
}

// ================= fp16 HMMA GEMM, optional fused LN/RoPE epilogue =======
#define GTILE 16384                 // 128 rows x 128 bytes
#define GSTAGE (2*GTILE)            // A,B = 32 KB
#define GEMM_SMEM (3*GSTAGE)        // 98304

template<bool FUSED>
__global__ __launch_bounds__(256, 2)
void gemm_mma(const __half* __restrict__ Ah, const __half* __restrict__ Bh,
              float* __restrict__ Cm, int Mdim, int Ndim, int Kdim,
              const float* __restrict__ bias,
              const float* __restrict__ cosr, const float* __restrict__ sinr,
              const float* __restrict__ qw, const float* __restrict__ qb,
              const float* __restrict__ kw, const float* __restrict__ kb,
              const int* __restrict__ pP, const int* __restrict__ pL,
              __half* __restrict__ Qh,
              __half* __restrict__ Kh, __half* __restrict__ Vh)
{
    extern __shared__ char smem[];
    const uint32_t sb = smem_u32(smem);
    const int tid = threadIdx.x;
    const int wid = tid >> 5, lane = tid & 31;
    const int m0 = blockIdx.y * 128, n0 = blockIdx.x * 128;
    const int wm = (wid & 3) * 32, wn = (wid >> 2) * 64;
    const int nchunks = Kdim / 64;   // 12

    const int r0 = tid >> 3, u8 = tid & 7;
    const __half* pA = Ah + (size_t)(m0 + r0) * Kdim + u8 * 8;
    const __half* pB = Bh + (size_t)(n0 + r0) * Kdim + u8 * 8;
    const uint32_t d0 = sw128((uint32_t)(r0 * 128 + u8 * 16));
    const size_t rstr = (size_t)32 * Kdim;

    auto issue = [&](int c) {
        const uint32_t stg = sb + (uint32_t)(c % 3) * GSTAGE;
        const int k0 = c * 64;
        const __half* a = pA + k0;
        const __half* b = pB + k0;
        #pragma unroll
        for (int t = 0; t < 4; t++) {
            CP_A16(stg + d0 + t*4096,
                   (u64)__cvta_generic_to_global(a + t*rstr));
            CP_A16(stg + GTILE + d0 + t*4096,
                   (u64)__cvta_generic_to_global(b + t*rstr));
        }
    };

    uint32_t offA[2], offB[4];
    #pragma unroll
    for (int mt = 0; mt < 2; mt++)
        offA[mt] = swbase((uint32_t)((wm + mt*16 + (lane & 15)) * 128)) ^ (lane & 16);
    #pragma unroll
    for (int p = 0; p < 4; p++)
        offB[p] = swbase((uint32_t)((wn + p*16 + (lane & 7) + ((lane & 16) >> 1)) * 128))
                  ^ ((lane & 8) << 1);

    float acc[2][8][4];
    #pragma unroll
    for (int i = 0; i < 2; i++)
        #pragma unroll
        for (int j = 0; j < 8; j++)
            #pragma unroll
            for (int q = 0; q < 4; q++) acc[i][j][q] = 0.f;

    issue(0); CP_COMMIT();
    issue(1); CP_COMMIT();

    uint32_t ah[2][2][4], bh[2][4][4];   // ping-pong fragment buffers

    for (int c = 0; c < nchunks; c++) {
        if (c == nchunks - 1) { CP_WAIT0(); } else { CP_WAIT1(); }
        __syncthreads();
        if (c + 2 < nchunks) { issue(c + 2); CP_COMMIT(); }

        const uint32_t sAh = sb + (uint32_t)(c % 3) * GSTAGE;
        const uint32_t sBh = sAh + GTILE;

        // preload ks=0 fragments
        #pragma unroll
        for (int mt = 0; mt < 2; mt++)
            LDSM4(ah[0][mt], sAh + offA[mt]);
        #pragma unroll
        for (int p = 0; p < 4; p++)
            LDSM4(bh[0][p], sBh + offB[p]);

        #pragma unroll
        for (int ks = 0; ks < 4; ks++) {
            const int cur = ks & 1, nxt = cur ^ 1;
            if (ks < 3) {
                const uint32_t kx = (uint32_t)((ks + 1) << 5);
                #pragma unroll
                for (int mt = 0; mt < 2; mt++)
                    LDSM4(ah[nxt][mt], sAh + (offA[mt] ^ kx));
                #pragma unroll
                for (int p = 0; p < 4; p++)
                    LDSM4(bh[nxt][p], sBh + (offB[p] ^ kx));
            }
            #pragma unroll
            for (int mt = 0; mt < 2; mt++)
                #pragma unroll
                for (int p = 0; p < 4; p++)
                    #pragma unroll
                    for (int h2 = 0; h2 < 2; h2++) {
                        int nt = 2*p + h2;
                        mma16816(acc[mt][nt], ah[cur][mt],
                                 bh[cur][p][2*h2], bh[cur][p][2*h2+1]);
                    }
        }
    }

    if (!FUSED) {
        #pragma unroll
        for (int mt = 0; mt < 2; mt++)
            #pragma unroll
            for (int nt = 0; nt < 8; nt++) {
                int row = m0 + wm + mt*16 + (lane >> 2);
                int col = n0 + wn + nt*8 + 2*(lane & 3);
                float b0 = 0.f, b1 = 0.f;
                if (bias) { b0 = bias[col]; b1 = bias[col + 1]; }
                float2 v0 = make_float2(acc[mt][nt][0] + b0, acc[mt][nt][1] + b1);
                float2 v1 = make_float2(acc[mt][nt][2] + b0, acc[mt][nt][3] + b1);
                *(float2*)(Cm + (size_t)row * Ndim + col)       = v0;
                *(float2*)(Cm + (size_t)(row + 8) * Ndim + col) = v1;
            }
    } else {
        const int gcol = n0 + wn;
        const int kind = gcol / C_;             // 0=q, 1=k, 2=v
        const int head = (gcol % C_) / D_;
        const int Pp = __ldg(pP), Ll = __ldg(pL);
        const float* lw = (kind == 0) ? qw : kw;
        const float* lb = (kind == 0) ? qb : kb;
        const float QSC = 0.18033688011112042f; // (1/8)*log2(e)

        #pragma unroll
        for (int mt = 0; mt < 2; mt++) {
            const int m1 = m0 + wm + mt*16 + (lane >> 2);
            const int m2 = m1 + 8;
            const int b1i = m1 >> 10, n1 = m1 & (N_-1);
            const int b2i = m2 >> 10, n2 = m2 & (N_-1);
            const size_t o1 = (((size_t)(b1i*H_ + head))*N_ + n1) * D_;
            const size_t o2 = (((size_t)(b2i*H_ + head))*N_ + n2) * D_;

            if (kind == 2) {
                #pragma unroll
                for (int nt = 0; nt < 8; nt++) {
                    int col = nt*8 + 2*(lane & 3);
                    *(uint32_t*)(Vh + o1 + col) = packhf(acc[mt][nt][0], acc[mt][nt][1]);
                    *(uint32_t*)(Vh + o2 + col) = packhf(acc[mt][nt][2], acc[mt][nt][3]);
                }
            } else {
                float s1 = 0.f, s2 = 0.f;
                #pragma unroll
                for (int nt = 0; nt < 8; nt++) {
                    s1 += acc[mt][nt][0] + acc[mt][nt][1];
                    s2 += acc[mt][nt][2] + acc[mt][nt][3];
                }
                s1 += __shfl_xor_sync(~0u, s1, 1); s1 += __shfl_xor_sync(~0u, s1, 2);
                s2 += __shfl_xor_sync(~0u, s2, 1); s2 += __shfl_xor_sync(~0u, s2, 2);
                const float mu1 = s1 * (1.0f/64.0f), mu2 = s2 * (1.0f/64.0f);
                float v1 = 0.f, v2 = 0.f;
                #pragma unroll
                for (int nt = 0; nt < 8; nt++) {
                    float d0f = acc[mt][nt][0] - mu1, d1f = acc[mt][nt][1] - mu1;
                    float d2f = acc[mt][nt][2] - mu2, d3f = acc[mt][nt][3] - mu2;
                    v1 += d0f*d0f + d1f*d1f;
                    v2 += d2f*d2f + d3f*d3f;
                }
                v1 += __shfl_xor_sync(~0u, v1, 1); v1 += __shfl_xor_sync(~0u, v1, 2);
                v2 += __shfl_xor_sync(~0u, v2, 1); v2 += __shfl_xor_sync(~0u, v2, 2);
                const float iv1 = rsqrtf(v1*(1.0f/64.0f) + 1e-5f);
                const float iv2 = rsqrtf(v2*(1.0f/64.0f) + 1e-5f);
                const bool r1 = (n1 >= Pp) && (n1 < N_ - Ll);
                const bool r2 = (n2 >= Pp) && (n2 < N_ - Ll);

                #pragma unroll
                for (int nt = 0; nt < 8; nt++) {
                    const int col  = nt*8 + 2*(lane & 3);
                    const int colp = nt*4 + (lane & 3);
                    float2 w2 = *(const float2*)(lw + col);
                    float2 bb = *(const float2*)(lb + col);
                    float y0 = fmaf((acc[mt][nt][0]-mu1)*iv1, w2.x, bb.x);
                    float y1 = fmaf((acc[mt][nt][1]-mu1)*iv1, w2.y, bb.y);
                    float y2 = fmaf((acc[mt][nt][2]-mu2)*iv2, w2.x, bb.x);
                    float y3 = fmaf((acc[mt][nt][3]-mu2)*iv2, w2.y, bb.y);
                    if (r1) {
                        float rc = cosr[(n1-Pp)*32 + colp], rs = sinr[(n1-Pp)*32 + colp];
                        float t0 = y0*rc - y1*rs, t1 = y0*rs + y1*rc;
                        y0 = t0; y1 = t1;
                    }
                    if (r2) {
                        float rc = cosr[(n2-Pp)*32 + colp], rs = sinr[(n2-Pp)*32 + colp];
                        float t2 = y2*rc - y3*rs, t3 = y2*rs + y3*rc;
                        y2 = t2; y3 = t3;
                    }
                    if (kind == 0) {
                        y0 *= QSC; y1 *= QSC; y2 *= QSC; y3 *= QSC;
                        *(uint32_t*)(Qh + o1 + col) = packhf(y0, y1);
                        *(uint32_t*)(Qh + o2 + col) = packhf(y2, y3);
                    } else {
                        *(uint32_t*)(Kh + o1 + col) = packhf(y0, y1);
                        *(uint32_t*)(Kh + o2 + col) = packhf(y2, y3);
                    }
                }
            }
        }
    }
}

// ================= HMMA flash attention (fixed-max softmax) =============
// |S_log2| <= 11.54 (Cauchy-Schwarz after LN) -> constant shift 12.5, exact.
// K and V fragments ping-pong pipelined against MMAs.
#define KTILE2 16384                  // 128 rows x 128 bytes
#define ASTAGE (2*KTILE2)             // Kh,Vh = 32 KB
#define ATT_SMEM (3*ASTAGE)           // 98304

__global__ __launch_bounds__(256, 2)
void attn_mma(const __half* __restrict__ Qh,
              const __half* __restrict__ Kh, const __half* __restrict__ Vh,
              __half* __restrict__ Oh)
{
    extern __shared__ char smem[];
    const uint32_t sb = smem_u32(smem);
    const int tid = threadIdx.x;
    const int wid = tid >> 5, lane = tid & 31;
    const int b = blockIdx.z, h = blockIdx.y;
    const int q0 = blockIdx.x * 128;
    const size_t base = ((size_t)(b*H_ + h)) * N_;

    ExpC EC; EC.init();
    const u64 FM = pk2(-12.5f, -12.5f);    // fixed softmax shift

    const int r0 = tid >> 3, u8 = tid & 7;
    const uint32_t d0 = sw128((uint32_t)(r0 * 128 + u8 * 16));
    const __half* pK = Kh + (base + r0) * D_ + u8 * 8;
    const __half* pV = Vh + (base + r0) * D_ + u8 * 8;

    // ---- stage Q tile (16 KB, in stage-0 area) ----
    {
        const __half* pQ = Qh + (base + q0 + r0) * D_ + u8 * 8;
        #pragma unroll
        for (int t = 0; t < 4; t++) {
            uint4 v = *(const uint4*)(pQ + t * 32 * D_);
            *(uint4*)(smem + d0 + t*4096) = v;
        }
    }
    __syncthreads();

    uint32_t qh[4][4];
    {
        const uint32_t offQ = swbase((uint32_t)((wid*16 + (lane & 15)) * 128)) ^ (lane & 16);
        #pragma unroll
        for (int ks = 0; ks < 4; ks++)
            LDSM4(qh[ks], sb + (offQ ^ (uint32_t)(ks << 5)));
    }
    __syncthreads();   // Q reads done; smem reusable for KV stages

    uint32_t offK[4], offV[4];
    #pragma unroll
    for (int p = 0; p < 4; p++)
        offK[p] = swbase((uint32_t)((p*16 + (lane & 7) + ((lane & 16) >> 1)) * 128))
                  ^ ((lane & 8) << 1);
    #pragma unroll
    for (int ds = 0; ds < 4; ds++)
        offV[ds] = swbase((uint32_t)((ds*16 + (lane & 15)) * 128)) ^ (lane & 16);

    auto issue = [&](int kt) {
        const uint32_t stg = sb + (uint32_t)(kt % 3) * ASTAGE;
        const int koff = kt * 128 * D_;
        const __half* k = pK + koff;
        const __half* v = pV + koff;
        #pragma unroll
        for (int t = 0; t < 4; t++) {
            CP_A16(stg + d0 + t*4096,
                   (u64)__cvta_generic_to_global(k + t * 32 * D_));
            CP_A16(stg + KTILE2 + d0 + t*4096,
                   (u64)__cvta_generic_to_global(v + t * 32 * D_));
        }
    };

    float o[8][4];
    #pragma unroll
    for (int j = 0; j < 8; j++)
        #pragma unroll
        for (int q = 0; q < 4; q++) o[j][q] = 0.f;
    u64 ls0 = 0ull, ls1 = 0ull;            // packed li accumulators

    issue(0); CP_COMMIT();
    issue(1); CP_COMMIT();

    for (int kt = 0; kt < 8; kt++) {
        if (kt == 7) { CP_WAIT0(); } else { CP_WAIT1(); }
        __syncthreads();
        if (kt + 2 < 8) { issue(kt + 2); CP_COMMIT(); }

        const uint32_t stg = sb + (uint32_t)(kt % 3) * ASTAGE;

        #pragma unroll
        for (int sub = 0; sub < 2; sub++) {
            const uint32_t sKh = stg + (uint32_t)sub * 8192;
            const uint32_t sVh = stg + KTILE2 + (uint32_t)sub * 8192;

            // ---- S = Q K^T (K frags ping-pong) ----
            float s[8][4];
            #pragma unroll
            for (int j = 0; j < 8; j++)
                #pragma unroll
                for (int q = 0; q < 4; q++) s[j][q] = 0.f;

            uint32_t kk[2][4][4];
            #pragma unroll
            for (int p = 0; p < 4; p++)
                LDSM4(kk[0][p], sKh + offK[p]);

            #pragma unroll
            for (int ks = 0; ks < 4; ks++) {
                const int cur = ks & 1, nxt = cur ^ 1;
                if (ks < 3) {
                    const uint32_t kx = (uint32_t)((ks + 1) << 5);
                    #pragma unroll
                    for (int p = 0; p < 4; p++)
                        LDSM4(kk[nxt][p], sKh + (offK[p] ^ kx));
                }
                #pragma unroll
                for (int p = 0; p < 4; p++)
                    #pragma unroll
                    for (int h2 = 0; h2 < 2; h2++) {
                        int nt = 2*p + h2;
                        mma16816(s[nt], qh[ks],
                                 kk[cur][p][2*h2], kk[cur][p][2*h2+1]);
                    }
            }

            // ---- prefetch V fragments for ds=0 (hidden by exp work) ----
            uint32_t vv[2][4][4];
            #pragma unroll
            for (int dj = 0; dj < 4; dj++)
                LDSM4T(vv[0][dj], sVh + (offV[0] ^ (uint32_t)(dj << 5)));

            // ---- fixed-max softmax: p = exp2(s - 12.5), accumulate li ----
            #pragma unroll
            for (int nt = 0; nt < 8; nt++) {
                u64 x0, x1;
                ADD2(x0, pk2(s[nt][0], s[nt][1]), FM);
                ADD2(x1, pk2(s[nt][2], s[nt][3]), FM);
                u64 e0 = exp2x2(x0, EC);
                u64 e1 = exp2x2(x1, EC);
                upk2(e0, s[nt][0], s[nt][1]);
                upk2(e1, s[nt][2], s[nt][3]);
                ADD2(ls0, ls0, e0);
                ADD2(ls1, ls1, e1);
            }

            // ---- O += P V (V frags ping-pong) ----
            #pragma unroll
            for (int ds = 0; ds < 4; ds++) {
                const int cur = ds & 1, nxt = cur ^ 1;
                uint32_t ph[4];
                #pragma unroll
                for (int half = 0; half < 2; half++) {
                    int nt = 2*ds + half;
                    ph[2*half]   = packhf(s[nt][0], s[nt][1]);
                    ph[2*half+1] = packhf(s[nt][2], s[nt][3]);
                }
                if (ds < 3) {
                    #pragma unroll
                    for (int dj = 0; dj < 4; dj++)
                        LDSM4T(vv[nxt][dj], sVh + (offV[ds+1] ^ (uint32_t)(dj << 5)));
                }
                #pragma unroll
                for (int dj = 0; dj < 4; dj++)
                    #pragma unroll
                    for (int h2 = 0; h2 < 2; h2++) {
                        int dt = 2*dj + h2;
                        mma16816(o[dt], ph, vv[cur][dj][2*h2], vv[cur][dj][2*h2+1]);
                    }
            }
        }
    }

    // ---- reduce li once, normalize, round fp16, store [B,N,C] ----
    float la, lb2, li0, li1;
    upk2(ls0, la, lb2); li0 = la + lb2;
    upk2(ls1, la, lb2); li1 = la + lb2;
    li0 += __shfl_xor_sync(~0u, li0, 1);
    li0 += __shfl_xor_sync(~0u, li0, 2);
    li1 += __shfl_xor_sync(~0u, li1, 1);
    li1 += __shfl_xor_sync(~0u, li1, 2);
    const float inv1 = 1.0f / li0;
    const float inv2 = 1.0f / li1;
    const int row1 = q0 + wid*16 + (lane >> 2);
    #pragma unroll
    for (int dt = 0; dt < 8; dt++) {
        int col = h*D_ + dt*8 + 2*(lane & 3);
        size_t i1 = (size_t)(b*N_ + row1) * C_ + col;
        size_t i2 = (size_t)(b*N_ + row1 + 8) * C_ + col;
        *(uint32_t*)(Oh + i1) = packhf(o[dt][0]*inv1, o[dt][1]*inv1);
        *(uint32_t*)(Oh + i2) = packhf(o[dt][2]*inv2, o[dt][3]*inv2);
    }
}

// ================= launch =================
extern "C" void kernel_launch(void* const* d_in, const int* in_sizes, int n_in,
                              void* d_out, int out_size)
{
    const float* x      = (const float*)d_in[0];
    const float* cosr   = (const float*)d_in[1];
    const float* sinr   = (const float*)d_in[2];
    const float* w_qkv  = (const float*)d_in[3];
    const float* q_ln_w = (const float*)d_in[4];
    const float* q_ln_b = (const float*)d_in[5];
    const float* k_ln_w = (const float*)d_in[6];
    const float* k_ln_b = (const float*)d_in[7];
    const float* w_proj = (const float*)d_in[8];
    const float* b_proj = (const float*)d_in[9];
    const int*   pP     = (const int*)d_in[10];
    const int*   pL     = (const int*)d_in[11];
    float* out = (float*)d_out;

    __half *xh, *wqh, *wph, *qh, *kh, *vh, *oh;
    cudaGetSymbolAddress((void**)&xh,  g_xh);
    cudaGetSymbolAddress((void**)&wqh, g_wqh);
    cudaGetSymbolAddress((void**)&wph, g_wph);
    cudaGetSymbolAddress((void**)&qh,  g_qh);
    cudaGetSymbolAddress((void**)&kh,  g_kh);
    cudaGetSymbolAddress((void**)&vh,  g_vh);
    cudaGetSymbolAddress((void**)&oh,  g_oh);

    cudaFuncSetAttribute(gemm_mma<false>, cudaFuncAttributeMaxDynamicSharedMemorySize, GEMM_SMEM);
    cudaFuncSetAttribute(gemm_mma<true>,  cudaFuncAttributeMaxDynamicSharedMemorySize, GEMM_SMEM);
    cudaFuncSetAttribute(attn_mma, cudaFuncAttributeMaxDynamicSharedMemorySize, ATT_SMEM);

    // 0) fused prep: x round + both weight transposes
    prep_all<<<XBLK + 1728 + 576, 256>>>((const float4*)x, xh,
                                         w_qkv, wqh, w_proj, wph);

    // 1) QKV projection with fused LN+RoPE epilogue -> fp16 Q/K/V
    gemm_mma<true><<<dim3(QKV_/128, M_/128), 256, GEMM_SMEM>>>(
        xh, wqh, nullptr, M_, QKV_, C_, nullptr,
        cosr, sinr, q_ln_w, q_ln_b, k_ln_w, k_ln_b, pP, pL,
        qh, kh, vh);

    // 2) attention -> fp16 [B,N,C]
    attn_mma<<<dim3(N_/128, H_, B_), 256, ATT_SMEM>>>(qh, kh, vh, oh);

    // 3) output projection + bias
    gemm_mma<false><<<dim3(C_/128, M_/128), 256, GEMM_SMEM>>>(
        oh, wph, out, M_, C_, C_, b_proj,
        nullptr, nullptr, nullptr, nullptr, nullptr, nullptr, nullptr, nullptr,
        nullptr, nullptr, nullptr);
}